// round 6
// baseline (speedup 1.0000x reference)
#include <cuda_runtime.h>
#include <cuda_bf16.h>
#include <cstdint>

#define BB 8
#define TT 2048
#define CC 1024

typedef __nv_bfloat16 bf16;

// Scratch (device globals — allocation-free)
__device__ bf16   g_xhi  [(size_t)BB * TT * CC];
__device__ bf16   g_xlo  [(size_t)BB * TT * CC];
__device__ bf16   g_whi  [(size_t)CC * CC];
__device__ bf16   g_wlo  [(size_t)CC * CC];
__device__ bf16   g_xHhi [(size_t)BB * TT * CC];
__device__ bf16   g_xHlo [(size_t)BB * TT * CC];
__device__ float  g_sc   [(size_t)BB * TT * TT];
__device__ float2 g_stats[(size_t)BB * TT];

// ===========================================================================
// helpers
// ===========================================================================
__device__ __forceinline__ uint32_t smem_u32(const void* p) {
    uint32_t a;
    asm("{ .reg .u64 t; cvta.to.shared.u64 t, %1; cvt.u32.u64 %0, t; }" : "=r"(a) : "l"(p));
    return a;
}
__device__ __forceinline__ void cp16(uint32_t s, const void* g) {
    asm volatile("cp.async.cg.shared.global [%0], [%1], 16;" :: "r"(s), "l"(g) : "memory");
}
__device__ __forceinline__ void ldsm4(uint32_t addr, uint32_t& r0, uint32_t& r1,
                                      uint32_t& r2, uint32_t& r3) {
    asm volatile("ldmatrix.sync.aligned.m8n8.x4.shared.b16 {%0,%1,%2,%3}, [%4];"
                 : "=r"(r0), "=r"(r1), "=r"(r2), "=r"(r3) : "r"(addr));
}
__device__ __forceinline__ void ldsm4t(uint32_t addr, uint32_t& r0, uint32_t& r1,
                                       uint32_t& r2, uint32_t& r3) {
    asm volatile("ldmatrix.sync.aligned.m8n8.x4.trans.shared.b16 {%0,%1,%2,%3}, [%4];"
                 : "=r"(r0), "=r"(r1), "=r"(r2), "=r"(r3) : "r"(addr));
}
__device__ __forceinline__ void mma_bf16(float c[4], const uint32_t a[4], const uint32_t b[2]) {
    asm volatile(
        "mma.sync.aligned.m16n8k16.row.col.f32.bf16.bf16.f32 "
        "{%0,%1,%2,%3}, {%4,%5,%6,%7}, {%8,%9}, {%0,%1,%2,%3};"
        : "+f"(c[0]), "+f"(c[1]), "+f"(c[2]), "+f"(c[3])
        : "r"(a[0]), "r"(a[1]), "r"(a[2]), "r"(a[3]), "r"(b[0]), "r"(b[1]));
}

// swizzled 16B-chunk offset within a K-major (64B-row) tile
__device__ __forceinline__ uint32_t swz(int row, int chunk) {
    return (uint32_t)(row * 64 + ((chunk ^ ((row >> 1) & 3)) << 4));
}

// ===========================================================================
// 3xBF16 GEMM:  C = A[M,K] @ B[N,K]^T, bf16 hi/lo inputs
// CTA tile 128x256, warp tile 64x64 (2x4 warp grid), KC=32, 4-stage pipeline.
// OUTMODE: 0 = fp32, 2 = bf16 hi/lo split pair
// ===========================================================================
#define AHI_OFF 0
#define ALO_OFF 8192
#define BHI_OFF 16384
#define BLO_OFF 32768
#define STG_BYTES 49152
#define SMEM_TOTAL (4 * STG_BYTES)   // 196608

template <bool CAUSAL, int OUTMODE>
__global__ __launch_bounds__(256, 1) void gemm_bf3(
    const bf16* __restrict__ Ahi, const bf16* __restrict__ Alo,
    const bf16* __restrict__ Bhi, const bf16* __restrict__ Blo,
    float* __restrict__ Cf, bf16* __restrict__ Chi, bf16* __restrict__ Clo,
    int lda, int ldb, int ldc, int Kfull,
    long long sA, long long sB, long long sC)
{
    const int bx = blockIdx.x, by = blockIdx.y, bz = blockIdx.z;
    if (CAUSAL && (2 * bx >= by + 1)) return;   // tile fully masked

    Ahi += (long long)bz * sA; Alo += (long long)bz * sA;
    Bhi += (long long)bz * sB; Blo += (long long)bz * sB;

    const int m0 = by * 128, n0 = bx * 256;
    const int nc = Kfull / 32;

    extern __shared__ char smem[];
    const uint32_t sbase = smem_u32(smem);
    const int tid = threadIdx.x;
    const int wid = tid >> 5, lane = tid & 31;
    const int wm = wid & 1, wn = wid >> 1;      // 2 x 4 warps, each 64x64
    const int g = lane >> 3, i = lane & 7;

    // fragment lane geometry
    const int arow_base = wm * 64 + i + (g & 1) * 8;    // + mt*16
    const int brow_base = wn * 64 + i + (g >> 1) * 8;   // + j*16
    const int achunk0 = g >> 1;                          // + ks*2
    const int bchunk0 = g & 1;                           // + ks*2

    // loader mapping: row = idx>>2, chunk = idx&3
    const int l_row = tid >> 2, l_ch = tid & 3;

    float acc[4][8][4];
#pragma unroll
    for (int a = 0; a < 4; a++)
#pragma unroll
        for (int b = 0; b < 8; b++)
#pragma unroll
            for (int c = 0; c < 4; c++) acc[a][b][c] = 0.f;

    auto issue = [&](int ch) {
        const uint32_t st = sbase + (uint32_t)(ch & 3) * STG_BYTES;
        const long long k0 = (long long)ch * 32 + l_ch * 8;
        // A: 128 rows
#pragma unroll
        for (int r = 0; r < 2; r++) {
            const int row = l_row + r * 64;
            const uint32_t so = swz(row, l_ch);
            const long long ga = (long long)(m0 + row) * lda + k0;
            cp16(st + AHI_OFF + so, Ahi + ga);
            cp16(st + ALO_OFF + so, Alo + ga);
        }
        // B: 256 rows
#pragma unroll
        for (int r = 0; r < 4; r++) {
            const int row = l_row + r * 64;
            const uint32_t so = swz(row, l_ch);
            const long long gb = (long long)(n0 + row) * ldb + k0;
            cp16(st + BHI_OFF + so, Bhi + gb);
            cp16(st + BLO_OFF + so, Blo + gb);
        }
    };

#pragma unroll
    for (int s = 0; s < 3; s++) {
        if (s < nc) issue(s);
        asm volatile("cp.async.commit_group;" ::: "memory");
    }

    for (int ch = 0; ch < nc; ch++) {
        asm volatile("cp.async.wait_group 2;" ::: "memory");
        __syncthreads();
        if (ch + 3 < nc) issue(ch + 3);
        asm volatile("cp.async.commit_group;" ::: "memory");

        const uint32_t st = sbase + (uint32_t)(ch & 3) * STG_BYTES;

#pragma unroll
        for (int ks = 0; ks < 2; ks++) {
            uint32_t ah[4][4], al[4][4], bh[8][2], bl[8][2];
#pragma unroll
            for (int mt = 0; mt < 4; mt++) {
                const uint32_t ao = swz(arow_base + mt * 16, achunk0 + ks * 2);
                ldsm4(st + AHI_OFF + ao, ah[mt][0], ah[mt][1], ah[mt][2], ah[mt][3]);
                ldsm4(st + ALO_OFF + ao, al[mt][0], al[mt][1], al[mt][2], al[mt][3]);
            }
#pragma unroll
            for (int j = 0; j < 4; j++) {
                const uint32_t bo = swz(brow_base + j * 16, bchunk0 + ks * 2);
                uint32_t r0, r1, r2, r3;
                ldsm4(st + BHI_OFF + bo, r0, r1, r2, r3);
                bh[2 * j][0] = r0; bh[2 * j][1] = r1; bh[2 * j + 1][0] = r2; bh[2 * j + 1][1] = r3;
                ldsm4(st + BLO_OFF + bo, r0, r1, r2, r3);
                bl[2 * j][0] = r0; bl[2 * j][1] = r1; bl[2 * j + 1][0] = r2; bl[2 * j + 1][1] = r3;
            }
#pragma unroll
            for (int mt = 0; mt < 4; mt++)
#pragma unroll
                for (int nt = 0; nt < 8; nt++) mma_bf16(acc[mt][nt], ah[mt], bh[nt]);
#pragma unroll
            for (int mt = 0; mt < 4; mt++)
#pragma unroll
                for (int nt = 0; nt < 8; nt++) mma_bf16(acc[mt][nt], ah[mt], bl[nt]);
#pragma unroll
            for (int mt = 0; mt < 4; mt++)
#pragma unroll
                for (int nt = 0; nt < 8; nt++) mma_bf16(acc[mt][nt], al[mt], bh[nt]);
        }
    }

    // ---- epilogue ----
    const int rr = lane >> 2, cb = (lane & 3) * 2;
#pragma unroll
    for (int mt = 0; mt < 4; mt++) {
#pragma unroll
        for (int nt = 0; nt < 8; nt++) {
            const int row = m0 + wm * 64 + mt * 16 + rr;
            const int col = n0 + wn * 64 + nt * 8 + cb;
            const float s0 = acc[mt][nt][0], s1 = acc[mt][nt][1];
            const float s2 = acc[mt][nt][2], s3 = acc[mt][nt][3];
            if (OUTMODE == 0) {
                float* base = Cf + (long long)bz * sC;
                *(float2*)(base + (long long)row * ldc + col)       = make_float2(s0, s1);
                *(float2*)(base + (long long)(row + 8) * ldc + col) = make_float2(s2, s3);
            } else {
                bf16* oh = Chi + (long long)bz * sC;
                bf16* ol = Clo + (long long)bz * sC;
                bf16 h0 = __float2bfloat16(s0), h1 = __float2bfloat16(s1);
                bf16 h2 = __float2bfloat16(s2), h3 = __float2bfloat16(s3);
                bf16 l0 = __float2bfloat16(s0 - __bfloat162float(h0));
                bf16 l1 = __float2bfloat16(s1 - __bfloat162float(h1));
                bf16 l2 = __float2bfloat16(s2 - __bfloat162float(h2));
                bf16 l3 = __float2bfloat16(s3 - __bfloat162float(h3));
                *(__nv_bfloat162*)(oh + (long long)row * ldc + col)       = __halves2bfloat162(h0, h1);
                *(__nv_bfloat162*)(oh + (long long)(row + 8) * ldc + col) = __halves2bfloat162(h2, h3);
                *(__nv_bfloat162*)(ol + (long long)row * ldc + col)       = __halves2bfloat162(l0, l1);
                *(__nv_bfloat162*)(ol + (long long)(row + 8) * ldc + col) = __halves2bfloat162(l2, l3);
            }
        }
    }
}

// ===========================================================================
// K4: out[t][c] = -sum_s wei[t][s] * xH[s][c]
// wei from fp32 scores + row stats on the fly; 128x128, 3 stages, 2 CTA/SM.
// ===========================================================================
#define W_AHI 0
#define W_ALO 8192
#define W_BHI 16384
#define W_BLO 25088
#define W_STG 33792
#define W_SMEM (3 * W_STG)   // 101376

__global__ __launch_bounds__(256, 2) void gemm_wei(
    const float* __restrict__ scA, const float2* __restrict__ stats,
    const bf16* __restrict__ Bhi, const bf16* __restrict__ Blo,
    float* __restrict__ Out)
{
    const int bx = blockIdx.x, by = blockIdx.y, bz = blockIdx.z;
    const float* sc = scA + (long long)bz * TT * TT;
    const float2* stt = stats + (long long)bz * TT;
    const bf16* bhi = Bhi + (long long)bz * TT * CC;
    const bf16* blo = Blo + (long long)bz * TT * CC;
    float* out = Out + (long long)bz * TT * CC;

    const int m0 = by * 128, n0 = bx * 128;
    const int Klim = min(TT, (by + 1) * 128);
    const int nc = Klim / 32;

    extern __shared__ char smem[];
    const uint32_t sbase = smem_u32(smem);
    const int tid = threadIdx.x;
    const int wid = tid >> 5, lane = tid & 31;
    const int wm = wid & 1, wn = wid >> 1;
    const int g = lane >> 3, i = lane & 7;

    const int arow_base = wm * 64 + i + (g & 1) * 8;
    const int achunk0 = g >> 1;
    const uint32_t bLaneT = (uint32_t)((lane & 15) * 272 + (lane >> 4) * 16 + wn * 64);

    const int arow = tid >> 1, aseg = tid & 1;
    const int t_glob = m0 + arow;
    const float2 rs = stt[t_glob];
    float4 pa[4];

    auto ldgA = [&](int ch) {
        const float* src = sc + (long long)t_glob * TT + ch * 32 + aseg * 16;
        pa[0] = *(const float4*)(src + 0);
        pa[1] = *(const float4*)(src + 4);
        pa[2] = *(const float4*)(src + 8);
        pa[3] = *(const float4*)(src + 12);
    };
    auto stsA = [&](int ch) {
        char* stg = smem + (size_t)(ch % 3) * W_STG;
        const int sb0 = ch * 32 + aseg * 16;
        uint32_t hi[8], lo[8];
#pragma unroll
        for (int q = 0; q < 4; q++) {
            const float vv[4] = { pa[q].x, pa[q].y, pa[q].z, pa[q].w };
            float w[4];
#pragma unroll
            for (int e = 0; e < 4; e++) {
                const int s = sb0 + q * 4 + e;
                w[e] = (s < t_glob) ? __expf(vv[e] - rs.x) * rs.y : 0.0f;
            }
#pragma unroll
            for (int e = 0; e < 4; e += 2) {
                const bf16 h0 = __float2bfloat16(w[e]);
                const bf16 h1 = __float2bfloat16(w[e + 1]);
                const bf16 l0 = __float2bfloat16(w[e] - __bfloat162float(h0));
                const bf16 l1 = __float2bfloat16(w[e + 1] - __bfloat162float(h1));
                __nv_bfloat162 ph = __halves2bfloat162(h0, h1);
                __nv_bfloat162 pl = __halves2bfloat162(l0, l1);
                hi[q * 2 + e / 2] = *(uint32_t*)&ph;
                lo[q * 2 + e / 2] = *(uint32_t*)&pl;
            }
        }
        const uint32_t o0 = swz(arow, 2 * aseg);
        const uint32_t o1 = swz(arow, 2 * aseg + 1);
        *(uint4*)(stg + W_AHI + o0) = *(uint4*)(hi + 0);
        *(uint4*)(stg + W_AHI + o1) = *(uint4*)(hi + 4);
        *(uint4*)(stg + W_ALO + o0) = *(uint4*)(lo + 0);
        *(uint4*)(stg + W_ALO + o1) = *(uint4*)(lo + 4);
    };
    auto issueB = [&](int ch) {
        const uint32_t st = sbase + (uint32_t)(ch % 3) * W_STG;
        const long long k0 = (long long)ch * 32;
#pragma unroll
        for (int r = 0; r < 2; r++) {
            const int idx = tid + r * 256;
            const int brow = idx >> 4, bseg = idx & 15;
            const long long go = (k0 + brow) * CC + n0 + bseg * 8;
            const uint32_t so = (uint32_t)(brow * 272 + bseg * 16);
            cp16(st + W_BHI + so, bhi + go);
            cp16(st + W_BLO + so, blo + go);
        }
    };

    float acc[4][4][4];
#pragma unroll
    for (int a = 0; a < 4; a++)
#pragma unroll
        for (int b = 0; b < 4; b++)
#pragma unroll
            for (int c = 0; c < 4; c++) acc[a][b][c] = 0.f;

    ldgA(0);
#pragma unroll
    for (int s = 0; s < 2; s++) {
        if (s < nc) issueB(s);
        asm volatile("cp.async.commit_group;" ::: "memory");
    }

    for (int ch = 0; ch < nc; ch++) {
        asm volatile("cp.async.wait_group 1;" ::: "memory");
        stsA(ch);
        __syncthreads();
        if (ch + 1 < nc) ldgA(ch + 1);
        if (ch + 2 < nc) issueB(ch + 2);
        asm volatile("cp.async.commit_group;" ::: "memory");

        const uint32_t st = sbase + (uint32_t)(ch % 3) * W_STG;

#pragma unroll
        for (int ks = 0; ks < 2; ks++) {
            uint32_t ah[4][4], al[4][4], bh[4][2], bl[4][2];
#pragma unroll
            for (int mt = 0; mt < 4; mt++) {
                const uint32_t ao = swz(arow_base + mt * 16, achunk0 + ks * 2);
                ldsm4(st + W_AHI + ao, ah[mt][0], ah[mt][1], ah[mt][2], ah[mt][3]);
                ldsm4(st + W_ALO + ao, al[mt][0], al[mt][1], al[mt][2], al[mt][3]);
            }
#pragma unroll
            for (int j = 0; j < 2; j++) {
                uint32_t r0, r1, r2, r3;
                ldsm4t(st + W_BHI + bLaneT + ks * (16 * 272) + j * 32, r0, r1, r2, r3);
                bh[2 * j][0] = r0; bh[2 * j][1] = r1; bh[2 * j + 1][0] = r2; bh[2 * j + 1][1] = r3;
                ldsm4t(st + W_BLO + bLaneT + ks * (16 * 272) + j * 32, r0, r1, r2, r3);
                bl[2 * j][0] = r0; bl[2 * j][1] = r1; bl[2 * j + 1][0] = r2; bl[2 * j + 1][1] = r3;
            }
#pragma unroll
            for (int mt = 0; mt < 4; mt++)
#pragma unroll
                for (int nt = 0; nt < 4; nt++) mma_bf16(acc[mt][nt], ah[mt], bh[nt]);
#pragma unroll
            for (int mt = 0; mt < 4; mt++)
#pragma unroll
                for (int nt = 0; nt < 4; nt++) mma_bf16(acc[mt][nt], ah[mt], bl[nt]);
#pragma unroll
            for (int mt = 0; mt < 4; mt++)
#pragma unroll
                for (int nt = 0; nt < 4; nt++) mma_bf16(acc[mt][nt], al[mt], bh[nt]);
        }
    }

    const int rr = lane >> 2, cb = (lane & 3) * 2;
#pragma unroll
    for (int mt = 0; mt < 4; mt++) {
#pragma unroll
        for (int nt = 0; nt < 4; nt++) {
            const int row = m0 + wm * 64 + mt * 16 + rr;
            const int col = n0 + wn * 32 + nt * 8 + cb;
            *(float2*)(out + (long long)row * CC + col) =
                make_float2(-acc[mt][nt][0], -acc[mt][nt][1]);
            *(float2*)(out + (long long)(row + 8) * CC + col) =
                make_float2(-acc[mt][nt][2], -acc[mt][nt][3]);
        }
    }
}

// ===========================================================================
__global__ __launch_bounds__(256) void split_bf16(
    const float* __restrict__ src, bf16* __restrict__ hi, bf16* __restrict__ lo, long long n)
{
    for (long long idx = (long long)blockIdx.x * 256 + threadIdx.x; idx < n;
         idx += (long long)gridDim.x * 256) {
        const float x = src[idx];
        const bf16 h = __float2bfloat16(x);
        hi[idx] = h;
        lo[idx] = __float2bfloat16(x - __bfloat162float(h));
    }
}

__global__ __launch_bounds__(256) void row_stats(
    const float* __restrict__ sc, float2* __restrict__ stats)
{
    const long long row = blockIdx.x;
    const int t = (int)(row % TT);
    const float* p = sc + row * TT;
    const float4* p4 = (const float4*)p;
    const int n4 = t >> 2;
    const int tid = threadIdx.x;

    __shared__ float red[8];

    float m = -3.0e38f;
    for (int q = tid; q < n4; q += 256) {
        const float4 v = p4[q];
        m = fmaxf(m, fmaxf(fmaxf(v.x, v.y), fmaxf(v.z, v.w)));
    }
    for (int s = (n4 << 2) + tid; s < t; s += 256) m = fmaxf(m, p[s]);
#pragma unroll
    for (int o = 16; o; o >>= 1) m = fmaxf(m, __shfl_xor_sync(0xffffffffu, m, o));
    if ((tid & 31) == 0) red[tid >> 5] = m;
    __syncthreads();
    m = red[0];
#pragma unroll
    for (int w = 1; w < 8; w++) m = fmaxf(m, red[w]);
    __syncthreads();

    float sum = 0.0f;
    for (int q = tid; q < n4; q += 256) {
        const float4 v = p4[q];
        sum += __expf(v.x - m) + __expf(v.y - m) + __expf(v.z - m) + __expf(v.w - m);
    }
    for (int s = (n4 << 2) + tid; s < t; s += 256) sum += __expf(p[s] - m);
#pragma unroll
    for (int o = 16; o; o >>= 1) sum += __shfl_xor_sync(0xffffffffu, sum, o);
    if ((tid & 31) == 0) red[tid >> 5] = sum;
    __syncthreads();

    if (tid == 0) {
        sum = red[0] + red[1] + red[2] + red[3] + red[4] + red[5] + red[6] + red[7];
        stats[row] = make_float2(m, (t > 0) ? (1.0f / sum) : 0.0f);
    }
}

// ===========================================================================
extern "C" void kernel_launch(void* const* d_in, const int* in_sizes, int n_in,
                              void* d_out, int out_size)
{
    const float* x = (const float*)d_in[0];
    const float* W = (const float*)d_in[1];
    float* out = (float*)d_out;

    bf16 *xhi, *xlo, *whi, *wlo, *xHhi, *xHlo;
    float* sc; float2* stats;
    cudaGetSymbolAddress((void**)&xhi,   g_xhi);
    cudaGetSymbolAddress((void**)&xlo,   g_xlo);
    cudaGetSymbolAddress((void**)&whi,   g_whi);
    cudaGetSymbolAddress((void**)&wlo,   g_wlo);
    cudaGetSymbolAddress((void**)&xHhi,  g_xHhi);
    cudaGetSymbolAddress((void**)&xHlo,  g_xHlo);
    cudaGetSymbolAddress((void**)&sc,    g_sc);
    cudaGetSymbolAddress((void**)&stats, g_stats);

    cudaFuncSetAttribute(gemm_bf3<false, 2>,
                         cudaFuncAttributeMaxDynamicSharedMemorySize, SMEM_TOTAL);
    cudaFuncSetAttribute(gemm_bf3<true, 0>,
                         cudaFuncAttributeMaxDynamicSharedMemorySize, SMEM_TOTAL);
    cudaFuncSetAttribute(gemm_wei,
                         cudaFuncAttributeMaxDynamicSharedMemorySize, W_SMEM);

    split_bf16<<<8192, 256>>>(x, xhi, xlo, (long long)BB * TT * CC);
    split_bf16<<<2048, 256>>>(W, whi, wlo, (long long)CC * CC);

    // K1: xH = x @ W^T  -> bf16 hi/lo   (tiles 128x256)
    gemm_bf3<false, 2><<<dim3(CC / 256, (BB * TT) / 128, 1), 256, SMEM_TOTAL>>>(
        xhi, xlo, whi, wlo, nullptr, xHhi, xHlo,
        CC, CC, CC, CC, 0, 0, 0);

    // K2: scores(fp32) = x @ xH^T per batch, causal tiles only (128x256)
    gemm_bf3<true, 0><<<dim3(TT / 256, TT / 128, BB), 256, SMEM_TOTAL>>>(
        xhi, xlo, xHhi, xHlo, sc, nullptr, nullptr,
        CC, CC, TT, CC,
        (long long)TT * CC, (long long)TT * CC, (long long)TT * TT);

    // K3: row stats
    row_stats<<<BB * TT, 256>>>(sc, stats);

    // K4: out = -(wei @ xH), wei on the fly, K clamped
    gemm_wei<<<dim3(CC / 128, TT / 128, BB), 256, W_SMEM>>>(
        sc, stats, xHhi, xHlo, out);
}

// round 7
// speedup vs baseline: 1.0736x; 1.0736x over previous
#include <cuda_runtime.h>
#include <cuda_bf16.h>
#include <cstdint>

#define BB 8
#define TT 2048
#define CC 1024

typedef __nv_bfloat16 bf16;

// Scratch (device globals — allocation-free)
__device__ bf16   g_xhi  [(size_t)BB * TT * CC];
__device__ bf16   g_xlo  [(size_t)BB * TT * CC];
__device__ bf16   g_whi  [(size_t)CC * CC];
__device__ bf16   g_wlo  [(size_t)CC * CC];
__device__ bf16   g_xHhi [(size_t)BB * TT * CC];
__device__ bf16   g_xHlo [(size_t)BB * TT * CC];
__device__ float  g_sc   [(size_t)BB * TT * TT];
__device__ float2 g_stats[(size_t)BB * TT];

// ===========================================================================
// helpers
// ===========================================================================
__device__ __forceinline__ uint32_t smem_u32(const void* p) {
    uint32_t a;
    asm("{ .reg .u64 t; cvta.to.shared.u64 t, %1; cvt.u32.u64 %0, t; }" : "=r"(a) : "l"(p));
    return a;
}
__device__ __forceinline__ void cp16(uint32_t s, const void* g) {
    asm volatile("cp.async.cg.shared.global [%0], [%1], 16;" :: "r"(s), "l"(g) : "memory");
}
__device__ __forceinline__ void ldsm4(uint32_t addr, uint32_t& r0, uint32_t& r1,
                                      uint32_t& r2, uint32_t& r3) {
    asm volatile("ldmatrix.sync.aligned.m8n8.x4.shared.b16 {%0,%1,%2,%3}, [%4];"
                 : "=r"(r0), "=r"(r1), "=r"(r2), "=r"(r3) : "r"(addr));
}
__device__ __forceinline__ void ldsm4t(uint32_t addr, uint32_t& r0, uint32_t& r1,
                                       uint32_t& r2, uint32_t& r3) {
    asm volatile("ldmatrix.sync.aligned.m8n8.x4.trans.shared.b16 {%0,%1,%2,%3}, [%4];"
                 : "=r"(r0), "=r"(r1), "=r"(r2), "=r"(r3) : "r"(addr));
}
__device__ __forceinline__ void mma_bf16(float c[4], const uint32_t a[4], const uint32_t b[2]) {
    asm volatile(
        "mma.sync.aligned.m16n8k16.row.col.f32.bf16.bf16.f32 "
        "{%0,%1,%2,%3}, {%4,%5,%6,%7}, {%8,%9}, {%0,%1,%2,%3};"
        : "+f"(c[0]), "+f"(c[1]), "+f"(c[2]), "+f"(c[3])
        : "r"(a[0]), "r"(a[1]), "r"(a[2]), "r"(a[3]), "r"(b[0]), "r"(b[1]));
}

// swizzled 16B-chunk offset within a 128x32-bf16 (64B-row) K-major tile
__device__ __forceinline__ uint32_t swz(int row, int chunk) {
    return (uint32_t)(row * 64 + ((chunk ^ ((row >> 1) & 3)) << 4));
}

// ===========================================================================
// 3xBF16 GEMM:  C = A[M,K] @ B[N,K]^T, bf16 hi/lo inputs, 128x128 tile, KC=32
// 3-stage cp.async pipeline, swizzled 64B rows, 2 CTAs/SM.
// OUTMODE: 0 = fp32, 2 = bf16 hi/lo split pair
// ===========================================================================
#define AHI_OFF 0
#define ALO_OFF 8192
#define BHI_OFF 16384
#define BLO_OFF 24576
#define STG_BYTES 32768
#define SMEM_TOTAL (3 * STG_BYTES)   // 98304

template <bool CAUSAL, int OUTMODE>
__global__ __launch_bounds__(256, 2) void gemm_bf3(
    const bf16* __restrict__ Ahi, const bf16* __restrict__ Alo,
    const bf16* __restrict__ Bhi, const bf16* __restrict__ Blo,
    float* __restrict__ Cf, bf16* __restrict__ Chi, bf16* __restrict__ Clo,
    int lda, int ldb, int ldc, int Kfull,
    long long sA, long long sB, long long sC)
{
    const int bx = blockIdx.x, by = blockIdx.y, bz = blockIdx.z;
    if (CAUSAL && bx > by) return;

    Ahi += (long long)bz * sA; Alo += (long long)bz * sA;
    Bhi += (long long)bz * sB; Blo += (long long)bz * sB;

    const int m0 = by * 128, n0 = bx * 128;
    const int nc = Kfull / 32;

    extern __shared__ char smem[];
    const uint32_t sbase = smem_u32(smem);
    const int tid = threadIdx.x;
    const int wid = tid >> 5, lane = tid & 31;
    const int wm = wid & 1, wn = wid >> 1;
    const int g = lane >> 3, i = lane & 7;

    const int arow_base = wm * 64 + i + (g & 1) * 8;
    const int brow_base = wn * 32 + i + (g >> 1) * 8;
    const int achunk0 = g >> 1;
    const int bchunk0 = g & 1;

    const int l_row = tid >> 2, l_ch = tid & 3;
    const uint32_t l_soff0 = swz(l_row, l_ch);
    const uint32_t l_soff1 = swz(l_row + 64, l_ch);

    float acc[4][4][4];
#pragma unroll
    for (int a = 0; a < 4; a++)
#pragma unroll
        for (int b = 0; b < 4; b++)
#pragma unroll
            for (int c = 0; c < 4; c++) acc[a][b][c] = 0.f;

    auto issue = [&](int ch) {
        const uint32_t st = sbase + (uint32_t)(ch % 3) * STG_BYTES;
        const long long k0 = (long long)ch * 32 + l_ch * 8;
        {
            const long long ga = (long long)(m0 + l_row) * lda + k0;
            const long long gb = (long long)(n0 + l_row) * ldb + k0;
            cp16(st + AHI_OFF + l_soff0, Ahi + ga);
            cp16(st + ALO_OFF + l_soff0, Alo + ga);
            cp16(st + BHI_OFF + l_soff0, Bhi + gb);
            cp16(st + BLO_OFF + l_soff0, Blo + gb);
        }
        {
            const long long ga = (long long)(m0 + l_row + 64) * lda + k0;
            const long long gb = (long long)(n0 + l_row + 64) * ldb + k0;
            cp16(st + AHI_OFF + l_soff1, Ahi + ga);
            cp16(st + ALO_OFF + l_soff1, Alo + ga);
            cp16(st + BHI_OFF + l_soff1, Bhi + gb);
            cp16(st + BLO_OFF + l_soff1, Blo + gb);
        }
    };

#pragma unroll
    for (int s = 0; s < 2; s++) {
        if (s < nc) issue(s);
        asm volatile("cp.async.commit_group;" ::: "memory");
    }

    for (int ch = 0; ch < nc; ch++) {
        asm volatile("cp.async.wait_group 1;" ::: "memory");
        __syncthreads();
        if (ch + 2 < nc) issue(ch + 2);
        asm volatile("cp.async.commit_group;" ::: "memory");

        const uint32_t st = sbase + (uint32_t)(ch % 3) * STG_BYTES;

#pragma unroll
        for (int ks = 0; ks < 2; ks++) {
            uint32_t ah[4][4], al[4][4], bh[4][2], bl[4][2];
#pragma unroll
            for (int mt = 0; mt < 4; mt++) {
                const uint32_t ao = swz(arow_base + mt * 16, achunk0 + ks * 2);
                ldsm4(st + AHI_OFF + ao, ah[mt][0], ah[mt][1], ah[mt][2], ah[mt][3]);
                ldsm4(st + ALO_OFF + ao, al[mt][0], al[mt][1], al[mt][2], al[mt][3]);
            }
#pragma unroll
            for (int j = 0; j < 2; j++) {
                const uint32_t bo = swz(brow_base + j * 16, bchunk0 + ks * 2);
                uint32_t r0, r1, r2, r3;
                ldsm4(st + BHI_OFF + bo, r0, r1, r2, r3);
                bh[2 * j][0] = r0; bh[2 * j][1] = r1; bh[2 * j + 1][0] = r2; bh[2 * j + 1][1] = r3;
                ldsm4(st + BLO_OFF + bo, r0, r1, r2, r3);
                bl[2 * j][0] = r0; bl[2 * j][1] = r1; bl[2 * j + 1][0] = r2; bl[2 * j + 1][1] = r3;
            }
#pragma unroll
            for (int mt = 0; mt < 4; mt++)
#pragma unroll
                for (int nt = 0; nt < 4; nt++) mma_bf16(acc[mt][nt], ah[mt], bh[nt]);
#pragma unroll
            for (int mt = 0; mt < 4; mt++)
#pragma unroll
                for (int nt = 0; nt < 4; nt++) mma_bf16(acc[mt][nt], ah[mt], bl[nt]);
#pragma unroll
            for (int mt = 0; mt < 4; mt++)
#pragma unroll
                for (int nt = 0; nt < 4; nt++) mma_bf16(acc[mt][nt], al[mt], bh[nt]);
        }
    }

    // ---- epilogue ----
    const int rr = lane >> 2, cb = (lane & 3) * 2;
#pragma unroll
    for (int mt = 0; mt < 4; mt++) {
#pragma unroll
        for (int nt = 0; nt < 4; nt++) {
            const int row = m0 + wm * 64 + mt * 16 + rr;
            const int col = n0 + wn * 32 + nt * 8 + cb;
            const float s0 = acc[mt][nt][0], s1 = acc[mt][nt][1];
            const float s2 = acc[mt][nt][2], s3 = acc[mt][nt][3];
            if (OUTMODE == 0) {
                float* base = Cf + (long long)bz * sC;
                *(float2*)(base + (long long)row * ldc + col)       = make_float2(s0, s1);
                *(float2*)(base + (long long)(row + 8) * ldc + col) = make_float2(s2, s3);
            } else {
                bf16* oh = Chi + (long long)bz * sC;
                bf16* ol = Clo + (long long)bz * sC;
                bf16 h0 = __float2bfloat16(s0), h1 = __float2bfloat16(s1);
                bf16 h2 = __float2bfloat16(s2), h3 = __float2bfloat16(s3);
                bf16 l0 = __float2bfloat16(s0 - __bfloat162float(h0));
                bf16 l1 = __float2bfloat16(s1 - __bfloat162float(h1));
                bf16 l2 = __float2bfloat16(s2 - __bfloat162float(h2));
                bf16 l3 = __float2bfloat16(s3 - __bfloat162float(h3));
                *(__nv_bfloat162*)(oh + (long long)row * ldc + col)       = __halves2bfloat162(h0, h1);
                *(__nv_bfloat162*)(oh + (long long)(row + 8) * ldc + col) = __halves2bfloat162(h2, h3);
                *(__nv_bfloat162*)(ol + (long long)row * ldc + col)       = __halves2bfloat162(l0, l1);
                *(__nv_bfloat162*)(ol + (long long)(row + 8) * ldc + col) = __halves2bfloat162(l2, l3);
            }
        }
    }
}

// ===========================================================================
// K4: out[t][c] = -sum_s wei[t][s] * xH[s][c]
// wei from fp32 scores + row stats on the fly; 3 stages, 2 CTA/SM.
// LPT: by is REVERSED (longest-K CTAs launch first) to kill the tail wave.
// ===========================================================================
#define W_AHI 0
#define W_ALO 8192
#define W_BHI 16384
#define W_BLO 25088
#define W_STG 33792
#define W_SMEM (3 * W_STG)   // 101376

__global__ __launch_bounds__(256, 2) void gemm_wei(
    const float* __restrict__ scA, const float2* __restrict__ stats,
    const bf16* __restrict__ Bhi, const bf16* __restrict__ Blo,
    float* __restrict__ Out)
{
    const int bx = blockIdx.x, bz = blockIdx.z;
    const int by = (int)gridDim.y - 1 - (int)blockIdx.y;   // LPT: longest first
    const float* sc = scA + (long long)bz * TT * TT;
    const float2* stt = stats + (long long)bz * TT;
    const bf16* bhi = Bhi + (long long)bz * TT * CC;
    const bf16* blo = Blo + (long long)bz * TT * CC;
    float* out = Out + (long long)bz * TT * CC;

    const int m0 = by * 128, n0 = bx * 128;
    const int Klim = min(TT, (by + 1) * 128);
    const int nc = Klim / 32;

    extern __shared__ char smem[];
    const uint32_t sbase = smem_u32(smem);
    const int tid = threadIdx.x;
    const int wid = tid >> 5, lane = tid & 31;
    const int wm = wid & 1, wn = wid >> 1;
    const int g = lane >> 3, i = lane & 7;

    const int arow_base = wm * 64 + i + (g & 1) * 8;
    const int achunk0 = g >> 1;
    const uint32_t bLaneT = (uint32_t)((lane & 15) * 272 + (lane >> 4) * 16 + wn * 64);

    const int arow = tid >> 1, aseg = tid & 1;
    const int t_glob = m0 + arow;
    const float2 rs = stt[t_glob];
    float4 pa[4];

    auto ldgA = [&](int ch) {
        const float* src = sc + (long long)t_glob * TT + ch * 32 + aseg * 16;
        pa[0] = *(const float4*)(src + 0);
        pa[1] = *(const float4*)(src + 4);
        pa[2] = *(const float4*)(src + 8);
        pa[3] = *(const float4*)(src + 12);
    };
    auto stsA = [&](int ch) {
        char* stg = smem + (size_t)(ch % 3) * W_STG;
        const int sb0 = ch * 32 + aseg * 16;
        uint32_t hi[8], lo[8];
#pragma unroll
        for (int q = 0; q < 4; q++) {
            const float vv[4] = { pa[q].x, pa[q].y, pa[q].z, pa[q].w };
            float w[4];
#pragma unroll
            for (int e = 0; e < 4; e++) {
                const int s = sb0 + q * 4 + e;
                w[e] = (s < t_glob) ? __expf(vv[e] - rs.x) * rs.y : 0.0f;
            }
#pragma unroll
            for (int e = 0; e < 4; e += 2) {
                const bf16 h0 = __float2bfloat16(w[e]);
                const bf16 h1 = __float2bfloat16(w[e + 1]);
                const bf16 l0 = __float2bfloat16(w[e] - __bfloat162float(h0));
                const bf16 l1 = __float2bfloat16(w[e + 1] - __bfloat162float(h1));
                __nv_bfloat162 ph = __halves2bfloat162(h0, h1);
                __nv_bfloat162 pl = __halves2bfloat162(l0, l1);
                hi[q * 2 + e / 2] = *(uint32_t*)&ph;
                lo[q * 2 + e / 2] = *(uint32_t*)&pl;
            }
        }
        const uint32_t o0 = swz(arow, 2 * aseg);
        const uint32_t o1 = swz(arow, 2 * aseg + 1);
        *(uint4*)(stg + W_AHI + o0) = *(uint4*)(hi + 0);
        *(uint4*)(stg + W_AHI + o1) = *(uint4*)(hi + 4);
        *(uint4*)(stg + W_ALO + o0) = *(uint4*)(lo + 0);
        *(uint4*)(stg + W_ALO + o1) = *(uint4*)(lo + 4);
    };
    auto issueB = [&](int ch) {
        const uint32_t st = sbase + (uint32_t)(ch % 3) * W_STG;
        const long long k0 = (long long)ch * 32;
#pragma unroll
        for (int r = 0; r < 2; r++) {
            const int idx = tid + r * 256;
            const int brow = idx >> 4, bseg = idx & 15;
            const long long go = (k0 + brow) * CC + n0 + bseg * 8;
            const uint32_t so = (uint32_t)(brow * 272 + bseg * 16);
            cp16(st + W_BHI + so, bhi + go);
            cp16(st + W_BLO + so, blo + go);
        }
    };

    float acc[4][4][4];
#pragma unroll
    for (int a = 0; a < 4; a++)
#pragma unroll
        for (int b = 0; b < 4; b++)
#pragma unroll
            for (int c = 0; c < 4; c++) acc[a][b][c] = 0.f;

    ldgA(0);
#pragma unroll
    for (int s = 0; s < 2; s++) {
        if (s < nc) issueB(s);
        asm volatile("cp.async.commit_group;" ::: "memory");
    }

    for (int ch = 0; ch < nc; ch++) {
        asm volatile("cp.async.wait_group 1;" ::: "memory");
        stsA(ch);
        __syncthreads();
        if (ch + 1 < nc) ldgA(ch + 1);
        if (ch + 2 < nc) issueB(ch + 2);
        asm volatile("cp.async.commit_group;" ::: "memory");

        const uint32_t st = sbase + (uint32_t)(ch % 3) * W_STG;

#pragma unroll
        for (int ks = 0; ks < 2; ks++) {
            uint32_t ah[4][4], al[4][4], bh[4][2], bl[4][2];
#pragma unroll
            for (int mt = 0; mt < 4; mt++) {
                const uint32_t ao = swz(arow_base + mt * 16, achunk0 + ks * 2);
                ldsm4(st + W_AHI + ao, ah[mt][0], ah[mt][1], ah[mt][2], ah[mt][3]);
                ldsm4(st + W_ALO + ao, al[mt][0], al[mt][1], al[mt][2], al[mt][3]);
            }
#pragma unroll
            for (int j = 0; j < 2; j++) {
                uint32_t r0, r1, r2, r3;
                ldsm4t(st + W_BHI + bLaneT + ks * (16 * 272) + j * 32, r0, r1, r2, r3);
                bh[2 * j][0] = r0; bh[2 * j][1] = r1; bh[2 * j + 1][0] = r2; bh[2 * j + 1][1] = r3;
                ldsm4t(st + W_BLO + bLaneT + ks * (16 * 272) + j * 32, r0, r1, r2, r3);
                bl[2 * j][0] = r0; bl[2 * j][1] = r1; bl[2 * j + 1][0] = r2; bl[2 * j + 1][1] = r3;
            }
#pragma unroll
            for (int mt = 0; mt < 4; mt++)
#pragma unroll
                for (int nt = 0; nt < 4; nt++) mma_bf16(acc[mt][nt], ah[mt], bh[nt]);
#pragma unroll
            for (int mt = 0; mt < 4; mt++)
#pragma unroll
                for (int nt = 0; nt < 4; nt++) mma_bf16(acc[mt][nt], ah[mt], bl[nt]);
#pragma unroll
            for (int mt = 0; mt < 4; mt++)
#pragma unroll
                for (int nt = 0; nt < 4; nt++) mma_bf16(acc[mt][nt], al[mt], bh[nt]);
        }
    }

    const int rr = lane >> 2, cb = (lane & 3) * 2;
#pragma unroll
    for (int mt = 0; mt < 4; mt++) {
#pragma unroll
        for (int nt = 0; nt < 4; nt++) {
            const int row = m0 + wm * 64 + mt * 16 + rr;
            const int col = n0 + wn * 32 + nt * 8 + cb;
            *(float2*)(out + (long long)row * CC + col) =
                make_float2(-acc[mt][nt][0], -acc[mt][nt][1]);
            *(float2*)(out + (long long)(row + 8) * CC + col) =
                make_float2(-acc[mt][nt][2], -acc[mt][nt][3]);
        }
    }
}

// ===========================================================================
__global__ __launch_bounds__(256) void split_bf16(
    const float* __restrict__ src, bf16* __restrict__ hi, bf16* __restrict__ lo, long long n)
{
    for (long long idx = (long long)blockIdx.x * 256 + threadIdx.x; idx < n;
         idx += (long long)gridDim.x * 256) {
        const float x = src[idx];
        const bf16 h = __float2bfloat16(x);
        hi[idx] = h;
        lo[idx] = __float2bfloat16(x - __bfloat162float(h));
    }
}

__global__ __launch_bounds__(256) void row_stats(
    const float* __restrict__ sc, float2* __restrict__ stats)
{
    const long long row = blockIdx.x;
    const int t = (int)(row % TT);
    const float* p = sc + row * TT;
    const float4* p4 = (const float4*)p;
    const int n4 = t >> 2;
    const int tid = threadIdx.x;

    __shared__ float red[8];

    float m = -3.0e38f;
    for (int q = tid; q < n4; q += 256) {
        const float4 v = p4[q];
        m = fmaxf(m, fmaxf(fmaxf(v.x, v.y), fmaxf(v.z, v.w)));
    }
    for (int s = (n4 << 2) + tid; s < t; s += 256) m = fmaxf(m, p[s]);
#pragma unroll
    for (int o = 16; o; o >>= 1) m = fmaxf(m, __shfl_xor_sync(0xffffffffu, m, o));
    if ((tid & 31) == 0) red[tid >> 5] = m;
    __syncthreads();
    m = red[0];
#pragma unroll
    for (int w = 1; w < 8; w++) m = fmaxf(m, red[w]);
    __syncthreads();

    float sum = 0.0f;
    for (int q = tid; q < n4; q += 256) {
        const float4 v = p4[q];
        sum += __expf(v.x - m) + __expf(v.y - m) + __expf(v.z - m) + __expf(v.w - m);
    }
    for (int s = (n4 << 2) + tid; s < t; s += 256) sum += __expf(p[s] - m);
#pragma unroll
    for (int o = 16; o; o >>= 1) sum += __shfl_xor_sync(0xffffffffu, sum, o);
    if ((tid & 31) == 0) red[tid >> 5] = sum;
    __syncthreads();

    if (tid == 0) {
        sum = red[0] + red[1] + red[2] + red[3] + red[4] + red[5] + red[6] + red[7];
        stats[row] = make_float2(m, (t > 0) ? (1.0f / sum) : 0.0f);
    }
}

// ===========================================================================
extern "C" void kernel_launch(void* const* d_in, const int* in_sizes, int n_in,
                              void* d_out, int out_size)
{
    const float* x = (const float*)d_in[0];
    const float* W = (const float*)d_in[1];
    float* out = (float*)d_out;

    bf16 *xhi, *xlo, *whi, *wlo, *xHhi, *xHlo;
    float* sc; float2* stats;
    cudaGetSymbolAddress((void**)&xhi,   g_xhi);
    cudaGetSymbolAddress((void**)&xlo,   g_xlo);
    cudaGetSymbolAddress((void**)&whi,   g_whi);
    cudaGetSymbolAddress((void**)&wlo,   g_wlo);
    cudaGetSymbolAddress((void**)&xHhi,  g_xHhi);
    cudaGetSymbolAddress((void**)&xHlo,  g_xHlo);
    cudaGetSymbolAddress((void**)&sc,    g_sc);
    cudaGetSymbolAddress((void**)&stats, g_stats);

    cudaFuncSetAttribute(gemm_bf3<false, 2>,
                         cudaFuncAttributeMaxDynamicSharedMemorySize, SMEM_TOTAL);
    cudaFuncSetAttribute(gemm_bf3<true, 0>,
                         cudaFuncAttributeMaxDynamicSharedMemorySize, SMEM_TOTAL);
    cudaFuncSetAttribute(gemm_wei,
                         cudaFuncAttributeMaxDynamicSharedMemorySize, W_SMEM);

    split_bf16<<<8192, 256>>>(x, xhi, xlo, (long long)BB * TT * CC);
    split_bf16<<<2048, 256>>>(W, whi, wlo, (long long)CC * CC);

    // K1: xH = x @ W^T  -> bf16 hi/lo   (128x128 tiles, 2 CTA/SM)
    gemm_bf3<false, 2><<<dim3(CC / 128, (BB * TT) / 128, 1), 256, SMEM_TOTAL>>>(
        xhi, xlo, whi, wlo, nullptr, xHhi, xHlo,
        CC, CC, CC, CC, 0, 0, 0);

    // K2: scores(fp32) = x @ xH^T per batch, causal tiles only
    gemm_bf3<true, 0><<<dim3(TT / 128, TT / 128, BB), 256, SMEM_TOTAL>>>(
        xhi, xlo, xHhi, xHlo, sc, nullptr, nullptr,
        CC, CC, TT, CC,
        (long long)TT * CC, (long long)TT * CC, (long long)TT * TT);

    // K3: row stats
    row_stats<<<BB * TT, 256>>>(sc, stats);

    // K4: out = -(wei @ xH), wei on the fly, K clamped, LPT-ordered
    gemm_wei<<<dim3(CC / 128, TT / 128, BB), 256, W_SMEM>>>(
        sc, stats, xHhi, xHlo, out);
}

// round 8
// speedup vs baseline: 1.1449x; 1.0664x over previous
#include <cuda_runtime.h>
#include <cuda_bf16.h>
#include <cstdint>

#define BB 8
#define TT 2048
#define CC 1024

typedef __nv_bfloat16 bf16;

// Scratch (device globals — allocation-free)
__device__ bf16   g_xhi  [(size_t)BB * TT * CC];
__device__ bf16   g_xlo  [(size_t)BB * TT * CC];
__device__ bf16   g_whi  [(size_t)CC * CC];
__device__ bf16   g_wlo  [(size_t)CC * CC];
__device__ bf16   g_xHhi [(size_t)BB * TT * CC];
__device__ bf16   g_xHlo [(size_t)BB * TT * CC];
__device__ float  g_sc   [(size_t)BB * TT * TT];
__device__ bf16   g_weihi[(size_t)BB * TT * TT];   // 64 MB
__device__ bf16   g_weilo[(size_t)BB * TT * TT];   // 64 MB

// ===========================================================================
// helpers
// ===========================================================================
__device__ __forceinline__ uint32_t smem_u32(const void* p) {
    uint32_t a;
    asm("{ .reg .u64 t; cvta.to.shared.u64 t, %1; cvt.u32.u64 %0, t; }" : "=r"(a) : "l"(p));
    return a;
}
__device__ __forceinline__ void cp16(uint32_t s, const void* g) {
    asm volatile("cp.async.cg.shared.global [%0], [%1], 16;" :: "r"(s), "l"(g) : "memory");
}
__device__ __forceinline__ void ldsm4(uint32_t addr, uint32_t& r0, uint32_t& r1,
                                      uint32_t& r2, uint32_t& r3) {
    asm volatile("ldmatrix.sync.aligned.m8n8.x4.shared.b16 {%0,%1,%2,%3}, [%4];"
                 : "=r"(r0), "=r"(r1), "=r"(r2), "=r"(r3) : "r"(addr));
}
__device__ __forceinline__ void ldsm4t(uint32_t addr, uint32_t& r0, uint32_t& r1,
                                       uint32_t& r2, uint32_t& r3) {
    asm volatile("ldmatrix.sync.aligned.m8n8.x4.trans.shared.b16 {%0,%1,%2,%3}, [%4];"
                 : "=r"(r0), "=r"(r1), "=r"(r2), "=r"(r3) : "r"(addr));
}
__device__ __forceinline__ void mma_bf16(float c[4], const uint32_t a[4], const uint32_t b[2]) {
    asm volatile(
        "mma.sync.aligned.m16n8k16.row.col.f32.bf16.bf16.f32 "
        "{%0,%1,%2,%3}, {%4,%5,%6,%7}, {%8,%9}, {%0,%1,%2,%3};"
        : "+f"(c[0]), "+f"(c[1]), "+f"(c[2]), "+f"(c[3])
        : "r"(a[0]), "r"(a[1]), "r"(a[2]), "r"(a[3]), "r"(b[0]), "r"(b[1]));
}

// swizzled 16B-chunk offset within a 128x32-bf16 (64B-row) K-major tile
__device__ __forceinline__ uint32_t swz(int row, int chunk) {
    return (uint32_t)(row * 64 + ((chunk ^ ((row >> 1) & 3)) << 4));
}

// ===========================================================================
// 3xBF16 GEMM:  C = A[M,K] @ B[N,K]^T, bf16 hi/lo inputs, 128x128 tile, KC=32
// 3-stage cp.async pipeline, swizzled 64B rows, 2 CTAs/SM.
// OUTMODE: 0 = fp32, 2 = bf16 hi/lo split pair
// ===========================================================================
#define AHI_OFF 0
#define ALO_OFF 8192
#define BHI_OFF 16384
#define BLO_OFF 24576
#define STG_BYTES 32768
#define SMEM_TOTAL (3 * STG_BYTES)   // 98304

template <bool CAUSAL, int OUTMODE>
__global__ __launch_bounds__(256, 2) void gemm_bf3(
    const bf16* __restrict__ Ahi, const bf16* __restrict__ Alo,
    const bf16* __restrict__ Bhi, const bf16* __restrict__ Blo,
    float* __restrict__ Cf, bf16* __restrict__ Chi, bf16* __restrict__ Clo,
    int lda, int ldb, int ldc, int Kfull,
    long long sA, long long sB, long long sC)
{
    const int bx = blockIdx.x, by = blockIdx.y, bz = blockIdx.z;
    if (CAUSAL && bx > by) return;

    Ahi += (long long)bz * sA; Alo += (long long)bz * sA;
    Bhi += (long long)bz * sB; Blo += (long long)bz * sB;

    const int m0 = by * 128, n0 = bx * 128;
    const int nc = Kfull / 32;

    extern __shared__ char smem[];
    const uint32_t sbase = smem_u32(smem);
    const int tid = threadIdx.x;
    const int wid = tid >> 5, lane = tid & 31;
    const int wm = wid & 1, wn = wid >> 1;
    const int g = lane >> 3, i = lane & 7;

    const int arow_base = wm * 64 + i + (g & 1) * 8;
    const int brow_base = wn * 32 + i + (g >> 1) * 8;
    const int achunk0 = g >> 1;
    const int bchunk0 = g & 1;

    const int l_row = tid >> 2, l_ch = tid & 3;
    const uint32_t l_soff0 = swz(l_row, l_ch);
    const uint32_t l_soff1 = swz(l_row + 64, l_ch);

    float acc[4][4][4];
#pragma unroll
    for (int a = 0; a < 4; a++)
#pragma unroll
        for (int b = 0; b < 4; b++)
#pragma unroll
            for (int c = 0; c < 4; c++) acc[a][b][c] = 0.f;

    auto issue = [&](int ch) {
        const uint32_t st = sbase + (uint32_t)(ch % 3) * STG_BYTES;
        const long long k0 = (long long)ch * 32 + l_ch * 8;
        {
            const long long ga = (long long)(m0 + l_row) * lda + k0;
            const long long gb = (long long)(n0 + l_row) * ldb + k0;
            cp16(st + AHI_OFF + l_soff0, Ahi + ga);
            cp16(st + ALO_OFF + l_soff0, Alo + ga);
            cp16(st + BHI_OFF + l_soff0, Bhi + gb);
            cp16(st + BLO_OFF + l_soff0, Blo + gb);
        }
        {
            const long long ga = (long long)(m0 + l_row + 64) * lda + k0;
            const long long gb = (long long)(n0 + l_row + 64) * ldb + k0;
            cp16(st + AHI_OFF + l_soff1, Ahi + ga);
            cp16(st + ALO_OFF + l_soff1, Alo + ga);
            cp16(st + BHI_OFF + l_soff1, Bhi + gb);
            cp16(st + BLO_OFF + l_soff1, Blo + gb);
        }
    };

#pragma unroll
    for (int s = 0; s < 2; s++) {
        if (s < nc) issue(s);
        asm volatile("cp.async.commit_group;" ::: "memory");
    }

    for (int ch = 0; ch < nc; ch++) {
        asm volatile("cp.async.wait_group 1;" ::: "memory");
        __syncthreads();
        if (ch + 2 < nc) issue(ch + 2);
        asm volatile("cp.async.commit_group;" ::: "memory");

        const uint32_t st = sbase + (uint32_t)(ch % 3) * STG_BYTES;

#pragma unroll
        for (int ks = 0; ks < 2; ks++) {
            uint32_t ah[4][4], al[4][4], bh[4][2], bl[4][2];
#pragma unroll
            for (int mt = 0; mt < 4; mt++) {
                const uint32_t ao = swz(arow_base + mt * 16, achunk0 + ks * 2);
                ldsm4(st + AHI_OFF + ao, ah[mt][0], ah[mt][1], ah[mt][2], ah[mt][3]);
                ldsm4(st + ALO_OFF + ao, al[mt][0], al[mt][1], al[mt][2], al[mt][3]);
            }
#pragma unroll
            for (int j = 0; j < 2; j++) {
                const uint32_t bo = swz(brow_base + j * 16, bchunk0 + ks * 2);
                uint32_t r0, r1, r2, r3;
                ldsm4(st + BHI_OFF + bo, r0, r1, r2, r3);
                bh[2 * j][0] = r0; bh[2 * j][1] = r1; bh[2 * j + 1][0] = r2; bh[2 * j + 1][1] = r3;
                ldsm4(st + BLO_OFF + bo, r0, r1, r2, r3);
                bl[2 * j][0] = r0; bl[2 * j][1] = r1; bl[2 * j + 1][0] = r2; bl[2 * j + 1][1] = r3;
            }
#pragma unroll
            for (int mt = 0; mt < 4; mt++)
#pragma unroll
                for (int nt = 0; nt < 4; nt++) mma_bf16(acc[mt][nt], ah[mt], bh[nt]);
#pragma unroll
            for (int mt = 0; mt < 4; mt++)
#pragma unroll
                for (int nt = 0; nt < 4; nt++) mma_bf16(acc[mt][nt], ah[mt], bl[nt]);
#pragma unroll
            for (int mt = 0; mt < 4; mt++)
#pragma unroll
                for (int nt = 0; nt < 4; nt++) mma_bf16(acc[mt][nt], al[mt], bh[nt]);
        }
    }

    // ---- epilogue ----
    const int rr = lane >> 2, cb = (lane & 3) * 2;
#pragma unroll
    for (int mt = 0; mt < 4; mt++) {
#pragma unroll
        for (int nt = 0; nt < 4; nt++) {
            const int row = m0 + wm * 64 + mt * 16 + rr;
            const int col = n0 + wn * 32 + nt * 8 + cb;
            const float s0 = acc[mt][nt][0], s1 = acc[mt][nt][1];
            const float s2 = acc[mt][nt][2], s3 = acc[mt][nt][3];
            if (OUTMODE == 0) {
                float* base = Cf + (long long)bz * sC;
                *(float2*)(base + (long long)row * ldc + col)       = make_float2(s0, s1);
                *(float2*)(base + (long long)(row + 8) * ldc + col) = make_float2(s2, s3);
            } else {
                bf16* oh = Chi + (long long)bz * sC;
                bf16* ol = Clo + (long long)bz * sC;
                bf16 h0 = __float2bfloat16(s0), h1 = __float2bfloat16(s1);
                bf16 h2 = __float2bfloat16(s2), h3 = __float2bfloat16(s3);
                bf16 l0 = __float2bfloat16(s0 - __bfloat162float(h0));
                bf16 l1 = __float2bfloat16(s1 - __bfloat162float(h1));
                bf16 l2 = __float2bfloat16(s2 - __bfloat162float(h2));
                bf16 l3 = __float2bfloat16(s3 - __bfloat162float(h3));
                *(__nv_bfloat162*)(oh + (long long)row * ldc + col)       = __halves2bfloat162(h0, h1);
                *(__nv_bfloat162*)(oh + (long long)(row + 8) * ldc + col) = __halves2bfloat162(h2, h3);
                *(__nv_bfloat162*)(ol + (long long)row * ldc + col)       = __halves2bfloat162(l0, l1);
                *(__nv_bfloat162*)(ol + (long long)(row + 8) * ldc + col) = __halves2bfloat162(l2, l3);
            }
        }
    }
}

// ===========================================================================
// K4: out[t][c] = -sum_s wei[t][s] * xH[s][c]
// Pure 3xBF16 GEMM: A = wei (bf16 hi/lo, K-major [t][s]), B = xH read
// MN-major with trans-ldmatrix. K clamped, LPT, 3 stages, 2 CTA/SM.
// ===========================================================================
#define W_AHI 0
#define W_ALO 8192
#define W_BHI 16384
#define W_BLO 25088
#define W_STG 33792
#define W_SMEM (3 * W_STG)   // 101376

__global__ __launch_bounds__(256, 2) void gemm_wei(
    const bf16* __restrict__ Whi, const bf16* __restrict__ Wlo,
    const bf16* __restrict__ Bhi, const bf16* __restrict__ Blo,
    float* __restrict__ Out)
{
    const int bx = blockIdx.x, bz = blockIdx.z;
    const int by = (int)gridDim.y - 1 - (int)blockIdx.y;   // LPT: longest first
    const bf16* whi = Whi + (long long)bz * TT * TT;
    const bf16* wlo = Wlo + (long long)bz * TT * TT;
    const bf16* bhi = Bhi + (long long)bz * TT * CC;
    const bf16* blo = Blo + (long long)bz * TT * CC;
    float* out = Out + (long long)bz * TT * CC;

    const int m0 = by * 128, n0 = bx * 128;
    const int Klim = min(TT, (by + 1) * 128);
    const int nc = Klim / 32;

    extern __shared__ char smem[];
    const uint32_t sbase = smem_u32(smem);
    const int tid = threadIdx.x;
    const int wid = tid >> 5, lane = tid & 31;
    const int wm = wid & 1, wn = wid >> 1;
    const int g = lane >> 3, i = lane & 7;

    const int arow_base = wm * 64 + i + (g & 1) * 8;
    const int achunk0 = g >> 1;
    const uint32_t bLaneT = (uint32_t)((lane & 15) * 272 + (lane >> 4) * 16 + wn * 64);

    const int l_row = tid >> 2, l_ch = tid & 3;
    const uint32_t l_soff0 = swz(l_row, l_ch);
    const uint32_t l_soff1 = swz(l_row + 64, l_ch);

    float acc[4][4][4];
#pragma unroll
    for (int a = 0; a < 4; a++)
#pragma unroll
        for (int b = 0; b < 4; b++)
#pragma unroll
            for (int c = 0; c < 4; c++) acc[a][b][c] = 0.f;

    auto issue = [&](int ch) {
        const uint32_t st = sbase + (uint32_t)(ch % 3) * W_STG;
        const long long k0 = (long long)ch * 32 + l_ch * 8;
        // A (wei): 128 t-rows x 32 s-cols, K-major, swizzled
        {
            const long long ga = (long long)(m0 + l_row) * TT + k0;
            cp16(st + W_AHI + l_soff0, whi + ga);
            cp16(st + W_ALO + l_soff0, wlo + ga);
            const long long ga1 = (long long)(m0 + l_row + 64) * TT + k0;
            cp16(st + W_AHI + l_soff1, whi + ga1);
            cp16(st + W_ALO + l_soff1, wlo + ga1);
        }
        // B (xH): 32 s-rows x 128 c-cols, MN-major (272B pad)
        const long long kb = (long long)ch * 32;
#pragma unroll
        for (int r = 0; r < 2; r++) {
            const int idx = tid + r * 256;
            const int brow = idx >> 4, bseg = idx & 15;
            const long long go = (kb + brow) * CC + n0 + bseg * 8;
            const uint32_t so = (uint32_t)(brow * 272 + bseg * 16);
            cp16(st + W_BHI + so, bhi + go);
            cp16(st + W_BLO + so, blo + go);
        }
    };

#pragma unroll
    for (int s = 0; s < 2; s++) {
        if (s < nc) issue(s);
        asm volatile("cp.async.commit_group;" ::: "memory");
    }

    for (int ch = 0; ch < nc; ch++) {
        asm volatile("cp.async.wait_group 1;" ::: "memory");
        __syncthreads();
        if (ch + 2 < nc) issue(ch + 2);
        asm volatile("cp.async.commit_group;" ::: "memory");

        const uint32_t st = sbase + (uint32_t)(ch % 3) * W_STG;

#pragma unroll
        for (int ks = 0; ks < 2; ks++) {
            uint32_t ah[4][4], al[4][4], bh[4][2], bl[4][2];
#pragma unroll
            for (int mt = 0; mt < 4; mt++) {
                const uint32_t ao = swz(arow_base + mt * 16, achunk0 + ks * 2);
                ldsm4(st + W_AHI + ao, ah[mt][0], ah[mt][1], ah[mt][2], ah[mt][3]);
                ldsm4(st + W_ALO + ao, al[mt][0], al[mt][1], al[mt][2], al[mt][3]);
            }
#pragma unroll
            for (int j = 0; j < 2; j++) {
                uint32_t r0, r1, r2, r3;
                ldsm4t(st + W_BHI + bLaneT + ks * (16 * 272) + j * 32, r0, r1, r2, r3);
                bh[2 * j][0] = r0; bh[2 * j][1] = r1; bh[2 * j + 1][0] = r2; bh[2 * j + 1][1] = r3;
                ldsm4t(st + W_BLO + bLaneT + ks * (16 * 272) + j * 32, r0, r1, r2, r3);
                bl[2 * j][0] = r0; bl[2 * j][1] = r1; bl[2 * j + 1][0] = r2; bl[2 * j + 1][1] = r3;
            }
#pragma unroll
            for (int mt = 0; mt < 4; mt++)
#pragma unroll
                for (int nt = 0; nt < 4; nt++) mma_bf16(acc[mt][nt], ah[mt], bh[nt]);
#pragma unroll
            for (int mt = 0; mt < 4; mt++)
#pragma unroll
                for (int nt = 0; nt < 4; nt++) mma_bf16(acc[mt][nt], ah[mt], bl[nt]);
#pragma unroll
            for (int mt = 0; mt < 4; mt++)
#pragma unroll
                for (int nt = 0; nt < 4; nt++) mma_bf16(acc[mt][nt], al[mt], bh[nt]);
        }
    }

    const int rr = lane >> 2, cb = (lane & 3) * 2;
#pragma unroll
    for (int mt = 0; mt < 4; mt++) {
#pragma unroll
        for (int nt = 0; nt < 4; nt++) {
            const int row = m0 + wm * 64 + mt * 16 + rr;
            const int col = n0 + wn * 32 + nt * 8 + cb;
            *(float2*)(out + (long long)row * CC + col) =
                make_float2(-acc[mt][nt][0], -acc[mt][nt][1]);
            *(float2*)(out + (long long)(row + 8) * CC + col) =
                make_float2(-acc[mt][nt][2], -acc[mt][nt][3]);
        }
    }
}

// ===========================================================================
// fp32 -> bf16 hi/lo split
// ===========================================================================
__global__ __launch_bounds__(256) void split_bf16(
    const float* __restrict__ src, bf16* __restrict__ hi, bf16* __restrict__ lo, long long n)
{
    for (long long idx = (long long)blockIdx.x * 256 + threadIdx.x; idx < n;
         idx += (long long)gridDim.x * 256) {
        const float x = src[idx];
        const bf16 h = __float2bfloat16(x);
        hi[idx] = h;
        lo[idx] = __float2bfloat16(x - __bfloat162float(h));
    }
}

// ===========================================================================
// Causal softmax: fp32 scores -> wei bf16 hi/lo (zeros at/after diagonal).
// One block per row; LPT order (longest rows first).
// ===========================================================================
__global__ __launch_bounds__(256) void softmax_causal(
    const float* __restrict__ sc, bf16* __restrict__ whi, bf16* __restrict__ wlo)
{
    const long long row = (long long)(BB * TT - 1) - blockIdx.x;   // LPT
    const int t = (int)(row % TT);
    const float* p = sc + row * TT;
    bf16* oh = whi + row * TT;
    bf16* ol = wlo + row * TT;
    const int tid = threadIdx.x;
    const float4* p4 = (const float4*)p;
    const int n4 = t >> 2;

    __shared__ float red[8];

    float m = -3.0e38f;
    for (int q = tid; q < n4; q += 256) {
        const float4 v = p4[q];
        m = fmaxf(m, fmaxf(fmaxf(v.x, v.y), fmaxf(v.z, v.w)));
    }
    for (int s = (n4 << 2) + tid; s < t; s += 256) m = fmaxf(m, p[s]);
#pragma unroll
    for (int o = 16; o; o >>= 1) m = fmaxf(m, __shfl_xor_sync(0xffffffffu, m, o));
    if ((tid & 31) == 0) red[tid >> 5] = m;
    __syncthreads();
    m = red[0];
#pragma unroll
    for (int w = 1; w < 8; w++) m = fmaxf(m, red[w]);
    __syncthreads();

    float sum = 0.0f;
    for (int q = tid; q < n4; q += 256) {
        const float4 v = p4[q];
        sum += __expf(v.x - m) + __expf(v.y - m) + __expf(v.z - m) + __expf(v.w - m);
    }
    for (int s = (n4 << 2) + tid; s < t; s += 256) sum += __expf(p[s] - m);
#pragma unroll
    for (int o = 16; o; o >>= 1) sum += __shfl_xor_sync(0xffffffffu, sum, o);
    if ((tid & 31) == 0) red[tid >> 5] = sum;
    __syncthreads();
    sum = red[0] + red[1] + red[2] + red[3] + red[4] + red[5] + red[6] + red[7];

    const float inv = (t > 0) ? (1.0f / sum) : 0.0f;

    // write wei (4 per thread per step; zeros at/after diagonal)
    for (int s0 = tid * 4; s0 < TT; s0 += 1024) {
        float w[4];
#pragma unroll
        for (int e = 0; e < 4; e++) {
            const int s = s0 + e;
            w[e] = (s < t) ? __expf(p[s] - m) * inv : 0.0f;
        }
        bf16 h[4], l[4];
#pragma unroll
        for (int e = 0; e < 4; e++) {
            h[e] = __float2bfloat16(w[e]);
            l[e] = __float2bfloat16(w[e] - __bfloat162float(h[e]));
        }
        *(__nv_bfloat162*)(oh + s0)     = __halves2bfloat162(h[0], h[1]);
        *(__nv_bfloat162*)(oh + s0 + 2) = __halves2bfloat162(h[2], h[3]);
        *(__nv_bfloat162*)(ol + s0)     = __halves2bfloat162(l[0], l[1]);
        *(__nv_bfloat162*)(ol + s0 + 2) = __halves2bfloat162(l[2], l[3]);
    }
}

// ===========================================================================
extern "C" void kernel_launch(void* const* d_in, const int* in_sizes, int n_in,
                              void* d_out, int out_size)
{
    const float* x = (const float*)d_in[0];
    const float* W = (const float*)d_in[1];
    float* out = (float*)d_out;

    bf16 *xhi, *xlo, *whi, *wlo, *xHhi, *xHlo, *weihi, *weilo;
    float* sc;
    cudaGetSymbolAddress((void**)&xhi,   g_xhi);
    cudaGetSymbolAddress((void**)&xlo,   g_xlo);
    cudaGetSymbolAddress((void**)&whi,   g_whi);
    cudaGetSymbolAddress((void**)&wlo,   g_wlo);
    cudaGetSymbolAddress((void**)&xHhi,  g_xHhi);
    cudaGetSymbolAddress((void**)&xHlo,  g_xHlo);
    cudaGetSymbolAddress((void**)&weihi, g_weihi);
    cudaGetSymbolAddress((void**)&weilo, g_weilo);
    cudaGetSymbolAddress((void**)&sc,    g_sc);

    cudaFuncSetAttribute(gemm_bf3<false, 2>,
                         cudaFuncAttributeMaxDynamicSharedMemorySize, SMEM_TOTAL);
    cudaFuncSetAttribute(gemm_bf3<true, 0>,
                         cudaFuncAttributeMaxDynamicSharedMemorySize, SMEM_TOTAL);
    cudaFuncSetAttribute(gemm_wei,
                         cudaFuncAttributeMaxDynamicSharedMemorySize, W_SMEM);

    split_bf16<<<8192, 256>>>(x, xhi, xlo, (long long)BB * TT * CC);
    split_bf16<<<2048, 256>>>(W, whi, wlo, (long long)CC * CC);

    // K1: xH = x @ W^T  -> bf16 hi/lo   (128x128 tiles, 2 CTA/SM)
    gemm_bf3<false, 2><<<dim3(CC / 128, (BB * TT) / 128, 1), 256, SMEM_TOTAL>>>(
        xhi, xlo, whi, wlo, nullptr, xHhi, xHlo,
        CC, CC, CC, CC, 0, 0, 0);

    // K2: scores(fp32) = x @ xH^T per batch, causal tiles only
    gemm_bf3<true, 0><<<dim3(TT / 128, TT / 128, BB), 256, SMEM_TOTAL>>>(
        xhi, xlo, xHhi, xHlo, sc, nullptr, nullptr,
        CC, CC, TT, CC,
        (long long)TT * CC, (long long)TT * CC, (long long)TT * TT);

    // K3: causal softmax -> wei bf16 hi/lo (LPT)
    softmax_causal<<<BB * TT, 256>>>(sc, weihi, weilo);

    // K4: out = -(wei @ xH), pure GEMM, K clamped, LPT
    gemm_wei<<<dim3(CC / 128, TT / 128, BB), 256, W_SMEM>>>(
        weihi, weilo, xHhi, xHlo, out);
}

// round 9
// speedup vs baseline: 1.1621x; 1.0151x over previous
#include <cuda_runtime.h>
#include <cuda_bf16.h>
#include <cstdint>

#define BB 8
#define TT 2048
#define CC 1024

typedef __nv_bfloat16 bf16;

// Scratch (device globals — allocation-free)
__device__ bf16   g_xhi  [(size_t)BB * TT * CC];
__device__ bf16   g_xlo  [(size_t)BB * TT * CC];
__device__ bf16   g_whi  [(size_t)CC * CC];
__device__ bf16   g_wlo  [(size_t)CC * CC];
__device__ bf16   g_xHhi [(size_t)BB * TT * CC];
__device__ bf16   g_xHlo [(size_t)BB * TT * CC];
__device__ float  g_sc   [(size_t)BB * TT * TT];
__device__ bf16   g_weihi[(size_t)BB * TT * TT];
__device__ bf16   g_weilo[(size_t)BB * TT * TT];

// ===========================================================================
// helpers
// ===========================================================================
__device__ __forceinline__ uint32_t smem_u32(const void* p) {
    uint32_t a;
    asm("{ .reg .u64 t; cvta.to.shared.u64 t, %1; cvt.u32.u64 %0, t; }" : "=r"(a) : "l"(p));
    return a;
}
__device__ __forceinline__ void cp16(uint32_t s, const void* g) {
    asm volatile("cp.async.cg.shared.global [%0], [%1], 16;" :: "r"(s), "l"(g) : "memory");
}
__device__ __forceinline__ void ldsm4(uint32_t addr, uint32_t& r0, uint32_t& r1,
                                      uint32_t& r2, uint32_t& r3) {
    asm volatile("ldmatrix.sync.aligned.m8n8.x4.shared.b16 {%0,%1,%2,%3}, [%4];"
                 : "=r"(r0), "=r"(r1), "=r"(r2), "=r"(r3) : "r"(addr));
}
__device__ __forceinline__ void ldsm4t(uint32_t addr, uint32_t& r0, uint32_t& r1,
                                       uint32_t& r2, uint32_t& r3) {
    asm volatile("ldmatrix.sync.aligned.m8n8.x4.trans.shared.b16 {%0,%1,%2,%3}, [%4];"
                 : "=r"(r0), "=r"(r1), "=r"(r2), "=r"(r3) : "r"(addr));
}
__device__ __forceinline__ void mma_bf16(float c[4], const uint32_t a[4], const uint32_t b[2]) {
    asm volatile(
        "mma.sync.aligned.m16n8k16.row.col.f32.bf16.bf16.f32 "
        "{%0,%1,%2,%3}, {%4,%5,%6,%7}, {%8,%9}, {%0,%1,%2,%3};"
        : "+f"(c[0]), "+f"(c[1]), "+f"(c[2]), "+f"(c[3])
        : "r"(a[0]), "r"(a[1]), "r"(a[2]), "r"(a[3]), "r"(b[0]), "r"(b[1]));
}

// swizzled 16B-chunk offset within a 128x32-bf16 (64B-row) K-major tile
__device__ __forceinline__ uint32_t swz(int row, int chunk) {
    return (uint32_t)(row * 64 + ((chunk ^ ((row >> 1) & 3)) << 4));
}

// ===========================================================================
// 3xBF16 GEMM:  C = A[M,K] @ B[N,K]^T, bf16 hi/lo inputs, 128x128 tile, KC=32
// 3-stage cp.async pipeline, swizzled 64B rows, 2 CTAs/SM.
// Warp-staggered ks order to de-correlate post-barrier LDSM bursts.
// OUTMODE: 0 = fp32, 2 = bf16 hi/lo split pair
// ===========================================================================
#define AHI_OFF 0
#define ALO_OFF 8192
#define BHI_OFF 16384
#define BLO_OFF 24576
#define STG_BYTES 32768
#define SMEM_TOTAL (3 * STG_BYTES)   // 98304

template <bool CAUSAL, int OUTMODE>
__global__ __launch_bounds__(256, 2) void gemm_bf3(
    const bf16* __restrict__ Ahi, const bf16* __restrict__ Alo,
    const bf16* __restrict__ Bhi, const bf16* __restrict__ Blo,
    float* __restrict__ Cf, bf16* __restrict__ Chi, bf16* __restrict__ Clo,
    int lda, int ldb, int ldc, int Kfull,
    long long sA, long long sB, long long sC)
{
    const int bx = blockIdx.x, by = blockIdx.y, bz = blockIdx.z;
    if (CAUSAL && bx > by) return;

    Ahi += (long long)bz * sA; Alo += (long long)bz * sA;
    Bhi += (long long)bz * sB; Blo += (long long)bz * sB;

    const int m0 = by * 128, n0 = bx * 128;
    const int nc = Kfull / 32;

    extern __shared__ char smem[];
    const uint32_t sbase = smem_u32(smem);
    const int tid = threadIdx.x;
    const int wid = tid >> 5, lane = tid & 31;
    const int wm = wid & 1, wn = wid >> 1;
    const int g = lane >> 3, i = lane & 7;
    const int ksx = wid & 1;     // stagger: odd warps do ks=1 first

    const int arow_base = wm * 64 + i + (g & 1) * 8;
    const int brow_base = wn * 32 + i + (g >> 1) * 8;
    const int achunk0 = g >> 1;
    const int bchunk0 = g & 1;

    const int l_row = tid >> 2, l_ch = tid & 3;
    const uint32_t l_soff0 = swz(l_row, l_ch);
    const uint32_t l_soff1 = swz(l_row + 64, l_ch);

    float acc[4][4][4];
#pragma unroll
    for (int a = 0; a < 4; a++)
#pragma unroll
        for (int b = 0; b < 4; b++)
#pragma unroll
            for (int c = 0; c < 4; c++) acc[a][b][c] = 0.f;

    auto issue = [&](int ch) {
        const uint32_t st = sbase + (uint32_t)(ch % 3) * STG_BYTES;
        const long long k0 = (long long)ch * 32 + l_ch * 8;
        {
            const long long ga = (long long)(m0 + l_row) * lda + k0;
            const long long gb = (long long)(n0 + l_row) * ldb + k0;
            cp16(st + AHI_OFF + l_soff0, Ahi + ga);
            cp16(st + ALO_OFF + l_soff0, Alo + ga);
            cp16(st + BHI_OFF + l_soff0, Bhi + gb);
            cp16(st + BLO_OFF + l_soff0, Blo + gb);
        }
        {
            const long long ga = (long long)(m0 + l_row + 64) * lda + k0;
            const long long gb = (long long)(n0 + l_row + 64) * ldb + k0;
            cp16(st + AHI_OFF + l_soff1, Ahi + ga);
            cp16(st + ALO_OFF + l_soff1, Alo + ga);
            cp16(st + BHI_OFF + l_soff1, Bhi + gb);
            cp16(st + BLO_OFF + l_soff1, Blo + gb);
        }
    };

#pragma unroll
    for (int s = 0; s < 2; s++) {
        if (s < nc) issue(s);
        asm volatile("cp.async.commit_group;" ::: "memory");
    }

    for (int ch = 0; ch < nc; ch++) {
        asm volatile("cp.async.wait_group 1;" ::: "memory");
        __syncthreads();
        if (ch + 2 < nc) issue(ch + 2);
        asm volatile("cp.async.commit_group;" ::: "memory");

        const uint32_t st = sbase + (uint32_t)(ch % 3) * STG_BYTES;

#pragma unroll
        for (int kk = 0; kk < 2; kk++) {
            const int ks = kk ^ ksx;
            uint32_t ah[4][4], al[4][4], bh[4][2], bl[4][2];
#pragma unroll
            for (int mt = 0; mt < 4; mt++) {
                const uint32_t ao = swz(arow_base + mt * 16, achunk0 + ks * 2);
                ldsm4(st + AHI_OFF + ao, ah[mt][0], ah[mt][1], ah[mt][2], ah[mt][3]);
                ldsm4(st + ALO_OFF + ao, al[mt][0], al[mt][1], al[mt][2], al[mt][3]);
            }
#pragma unroll
            for (int j = 0; j < 2; j++) {
                const uint32_t bo = swz(brow_base + j * 16, bchunk0 + ks * 2);
                uint32_t r0, r1, r2, r3;
                ldsm4(st + BHI_OFF + bo, r0, r1, r2, r3);
                bh[2 * j][0] = r0; bh[2 * j][1] = r1; bh[2 * j + 1][0] = r2; bh[2 * j + 1][1] = r3;
                ldsm4(st + BLO_OFF + bo, r0, r1, r2, r3);
                bl[2 * j][0] = r0; bl[2 * j][1] = r1; bl[2 * j + 1][0] = r2; bl[2 * j + 1][1] = r3;
            }
#pragma unroll
            for (int mt = 0; mt < 4; mt++)
#pragma unroll
                for (int nt = 0; nt < 4; nt++) mma_bf16(acc[mt][nt], ah[mt], bh[nt]);
#pragma unroll
            for (int mt = 0; mt < 4; mt++)
#pragma unroll
                for (int nt = 0; nt < 4; nt++) mma_bf16(acc[mt][nt], ah[mt], bl[nt]);
#pragma unroll
            for (int mt = 0; mt < 4; mt++)
#pragma unroll
                for (int nt = 0; nt < 4; nt++) mma_bf16(acc[mt][nt], al[mt], bh[nt]);
        }
    }

    // ---- epilogue ----
    const int rr = lane >> 2, cb = (lane & 3) * 2;
#pragma unroll
    for (int mt = 0; mt < 4; mt++) {
#pragma unroll
        for (int nt = 0; nt < 4; nt++) {
            const int row = m0 + wm * 64 + mt * 16 + rr;
            const int col = n0 + wn * 32 + nt * 8 + cb;
            const float s0 = acc[mt][nt][0], s1 = acc[mt][nt][1];
            const float s2 = acc[mt][nt][2], s3 = acc[mt][nt][3];
            if (OUTMODE == 0) {
                float* base = Cf + (long long)bz * sC;
                *(float2*)(base + (long long)row * ldc + col)       = make_float2(s0, s1);
                *(float2*)(base + (long long)(row + 8) * ldc + col) = make_float2(s2, s3);
            } else {
                bf16* oh = Chi + (long long)bz * sC;
                bf16* ol = Clo + (long long)bz * sC;
                bf16 h0 = __float2bfloat16(s0), h1 = __float2bfloat16(s1);
                bf16 h2 = __float2bfloat16(s2), h3 = __float2bfloat16(s3);
                bf16 l0 = __float2bfloat16(s0 - __bfloat162float(h0));
                bf16 l1 = __float2bfloat16(s1 - __bfloat162float(h1));
                bf16 l2 = __float2bfloat16(s2 - __bfloat162float(h2));
                bf16 l3 = __float2bfloat16(s3 - __bfloat162float(h3));
                *(__nv_bfloat162*)(oh + (long long)row * ldc + col)       = __halves2bfloat162(h0, h1);
                *(__nv_bfloat162*)(oh + (long long)(row + 8) * ldc + col) = __halves2bfloat162(h2, h3);
                *(__nv_bfloat162*)(ol + (long long)row * ldc + col)       = __halves2bfloat162(l0, l1);
                *(__nv_bfloat162*)(ol + (long long)(row + 8) * ldc + col) = __halves2bfloat162(l2, l3);
            }
        }
    }
}

// ===========================================================================
// K4: out[t][c] = -sum_s wei[t][s] * xH[s][c]
// Pure 3xBF16 GEMM, K clamped, LPT, 3 stages, 2 CTA/SM, staggered ks.
// ===========================================================================
#define W_AHI 0
#define W_ALO 8192
#define W_BHI 16384
#define W_BLO 25088
#define W_STG 33792
#define W_SMEM (3 * W_STG)   // 101376

__global__ __launch_bounds__(256, 2) void gemm_wei(
    const bf16* __restrict__ Whi, const bf16* __restrict__ Wlo,
    const bf16* __restrict__ Bhi, const bf16* __restrict__ Blo,
    float* __restrict__ Out)
{
    const int bx = blockIdx.x, bz = blockIdx.z;
    const int by = (int)gridDim.y - 1 - (int)blockIdx.y;   // LPT
    const bf16* whi = Whi + (long long)bz * TT * TT;
    const bf16* wlo = Wlo + (long long)bz * TT * TT;
    const bf16* bhi = Bhi + (long long)bz * TT * CC;
    const bf16* blo = Blo + (long long)bz * TT * CC;
    float* out = Out + (long long)bz * TT * CC;

    const int m0 = by * 128, n0 = bx * 128;
    const int Klim = min(TT, (by + 1) * 128);
    const int nc = Klim / 32;

    extern __shared__ char smem[];
    const uint32_t sbase = smem_u32(smem);
    const int tid = threadIdx.x;
    const int wid = tid >> 5, lane = tid & 31;
    const int wm = wid & 1, wn = wid >> 1;
    const int g = lane >> 3, i = lane & 7;
    const int ksx = wid & 1;

    const int arow_base = wm * 64 + i + (g & 1) * 8;
    const int achunk0 = g >> 1;
    const uint32_t bLaneT = (uint32_t)((lane & 15) * 272 + (lane >> 4) * 16 + wn * 64);

    const int l_row = tid >> 2, l_ch = tid & 3;
    const uint32_t l_soff0 = swz(l_row, l_ch);
    const uint32_t l_soff1 = swz(l_row + 64, l_ch);

    float acc[4][4][4];
#pragma unroll
    for (int a = 0; a < 4; a++)
#pragma unroll
        for (int b = 0; b < 4; b++)
#pragma unroll
            for (int c = 0; c < 4; c++) acc[a][b][c] = 0.f;

    auto issue = [&](int ch) {
        const uint32_t st = sbase + (uint32_t)(ch % 3) * W_STG;
        const long long k0 = (long long)ch * 32 + l_ch * 8;
        {
            const long long ga = (long long)(m0 + l_row) * TT + k0;
            cp16(st + W_AHI + l_soff0, whi + ga);
            cp16(st + W_ALO + l_soff0, wlo + ga);
            const long long ga1 = (long long)(m0 + l_row + 64) * TT + k0;
            cp16(st + W_AHI + l_soff1, whi + ga1);
            cp16(st + W_ALO + l_soff1, wlo + ga1);
        }
        const long long kb = (long long)ch * 32;
#pragma unroll
        for (int r = 0; r < 2; r++) {
            const int idx = tid + r * 256;
            const int brow = idx >> 4, bseg = idx & 15;
            const long long go = (kb + brow) * CC + n0 + bseg * 8;
            const uint32_t so = (uint32_t)(brow * 272 + bseg * 16);
            cp16(st + W_BHI + so, bhi + go);
            cp16(st + W_BLO + so, blo + go);
        }
    };

#pragma unroll
    for (int s = 0; s < 2; s++) {
        if (s < nc) issue(s);
        asm volatile("cp.async.commit_group;" ::: "memory");
    }

    for (int ch = 0; ch < nc; ch++) {
        asm volatile("cp.async.wait_group 1;" ::: "memory");
        __syncthreads();
        if (ch + 2 < nc) issue(ch + 2);
        asm volatile("cp.async.commit_group;" ::: "memory");

        const uint32_t st = sbase + (uint32_t)(ch % 3) * W_STG;

#pragma unroll
        for (int kk = 0; kk < 2; kk++) {
            const int ks = kk ^ ksx;
            uint32_t ah[4][4], al[4][4], bh[4][2], bl[4][2];
#pragma unroll
            for (int mt = 0; mt < 4; mt++) {
                const uint32_t ao = swz(arow_base + mt * 16, achunk0 + ks * 2);
                ldsm4(st + W_AHI + ao, ah[mt][0], ah[mt][1], ah[mt][2], ah[mt][3]);
                ldsm4(st + W_ALO + ao, al[mt][0], al[mt][1], al[mt][2], al[mt][3]);
            }
#pragma unroll
            for (int j = 0; j < 2; j++) {
                uint32_t r0, r1, r2, r3;
                ldsm4t(st + W_BHI + bLaneT + ks * (16 * 272) + j * 32, r0, r1, r2, r3);
                bh[2 * j][0] = r0; bh[2 * j][1] = r1; bh[2 * j + 1][0] = r2; bh[2 * j + 1][1] = r3;
                ldsm4t(st + W_BLO + bLaneT + ks * (16 * 272) + j * 32, r0, r1, r2, r3);
                bl[2 * j][0] = r0; bl[2 * j][1] = r1; bl[2 * j + 1][0] = r2; bl[2 * j + 1][1] = r3;
            }
#pragma unroll
            for (int mt = 0; mt < 4; mt++)
#pragma unroll
                for (int nt = 0; nt < 4; nt++) mma_bf16(acc[mt][nt], ah[mt], bh[nt]);
#pragma unroll
            for (int mt = 0; mt < 4; mt++)
#pragma unroll
                for (int nt = 0; nt < 4; nt++) mma_bf16(acc[mt][nt], ah[mt], bl[nt]);
#pragma unroll
            for (int mt = 0; mt < 4; mt++)
#pragma unroll
                for (int nt = 0; nt < 4; nt++) mma_bf16(acc[mt][nt], al[mt], bh[nt]);
        }
    }

    const int rr = lane >> 2, cb = (lane & 3) * 2;
#pragma unroll
    for (int mt = 0; mt < 4; mt++) {
#pragma unroll
        for (int nt = 0; nt < 4; nt++) {
            const int row = m0 + wm * 64 + mt * 16 + rr;
            const int col = n0 + wn * 32 + nt * 8 + cb;
            *(float2*)(out + (long long)row * CC + col) =
                make_float2(-acc[mt][nt][0], -acc[mt][nt][1]);
            *(float2*)(out + (long long)(row + 8) * CC + col) =
                make_float2(-acc[mt][nt][2], -acc[mt][nt][3]);
        }
    }
}

// ===========================================================================
// fp32 -> bf16 hi/lo split
// ===========================================================================
__global__ __launch_bounds__(256) void split_bf16(
    const float* __restrict__ src, bf16* __restrict__ hi, bf16* __restrict__ lo, long long n)
{
    for (long long idx = (long long)blockIdx.x * 256 + threadIdx.x; idx < n;
         idx += (long long)gridDim.x * 256) {
        const float x = src[idx];
        const bf16 h = __float2bfloat16(x);
        hi[idx] = h;
        lo[idx] = __float2bfloat16(x - __bfloat162float(h));
    }
}

// ===========================================================================
// Causal softmax: fp32 scores -> wei bf16 hi/lo.
// Writes ONLY s < ((t>>7)+1)*128 — K4's KCLAMP never reads beyond that.
// LPT order (longest rows first).
// ===========================================================================
__global__ __launch_bounds__(256) void softmax_causal(
    const float* __restrict__ sc, bf16* __restrict__ whi, bf16* __restrict__ wlo)
{
    const long long row = (long long)(BB * TT - 1) - blockIdx.x;   // LPT
    const int t = (int)(row % TT);
    const float* p = sc + row * TT;
    bf16* oh = whi + row * TT;
    bf16* ol = wlo + row * TT;
    const int tid = threadIdx.x;
    const float4* p4 = (const float4*)p;
    const int n4 = t >> 2;
    const int wlim = ((t >> 7) + 1) << 7;   // write limit (K4 read region)

    __shared__ float red[8];

    float m = -3.0e38f;
    for (int q = tid; q < n4; q += 256) {
        const float4 v = p4[q];
        m = fmaxf(m, fmaxf(fmaxf(v.x, v.y), fmaxf(v.z, v.w)));
    }
    for (int s = (n4 << 2) + tid; s < t; s += 256) m = fmaxf(m, p[s]);
#pragma unroll
    for (int o = 16; o; o >>= 1) m = fmaxf(m, __shfl_xor_sync(0xffffffffu, m, o));
    if ((tid & 31) == 0) red[tid >> 5] = m;
    __syncthreads();
    m = red[0];
#pragma unroll
    for (int w = 1; w < 8; w++) m = fmaxf(m, red[w]);
    __syncthreads();

    float sum = 0.0f;
    for (int q = tid; q < n4; q += 256) {
        const float4 v = p4[q];
        sum += __expf(v.x - m) + __expf(v.y - m) + __expf(v.z - m) + __expf(v.w - m);
    }
    for (int s = (n4 << 2) + tid; s < t; s += 256) sum += __expf(p[s] - m);
#pragma unroll
    for (int o = 16; o; o >>= 1) sum += __shfl_xor_sync(0xffffffffu, sum, o);
    if ((tid & 31) == 0) red[tid >> 5] = sum;
    __syncthreads();
    sum = red[0] + red[1] + red[2] + red[3] + red[4] + red[5] + red[6] + red[7];

    const float inv = (t > 0) ? (1.0f / sum) : 0.0f;

    for (int s0 = tid * 4; s0 < wlim; s0 += 1024) {
        float w[4];
#pragma unroll
        for (int e = 0; e < 4; e++) {
            const int s = s0 + e;
            w[e] = (s < t) ? __expf(p[s] - m) * inv : 0.0f;
        }
        bf16 h[4], l[4];
#pragma unroll
        for (int e = 0; e < 4; e++) {
            h[e] = __float2bfloat16(w[e]);
            l[e] = __float2bfloat16(w[e] - __bfloat162float(h[e]));
        }
        *(__nv_bfloat162*)(oh + s0)     = __halves2bfloat162(h[0], h[1]);
        *(__nv_bfloat162*)(oh + s0 + 2) = __halves2bfloat162(h[2], h[3]);
        *(__nv_bfloat162*)(ol + s0)     = __halves2bfloat162(l[0], l[1]);
        *(__nv_bfloat162*)(ol + s0 + 2) = __halves2bfloat162(l[2], l[3]);
    }
}

// ===========================================================================
extern "C" void kernel_launch(void* const* d_in, const int* in_sizes, int n_in,
                              void* d_out, int out_size)
{
    const float* x = (const float*)d_in[0];
    const float* W = (const float*)d_in[1];
    float* out = (float*)d_out;

    bf16 *xhi, *xlo, *whi, *wlo, *xHhi, *xHlo, *weihi, *weilo;
    float* sc;
    cudaGetSymbolAddress((void**)&xhi,   g_xhi);
    cudaGetSymbolAddress((void**)&xlo,   g_xlo);
    cudaGetSymbolAddress((void**)&whi,   g_whi);
    cudaGetSymbolAddress((void**)&wlo,   g_wlo);
    cudaGetSymbolAddress((void**)&xHhi,  g_xHhi);
    cudaGetSymbolAddress((void**)&xHlo,  g_xHlo);
    cudaGetSymbolAddress((void**)&weihi, g_weihi);
    cudaGetSymbolAddress((void**)&weilo, g_weilo);
    cudaGetSymbolAddress((void**)&sc,    g_sc);

    cudaFuncSetAttribute(gemm_bf3<false, 2>,
                         cudaFuncAttributeMaxDynamicSharedMemorySize, SMEM_TOTAL);
    cudaFuncSetAttribute(gemm_bf3<true, 0>,
                         cudaFuncAttributeMaxDynamicSharedMemorySize, SMEM_TOTAL);
    cudaFuncSetAttribute(gemm_wei,
                         cudaFuncAttributeMaxDynamicSharedMemorySize, W_SMEM);

    split_bf16<<<8192, 256>>>(x, xhi, xlo, (long long)BB * TT * CC);
    split_bf16<<<2048, 256>>>(W, whi, wlo, (long long)CC * CC);

    // K1: xH = x @ W^T  -> bf16 hi/lo
    gemm_bf3<false, 2><<<dim3(CC / 128, (BB * TT) / 128, 1), 256, SMEM_TOTAL>>>(
        xhi, xlo, whi, wlo, nullptr, xHhi, xHlo,
        CC, CC, CC, CC, 0, 0, 0);

    // K2: scores(fp32) = x @ xH^T per batch, causal tiles only
    gemm_bf3<true, 0><<<dim3(TT / 128, TT / 128, BB), 256, SMEM_TOTAL>>>(
        xhi, xlo, xHhi, xHlo, sc, nullptr, nullptr,
        CC, CC, TT, CC,
        (long long)TT * CC, (long long)TT * CC, (long long)TT * TT);

    // K3: causal softmax -> wei bf16 hi/lo (LPT, write-trimmed)
    softmax_causal<<<BB * TT, 256>>>(sc, weihi, weilo);

    // K4: out = -(wei @ xH), pure GEMM, K clamped, LPT
    gemm_wei<<<dim3(CC / 128, TT / 128, BB), 256, W_SMEM>>>(
        weihi, weilo, xHhi, xHlo, out);
}

// round 10
// speedup vs baseline: 1.2962x; 1.1154x over previous
#include <cuda_runtime.h>
#include <cuda_fp16.h>
#include <cstdint>

#define BB 8
#define TT 2048
#define CC 1024

typedef __half f16;

// Scratch (device globals — allocation-free)
__device__ f16    g_xhi  [(size_t)BB * TT * CC];
__device__ f16    g_xlo  [(size_t)BB * TT * CC];
__device__ f16    g_whi  [(size_t)CC * CC];
__device__ f16    g_wlo  [(size_t)CC * CC];
__device__ f16    g_xHhi [(size_t)BB * TT * CC];
__device__ f16    g_xHlo [(size_t)BB * TT * CC];
__device__ float  g_sc   [(size_t)BB * TT * TT];
__device__ f16    g_wei  [(size_t)BB * TT * TT];    // single fp16 wei

// ===========================================================================
// helpers
// ===========================================================================
__device__ __forceinline__ uint32_t smem_u32(const void* p) {
    uint32_t a;
    asm("{ .reg .u64 t; cvta.to.shared.u64 t, %1; cvt.u32.u64 %0, t; }" : "=r"(a) : "l"(p));
    return a;
}
__device__ __forceinline__ void cp16(uint32_t s, const void* g) {
    asm volatile("cp.async.cg.shared.global [%0], [%1], 16;" :: "r"(s), "l"(g) : "memory");
}
__device__ __forceinline__ void ldsm4(uint32_t addr, uint32_t& r0, uint32_t& r1,
                                      uint32_t& r2, uint32_t& r3) {
    asm volatile("ldmatrix.sync.aligned.m8n8.x4.shared.b16 {%0,%1,%2,%3}, [%4];"
                 : "=r"(r0), "=r"(r1), "=r"(r2), "=r"(r3) : "r"(addr));
}
__device__ __forceinline__ void ldsm4t(uint32_t addr, uint32_t& r0, uint32_t& r1,
                                       uint32_t& r2, uint32_t& r3) {
    asm volatile("ldmatrix.sync.aligned.m8n8.x4.trans.shared.b16 {%0,%1,%2,%3}, [%4];"
                 : "=r"(r0), "=r"(r1), "=r"(r2), "=r"(r3) : "r"(addr));
}
__device__ __forceinline__ void mma_f16(float c[4], const uint32_t a[4], const uint32_t b[2]) {
    asm volatile(
        "mma.sync.aligned.m16n8k16.row.col.f32.f16.f16.f32 "
        "{%0,%1,%2,%3}, {%4,%5,%6,%7}, {%8,%9}, {%0,%1,%2,%3};"
        : "+f"(c[0]), "+f"(c[1]), "+f"(c[2]), "+f"(c[3])
        : "r"(a[0]), "r"(a[1]), "r"(a[2]), "r"(a[3]), "r"(b[0]), "r"(b[1]));
}

// swizzled 16B-chunk offset within a 128x32-f16 (64B-row) K-major tile
__device__ __forceinline__ uint32_t swz(int row, int chunk) {
    return (uint32_t)(row * 64 + ((chunk ^ ((row >> 1) & 3)) << 4));
}

// ===========================================================================
// 3xFP16 GEMM:  C = A[M,K] @ B[N,K]^T, fp16 hi/lo inputs, 128x128 tile, KC=32
// 3-stage cp.async pipeline, swizzled 64B rows, 2 CTAs/SM.
// OUTMODE: 0 = fp32, 2 = fp16 hi/lo split pair
// ===========================================================================
#define AHI_OFF 0
#define ALO_OFF 8192
#define BHI_OFF 16384
#define BLO_OFF 24576
#define STG_BYTES 32768
#define SMEM_TOTAL (3 * STG_BYTES)   // 98304

template <bool CAUSAL, int OUTMODE>
__global__ __launch_bounds__(256, 2) void gemm_3x(
    const f16* __restrict__ Ahi, const f16* __restrict__ Alo,
    const f16* __restrict__ Bhi, const f16* __restrict__ Blo,
    float* __restrict__ Cf, f16* __restrict__ Chi, f16* __restrict__ Clo,
    int lda, int ldb, int ldc, int Kfull,
    long long sA, long long sB, long long sC)
{
    const int bx = blockIdx.x, by = blockIdx.y, bz = blockIdx.z;
    if (CAUSAL && bx > by) return;

    Ahi += (long long)bz * sA; Alo += (long long)bz * sA;
    Bhi += (long long)bz * sB; Blo += (long long)bz * sB;

    const int m0 = by * 128, n0 = bx * 128;
    const int nc = Kfull / 32;

    extern __shared__ char smem[];
    const uint32_t sbase = smem_u32(smem);
    const int tid = threadIdx.x;
    const int wid = tid >> 5, lane = tid & 31;
    const int wm = wid & 1, wn = wid >> 1;
    const int g = lane >> 3, i = lane & 7;

    const int arow_base = wm * 64 + i + (g & 1) * 8;
    const int brow_base = wn * 32 + i + (g >> 1) * 8;
    const int achunk0 = g >> 1;
    const int bchunk0 = g & 1;

    const int l_row = tid >> 2, l_ch = tid & 3;
    const uint32_t l_soff0 = swz(l_row, l_ch);
    const uint32_t l_soff1 = swz(l_row + 64, l_ch);

    float acc[4][4][4];
#pragma unroll
    for (int a = 0; a < 4; a++)
#pragma unroll
        for (int b = 0; b < 4; b++)
#pragma unroll
            for (int c = 0; c < 4; c++) acc[a][b][c] = 0.f;

    auto issue = [&](int ch) {
        const uint32_t st = sbase + (uint32_t)(ch % 3) * STG_BYTES;
        const long long k0 = (long long)ch * 32 + l_ch * 8;
        {
            const long long ga = (long long)(m0 + l_row) * lda + k0;
            const long long gb = (long long)(n0 + l_row) * ldb + k0;
            cp16(st + AHI_OFF + l_soff0, Ahi + ga);
            cp16(st + ALO_OFF + l_soff0, Alo + ga);
            cp16(st + BHI_OFF + l_soff0, Bhi + gb);
            cp16(st + BLO_OFF + l_soff0, Blo + gb);
        }
        {
            const long long ga = (long long)(m0 + l_row + 64) * lda + k0;
            const long long gb = (long long)(n0 + l_row + 64) * ldb + k0;
            cp16(st + AHI_OFF + l_soff1, Ahi + ga);
            cp16(st + ALO_OFF + l_soff1, Alo + ga);
            cp16(st + BHI_OFF + l_soff1, Bhi + gb);
            cp16(st + BLO_OFF + l_soff1, Blo + gb);
        }
    };

#pragma unroll
    for (int s = 0; s < 2; s++) {
        if (s < nc) issue(s);
        asm volatile("cp.async.commit_group;" ::: "memory");
    }

    for (int ch = 0; ch < nc; ch++) {
        asm volatile("cp.async.wait_group 1;" ::: "memory");
        __syncthreads();
        if (ch + 2 < nc) issue(ch + 2);
        asm volatile("cp.async.commit_group;" ::: "memory");

        const uint32_t st = sbase + (uint32_t)(ch % 3) * STG_BYTES;

#pragma unroll
        for (int ks = 0; ks < 2; ks++) {
            uint32_t ah[4][4], al[4][4], bh[4][2], bl[4][2];
#pragma unroll
            for (int mt = 0; mt < 4; mt++) {
                const uint32_t ao = swz(arow_base + mt * 16, achunk0 + ks * 2);
                ldsm4(st + AHI_OFF + ao, ah[mt][0], ah[mt][1], ah[mt][2], ah[mt][3]);
                ldsm4(st + ALO_OFF + ao, al[mt][0], al[mt][1], al[mt][2], al[mt][3]);
            }
#pragma unroll
            for (int j = 0; j < 2; j++) {
                const uint32_t bo = swz(brow_base + j * 16, bchunk0 + ks * 2);
                uint32_t r0, r1, r2, r3;
                ldsm4(st + BHI_OFF + bo, r0, r1, r2, r3);
                bh[2 * j][0] = r0; bh[2 * j][1] = r1; bh[2 * j + 1][0] = r2; bh[2 * j + 1][1] = r3;
                ldsm4(st + BLO_OFF + bo, r0, r1, r2, r3);
                bl[2 * j][0] = r0; bl[2 * j][1] = r1; bl[2 * j + 1][0] = r2; bl[2 * j + 1][1] = r3;
            }
#pragma unroll
            for (int mt = 0; mt < 4; mt++)
#pragma unroll
                for (int nt = 0; nt < 4; nt++) mma_f16(acc[mt][nt], ah[mt], bh[nt]);
#pragma unroll
            for (int mt = 0; mt < 4; mt++)
#pragma unroll
                for (int nt = 0; nt < 4; nt++) mma_f16(acc[mt][nt], ah[mt], bl[nt]);
#pragma unroll
            for (int mt = 0; mt < 4; mt++)
#pragma unroll
                for (int nt = 0; nt < 4; nt++) mma_f16(acc[mt][nt], al[mt], bh[nt]);
        }
    }

    // ---- epilogue ----
    const int rr = lane >> 2, cb = (lane & 3) * 2;
#pragma unroll
    for (int mt = 0; mt < 4; mt++) {
#pragma unroll
        for (int nt = 0; nt < 4; nt++) {
            const int row = m0 + wm * 64 + mt * 16 + rr;
            const int col = n0 + wn * 32 + nt * 8 + cb;
            const float s0 = acc[mt][nt][0], s1 = acc[mt][nt][1];
            const float s2 = acc[mt][nt][2], s3 = acc[mt][nt][3];
            if (OUTMODE == 0) {
                float* base = Cf + (long long)bz * sC;
                *(float2*)(base + (long long)row * ldc + col)       = make_float2(s0, s1);
                *(float2*)(base + (long long)(row + 8) * ldc + col) = make_float2(s2, s3);
            } else {
                f16* oh = Chi + (long long)bz * sC;
                f16* ol = Clo + (long long)bz * sC;
                f16 h0 = __float2half(s0), h1 = __float2half(s1);
                f16 h2 = __float2half(s2), h3 = __float2half(s3);
                f16 l0 = __float2half(s0 - __half2float(h0));
                f16 l1 = __float2half(s1 - __half2float(h1));
                f16 l2 = __float2half(s2 - __half2float(h2));
                f16 l3 = __float2half(s3 - __half2float(h3));
                *(__half2*)(oh + (long long)row * ldc + col)       = __halves2half2(h0, h1);
                *(__half2*)(oh + (long long)(row + 8) * ldc + col) = __halves2half2(h2, h3);
                *(__half2*)(ol + (long long)row * ldc + col)       = __halves2half2(l0, l1);
                *(__half2*)(ol + (long long)(row + 8) * ldc + col) = __halves2half2(l2, l3);
            }
        }
    }
}

// ===========================================================================
// K4: out[t][c] = -sum_s wei[t][s] * xH[s][c]
// 2-pass fp16 GEMM: A = wei (single fp16, K-major), B = xH fp16 hi/lo
// (MN-major, trans-ldmatrix). K clamped, LPT, 3 stages, 2 CTA/SM.
// ===========================================================================
#define W_A   0
#define W_BHI 8192
#define W_BLO 16896
#define W_STG 25600
#define W_SMEM (3 * W_STG)   // 76800

__global__ __launch_bounds__(256, 2) void gemm_wei(
    const f16* __restrict__ Wei,
    const f16* __restrict__ Bhi, const f16* __restrict__ Blo,
    float* __restrict__ Out)
{
    const int bx = blockIdx.x, bz = blockIdx.z;
    const int by = (int)gridDim.y - 1 - (int)blockIdx.y;   // LPT
    const f16* wei = Wei + (long long)bz * TT * TT;
    const f16* bhi = Bhi + (long long)bz * TT * CC;
    const f16* blo = Blo + (long long)bz * TT * CC;
    float* out = Out + (long long)bz * TT * CC;

    const int m0 = by * 128, n0 = bx * 128;
    const int Klim = min(TT, (by + 1) * 128);
    const int nc = Klim / 32;

    extern __shared__ char smem[];
    const uint32_t sbase = smem_u32(smem);
    const int tid = threadIdx.x;
    const int wid = tid >> 5, lane = tid & 31;
    const int wm = wid & 1, wn = wid >> 1;
    const int g = lane >> 3, i = lane & 7;

    const int arow_base = wm * 64 + i + (g & 1) * 8;
    const int achunk0 = g >> 1;
    const uint32_t bLaneT = (uint32_t)((lane & 15) * 272 + (lane >> 4) * 16 + wn * 64);

    const int l_row = tid >> 2, l_ch = tid & 3;
    const uint32_t l_soff0 = swz(l_row, l_ch);
    const uint32_t l_soff1 = swz(l_row + 64, l_ch);

    float acc[4][4][4];
#pragma unroll
    for (int a = 0; a < 4; a++)
#pragma unroll
        for (int b = 0; b < 4; b++)
#pragma unroll
            for (int c = 0; c < 4; c++) acc[a][b][c] = 0.f;

    auto issue = [&](int ch) {
        const uint32_t st = sbase + (uint32_t)(ch % 3) * W_STG;
        const long long k0 = (long long)ch * 32 + l_ch * 8;
        {
            cp16(st + W_A + l_soff0, wei + (long long)(m0 + l_row) * TT + k0);
            cp16(st + W_A + l_soff1, wei + (long long)(m0 + l_row + 64) * TT + k0);
        }
        const long long kb = (long long)ch * 32;
#pragma unroll
        for (int r = 0; r < 2; r++) {
            const int idx = tid + r * 256;
            const int brow = idx >> 4, bseg = idx & 15;
            const long long go = (kb + brow) * CC + n0 + bseg * 8;
            const uint32_t so = (uint32_t)(brow * 272 + bseg * 16);
            cp16(st + W_BHI + so, bhi + go);
            cp16(st + W_BLO + so, blo + go);
        }
    };

#pragma unroll
    for (int s = 0; s < 2; s++) {
        if (s < nc) issue(s);
        asm volatile("cp.async.commit_group;" ::: "memory");
    }

    for (int ch = 0; ch < nc; ch++) {
        asm volatile("cp.async.wait_group 1;" ::: "memory");
        __syncthreads();
        if (ch + 2 < nc) issue(ch + 2);
        asm volatile("cp.async.commit_group;" ::: "memory");

        const uint32_t st = sbase + (uint32_t)(ch % 3) * W_STG;

#pragma unroll
        for (int ks = 0; ks < 2; ks++) {
            uint32_t ah[4][4], bh[4][2], bl[4][2];
#pragma unroll
            for (int mt = 0; mt < 4; mt++) {
                const uint32_t ao = swz(arow_base + mt * 16, achunk0 + ks * 2);
                ldsm4(st + W_A + ao, ah[mt][0], ah[mt][1], ah[mt][2], ah[mt][3]);
            }
#pragma unroll
            for (int j = 0; j < 2; j++) {
                uint32_t r0, r1, r2, r3;
                ldsm4t(st + W_BHI + bLaneT + ks * (16 * 272) + j * 32, r0, r1, r2, r3);
                bh[2 * j][0] = r0; bh[2 * j][1] = r1; bh[2 * j + 1][0] = r2; bh[2 * j + 1][1] = r3;
                ldsm4t(st + W_BLO + bLaneT + ks * (16 * 272) + j * 32, r0, r1, r2, r3);
                bl[2 * j][0] = r0; bl[2 * j][1] = r1; bl[2 * j + 1][0] = r2; bl[2 * j + 1][1] = r3;
            }
#pragma unroll
            for (int mt = 0; mt < 4; mt++)
#pragma unroll
                for (int nt = 0; nt < 4; nt++) mma_f16(acc[mt][nt], ah[mt], bh[nt]);
#pragma unroll
            for (int mt = 0; mt < 4; mt++)
#pragma unroll
                for (int nt = 0; nt < 4; nt++) mma_f16(acc[mt][nt], ah[mt], bl[nt]);
        }
    }

    const int rr = lane >> 2, cb = (lane & 3) * 2;
#pragma unroll
    for (int mt = 0; mt < 4; mt++) {
#pragma unroll
        for (int nt = 0; nt < 4; nt++) {
            const int row = m0 + wm * 64 + mt * 16 + rr;
            const int col = n0 + wn * 32 + nt * 8 + cb;
            *(float2*)(out + (long long)row * CC + col) =
                make_float2(-acc[mt][nt][0], -acc[mt][nt][1]);
            *(float2*)(out + (long long)(row + 8) * CC + col) =
                make_float2(-acc[mt][nt][2], -acc[mt][nt][3]);
        }
    }
}

// ===========================================================================
// fp32 -> fp16 hi/lo split
// ===========================================================================
__global__ __launch_bounds__(256) void split_f16(
    const float* __restrict__ src, f16* __restrict__ hi, f16* __restrict__ lo, long long n)
{
    for (long long idx = (long long)blockIdx.x * 256 + threadIdx.x; idx < n;
         idx += (long long)gridDim.x * 256) {
        const float x = src[idx];
        const f16 h = __float2half(x);
        hi[idx] = h;
        lo[idx] = __float2half(x - __half2float(h));
    }
}

// ===========================================================================
// Causal softmax: fp32 scores -> wei fp16 (single array).
// Writes ONLY s < ((t>>7)+1)*128 — K4's KCLAMP never reads beyond that.
// LPT order (longest rows first).
// ===========================================================================
__global__ __launch_bounds__(256) void softmax_causal(
    const float* __restrict__ sc, f16* __restrict__ wout)
{
    const long long row = (long long)(BB * TT - 1) - blockIdx.x;   // LPT
    const int t = (int)(row % TT);
    const float* p = sc + row * TT;
    f16* oh = wout + row * TT;
    const int tid = threadIdx.x;
    const float4* p4 = (const float4*)p;
    const int n4 = t >> 2;
    const int wlim = ((t >> 7) + 1) << 7;   // write limit (K4 read region)

    __shared__ float red[8];

    float m = -3.0e38f;
    for (int q = tid; q < n4; q += 256) {
        const float4 v = p4[q];
        m = fmaxf(m, fmaxf(fmaxf(v.x, v.y), fmaxf(v.z, v.w)));
    }
    for (int s = (n4 << 2) + tid; s < t; s += 256) m = fmaxf(m, p[s]);
#pragma unroll
    for (int o = 16; o; o >>= 1) m = fmaxf(m, __shfl_xor_sync(0xffffffffu, m, o));
    if ((tid & 31) == 0) red[tid >> 5] = m;
    __syncthreads();
    m = red[0];
#pragma unroll
    for (int w = 1; w < 8; w++) m = fmaxf(m, red[w]);
    __syncthreads();

    float sum = 0.0f;
    for (int q = tid; q < n4; q += 256) {
        const float4 v = p4[q];
        sum += __expf(v.x - m) + __expf(v.y - m) + __expf(v.z - m) + __expf(v.w - m);
    }
    for (int s = (n4 << 2) + tid; s < t; s += 256) sum += __expf(p[s] - m);
#pragma unroll
    for (int o = 16; o; o >>= 1) sum += __shfl_xor_sync(0xffffffffu, sum, o);
    if ((tid & 31) == 0) red[tid >> 5] = sum;
    __syncthreads();
    sum = red[0] + red[1] + red[2] + red[3] + red[4] + red[5] + red[6] + red[7];

    const float inv = (t > 0) ? (1.0f / sum) : 0.0f;

    for (int s0 = tid * 4; s0 < wlim; s0 += 1024) {
        f16 h[4];
#pragma unroll
        for (int e = 0; e < 4; e++) {
            const int s = s0 + e;
            const float w = (s < t) ? __expf(p[s] - m) * inv : 0.0f;
            h[e] = __float2half(w);
        }
        *(__half2*)(oh + s0)     = __halves2half2(h[0], h[1]);
        *(__half2*)(oh + s0 + 2) = __halves2half2(h[2], h[3]);
    }
}

// ===========================================================================
extern "C" void kernel_launch(void* const* d_in, const int* in_sizes, int n_in,
                              void* d_out, int out_size)
{
    const float* x = (const float*)d_in[0];
    const float* W = (const float*)d_in[1];
    float* out = (float*)d_out;

    f16 *xhi, *xlo, *whi, *wlo, *xHhi, *xHlo, *wei;
    float* sc;
    cudaGetSymbolAddress((void**)&xhi,  g_xhi);
    cudaGetSymbolAddress((void**)&xlo,  g_xlo);
    cudaGetSymbolAddress((void**)&whi,  g_whi);
    cudaGetSymbolAddress((void**)&wlo,  g_wlo);
    cudaGetSymbolAddress((void**)&xHhi, g_xHhi);
    cudaGetSymbolAddress((void**)&xHlo, g_xHlo);
    cudaGetSymbolAddress((void**)&wei,  g_wei);
    cudaGetSymbolAddress((void**)&sc,   g_sc);

    cudaFuncSetAttribute(gemm_3x<false, 2>,
                         cudaFuncAttributeMaxDynamicSharedMemorySize, SMEM_TOTAL);
    cudaFuncSetAttribute(gemm_3x<true, 0>,
                         cudaFuncAttributeMaxDynamicSharedMemorySize, SMEM_TOTAL);
    cudaFuncSetAttribute(gemm_wei,
                         cudaFuncAttributeMaxDynamicSharedMemorySize, W_SMEM);

    split_f16<<<8192, 256>>>(x, xhi, xlo, (long long)BB * TT * CC);
    split_f16<<<2048, 256>>>(W, whi, wlo, (long long)CC * CC);

    // K1: xH = x @ W^T  -> fp16 hi/lo  (3-pass)
    gemm_3x<false, 2><<<dim3(CC / 128, (BB * TT) / 128, 1), 256, SMEM_TOTAL>>>(
        xhi, xlo, whi, wlo, nullptr, xHhi, xHlo,
        CC, CC, CC, CC, 0, 0, 0);

    // K2: scores(fp32) = x @ xH^T per batch, causal tiles only (3-pass)
    gemm_3x<true, 0><<<dim3(TT / 128, TT / 128, BB), 256, SMEM_TOTAL>>>(
        xhi, xlo, xHhi, xHlo, sc, nullptr, nullptr,
        CC, CC, TT, CC,
        (long long)TT * CC, (long long)TT * CC, (long long)TT * TT);

    // K3: causal softmax -> wei fp16 (LPT, write-trimmed)
    softmax_causal<<<BB * TT, 256>>>(sc, wei);

    // K4: out = -(wei @ xH), 2-pass fp16, K clamped, LPT
    gemm_wei<<<dim3(CC / 128, TT / 128, BB), 256, W_SMEM>>>(
        wei, xHhi, xHlo, out);
}

// round 11
// speedup vs baseline: 1.4661x; 1.1311x over previous
#include <cuda_runtime.h>
#include <cuda_fp16.h>
#include <cstdint>

#define BB 8
#define TT 2048
#define CC 1024

typedef __half f16;

// Scratch (device globals — allocation-free)
__device__ f16    g_xhi  [(size_t)BB * TT * CC];
__device__ f16    g_xlo  [(size_t)BB * TT * CC];
__device__ f16    g_whi  [(size_t)CC * CC];
__device__ f16    g_wlo  [(size_t)CC * CC];
__device__ f16    g_xHhi [(size_t)BB * TT * CC];
__device__ f16    g_xHlo [(size_t)BB * TT * CC];
__device__ float  g_sc   [(size_t)BB * TT * TT];
__device__ f16    g_wei  [(size_t)BB * TT * TT];    // single fp16 wei

// ===========================================================================
// helpers
// ===========================================================================
__device__ __forceinline__ uint32_t smem_u32(const void* p) {
    uint32_t a;
    asm("{ .reg .u64 t; cvta.to.shared.u64 t, %1; cvt.u32.u64 %0, t; }" : "=r"(a) : "l"(p));
    return a;
}
__device__ __forceinline__ void cp16(uint32_t s, const void* g) {
    asm volatile("cp.async.cg.shared.global [%0], [%1], 16;" :: "r"(s), "l"(g) : "memory");
}
__device__ __forceinline__ void ldsm4(uint32_t addr, uint32_t& r0, uint32_t& r1,
                                      uint32_t& r2, uint32_t& r3) {
    asm volatile("ldmatrix.sync.aligned.m8n8.x4.shared.b16 {%0,%1,%2,%3}, [%4];"
                 : "=r"(r0), "=r"(r1), "=r"(r2), "=r"(r3) : "r"(addr));
}
__device__ __forceinline__ void ldsm4t(uint32_t addr, uint32_t& r0, uint32_t& r1,
                                       uint32_t& r2, uint32_t& r3) {
    asm volatile("ldmatrix.sync.aligned.m8n8.x4.trans.shared.b16 {%0,%1,%2,%3}, [%4];"
                 : "=r"(r0), "=r"(r1), "=r"(r2), "=r"(r3) : "r"(addr));
}
__device__ __forceinline__ void mma_f16(float c[4], const uint32_t a[4], const uint32_t b[2]) {
    asm volatile(
        "mma.sync.aligned.m16n8k16.row.col.f32.f16.f16.f32 "
        "{%0,%1,%2,%3}, {%4,%5,%6,%7}, {%8,%9}, {%0,%1,%2,%3};"
        : "+f"(c[0]), "+f"(c[1]), "+f"(c[2]), "+f"(c[3])
        : "r"(a[0]), "r"(a[1]), "r"(a[2]), "r"(a[3]), "r"(b[0]), "r"(b[1]));
}

// swizzled 16B-chunk offset within a 128x32-f16 (64B-row) K-major tile
__device__ __forceinline__ uint32_t swz(int row, int chunk) {
    return (uint32_t)(row * 64 + ((chunk ^ ((row >> 1) & 3)) << 4));
}

// ===========================================================================
// 3xFP16 GEMM:  C = A[M,K] @ B[N,K]^T, fp16 hi/lo inputs, 128x128 tile, KC=32
// 3-stage cp.async pipeline, swizzled 64B rows, 2 CTAs/SM.
// OUTMODE: 0 = fp32, 2 = fp16 hi/lo split pair
// ===========================================================================
#define AHI_OFF 0
#define ALO_OFF 8192
#define BHI_OFF 16384
#define BLO_OFF 24576
#define STG_BYTES 32768
#define SMEM_TOTAL (3 * STG_BYTES)   // 98304

template <bool CAUSAL, int OUTMODE>
__global__ __launch_bounds__(256, 2) void gemm_3x(
    const f16* __restrict__ Ahi, const f16* __restrict__ Alo,
    const f16* __restrict__ Bhi, const f16* __restrict__ Blo,
    float* __restrict__ Cf, f16* __restrict__ Chi, f16* __restrict__ Clo,
    int lda, int ldb, int ldc, int Kfull,
    long long sA, long long sB, long long sC)
{
    const int bx = blockIdx.x, by = blockIdx.y, bz = blockIdx.z;
    if (CAUSAL && bx > by) return;

    Ahi += (long long)bz * sA; Alo += (long long)bz * sA;
    Bhi += (long long)bz * sB; Blo += (long long)bz * sB;

    const int m0 = by * 128, n0 = bx * 128;
    const int nc = Kfull / 32;

    extern __shared__ char smem[];
    const uint32_t sbase = smem_u32(smem);
    const int tid = threadIdx.x;
    const int wid = tid >> 5, lane = tid & 31;
    const int wm = wid & 1, wn = wid >> 1;
    const int g = lane >> 3, i = lane & 7;

    const int arow_base = wm * 64 + i + (g & 1) * 8;
    const int brow_base = wn * 32 + i + (g >> 1) * 8;
    const int achunk0 = g >> 1;
    const int bchunk0 = g & 1;

    const int l_row = tid >> 2, l_ch = tid & 3;
    const uint32_t l_soff0 = swz(l_row, l_ch);
    const uint32_t l_soff1 = swz(l_row + 64, l_ch);

    float acc[4][4][4];
#pragma unroll
    for (int a = 0; a < 4; a++)
#pragma unroll
        for (int b = 0; b < 4; b++)
#pragma unroll
            for (int c = 0; c < 4; c++) acc[a][b][c] = 0.f;

    auto issue = [&](int ch) {
        const uint32_t st = sbase + (uint32_t)(ch % 3) * STG_BYTES;
        const long long k0 = (long long)ch * 32 + l_ch * 8;
        {
            const long long ga = (long long)(m0 + l_row) * lda + k0;
            const long long gb = (long long)(n0 + l_row) * ldb + k0;
            cp16(st + AHI_OFF + l_soff0, Ahi + ga);
            cp16(st + ALO_OFF + l_soff0, Alo + ga);
            cp16(st + BHI_OFF + l_soff0, Bhi + gb);
            cp16(st + BLO_OFF + l_soff0, Blo + gb);
        }
        {
            const long long ga = (long long)(m0 + l_row + 64) * lda + k0;
            const long long gb = (long long)(n0 + l_row + 64) * ldb + k0;
            cp16(st + AHI_OFF + l_soff1, Ahi + ga);
            cp16(st + ALO_OFF + l_soff1, Alo + ga);
            cp16(st + BHI_OFF + l_soff1, Bhi + gb);
            cp16(st + BLO_OFF + l_soff1, Blo + gb);
        }
    };

#pragma unroll
    for (int s = 0; s < 2; s++) {
        if (s < nc) issue(s);
        asm volatile("cp.async.commit_group;" ::: "memory");
    }

    for (int ch = 0; ch < nc; ch++) {
        asm volatile("cp.async.wait_group 1;" ::: "memory");
        __syncthreads();
        if (ch + 2 < nc) issue(ch + 2);
        asm volatile("cp.async.commit_group;" ::: "memory");

        const uint32_t st = sbase + (uint32_t)(ch % 3) * STG_BYTES;

#pragma unroll
        for (int ks = 0; ks < 2; ks++) {
            uint32_t ah[4][4], al[4][4], bh[4][2], bl[4][2];
#pragma unroll
            for (int mt = 0; mt < 4; mt++) {
                const uint32_t ao = swz(arow_base + mt * 16, achunk0 + ks * 2);
                ldsm4(st + AHI_OFF + ao, ah[mt][0], ah[mt][1], ah[mt][2], ah[mt][3]);
                ldsm4(st + ALO_OFF + ao, al[mt][0], al[mt][1], al[mt][2], al[mt][3]);
            }
#pragma unroll
            for (int j = 0; j < 2; j++) {
                const uint32_t bo = swz(brow_base + j * 16, bchunk0 + ks * 2);
                uint32_t r0, r1, r2, r3;
                ldsm4(st + BHI_OFF + bo, r0, r1, r2, r3);
                bh[2 * j][0] = r0; bh[2 * j][1] = r1; bh[2 * j + 1][0] = r2; bh[2 * j + 1][1] = r3;
                ldsm4(st + BLO_OFF + bo, r0, r1, r2, r3);
                bl[2 * j][0] = r0; bl[2 * j][1] = r1; bl[2 * j + 1][0] = r2; bl[2 * j + 1][1] = r3;
            }
#pragma unroll
            for (int mt = 0; mt < 4; mt++)
#pragma unroll
                for (int nt = 0; nt < 4; nt++) mma_f16(acc[mt][nt], ah[mt], bh[nt]);
#pragma unroll
            for (int mt = 0; mt < 4; mt++)
#pragma unroll
                for (int nt = 0; nt < 4; nt++) mma_f16(acc[mt][nt], ah[mt], bl[nt]);
#pragma unroll
            for (int mt = 0; mt < 4; mt++)
#pragma unroll
                for (int nt = 0; nt < 4; nt++) mma_f16(acc[mt][nt], al[mt], bh[nt]);
        }
    }

    // ---- epilogue ----
    const int rr = lane >> 2, cb = (lane & 3) * 2;
#pragma unroll
    for (int mt = 0; mt < 4; mt++) {
#pragma unroll
        for (int nt = 0; nt < 4; nt++) {
            const int row = m0 + wm * 64 + mt * 16 + rr;
            const int col = n0 + wn * 32 + nt * 8 + cb;
            const float s0 = acc[mt][nt][0], s1 = acc[mt][nt][1];
            const float s2 = acc[mt][nt][2], s3 = acc[mt][nt][3];
            if (OUTMODE == 0) {
                float* base = Cf + (long long)bz * sC;
                *(float2*)(base + (long long)row * ldc + col)       = make_float2(s0, s1);
                *(float2*)(base + (long long)(row + 8) * ldc + col) = make_float2(s2, s3);
            } else {
                f16* oh = Chi + (long long)bz * sC;
                f16* ol = Clo + (long long)bz * sC;
                f16 h0 = __float2half(s0), h1 = __float2half(s1);
                f16 h2 = __float2half(s2), h3 = __float2half(s3);
                f16 l0 = __float2half(s0 - __half2float(h0));
                f16 l1 = __float2half(s1 - __half2float(h1));
                f16 l2 = __float2half(s2 - __half2float(h2));
                f16 l3 = __float2half(s3 - __half2float(h3));
                *(__half2*)(oh + (long long)row * ldc + col)       = __halves2half2(h0, h1);
                *(__half2*)(oh + (long long)(row + 8) * ldc + col) = __halves2half2(h2, h3);
                *(__half2*)(ol + (long long)row * ldc + col)       = __halves2half2(l0, l1);
                *(__half2*)(ol + (long long)(row + 8) * ldc + col) = __halves2half2(l2, l3);
            }
        }
    }
}

// ===========================================================================
// K4: out[t][c] = -sum_s wei[t][s] * xH[s][c]
// 1-pass fp16 GEMM: A = wei (fp16, K-major), B = xHhi only (MN-major,
// trans-ldmatrix). K clamped, LPT, 3 stages, 2 CTA/SM.
// ===========================================================================
#define W_A   0
#define W_B   8192
#define W_STG 16896              // 8192 + 32*272
#define W_SMEM (3 * W_STG)       // 50688

__global__ __launch_bounds__(256, 2) void gemm_wei(
    const f16* __restrict__ Wei,
    const f16* __restrict__ Bh,
    float* __restrict__ Out)
{
    const int bx = blockIdx.x, bz = blockIdx.z;
    const int by = (int)gridDim.y - 1 - (int)blockIdx.y;   // LPT
    const f16* wei = Wei + (long long)bz * TT * TT;
    const f16* bhi = Bh + (long long)bz * TT * CC;
    float* out = Out + (long long)bz * TT * CC;

    const int m0 = by * 128, n0 = bx * 128;
    const int Klim = min(TT, (by + 1) * 128);
    const int nc = Klim / 32;

    extern __shared__ char smem[];
    const uint32_t sbase = smem_u32(smem);
    const int tid = threadIdx.x;
    const int wid = tid >> 5, lane = tid & 31;
    const int wm = wid & 1, wn = wid >> 1;
    const int g = lane >> 3, i = lane & 7;

    const int arow_base = wm * 64 + i + (g & 1) * 8;
    const int achunk0 = g >> 1;
    const uint32_t bLaneT = (uint32_t)((lane & 15) * 272 + (lane >> 4) * 16 + wn * 64);

    const int l_row = tid >> 2, l_ch = tid & 3;
    const uint32_t l_soff0 = swz(l_row, l_ch);
    const uint32_t l_soff1 = swz(l_row + 64, l_ch);

    float acc[4][4][4];
#pragma unroll
    for (int a = 0; a < 4; a++)
#pragma unroll
        for (int b = 0; b < 4; b++)
#pragma unroll
            for (int c = 0; c < 4; c++) acc[a][b][c] = 0.f;

    auto issue = [&](int ch) {
        const uint32_t st = sbase + (uint32_t)(ch % 3) * W_STG;
        const long long k0 = (long long)ch * 32 + l_ch * 8;
        {
            cp16(st + W_A + l_soff0, wei + (long long)(m0 + l_row) * TT + k0);
            cp16(st + W_A + l_soff1, wei + (long long)(m0 + l_row + 64) * TT + k0);
        }
        // B: 32 rows x 128 cols fp16 = 512 x 16B chunks; 256 threads x 2
        const long long kb = (long long)ch * 32;
#pragma unroll
        for (int r = 0; r < 2; r++) {
            const int idx = tid + r * 256;
            const int brow = idx >> 4, bseg = idx & 15;
            const long long go = (kb + brow) * CC + n0 + bseg * 8;
            const uint32_t so = (uint32_t)(brow * 272 + bseg * 16);
            cp16(st + W_B + so, bhi + go);
        }
    };

#pragma unroll
    for (int s = 0; s < 2; s++) {
        if (s < nc) issue(s);
        asm volatile("cp.async.commit_group;" ::: "memory");
    }

    for (int ch = 0; ch < nc; ch++) {
        asm volatile("cp.async.wait_group 1;" ::: "memory");
        __syncthreads();
        if (ch + 2 < nc) issue(ch + 2);
        asm volatile("cp.async.commit_group;" ::: "memory");

        const uint32_t st = sbase + (uint32_t)(ch % 3) * W_STG;

#pragma unroll
        for (int ks = 0; ks < 2; ks++) {
            uint32_t ah[4][4], bh[4][2];
#pragma unroll
            for (int mt = 0; mt < 4; mt++) {
                const uint32_t ao = swz(arow_base + mt * 16, achunk0 + ks * 2);
                ldsm4(st + W_A + ao, ah[mt][0], ah[mt][1], ah[mt][2], ah[mt][3]);
            }
#pragma unroll
            for (int j = 0; j < 2; j++) {
                uint32_t r0, r1, r2, r3;
                ldsm4t(st + W_B + bLaneT + ks * (16 * 272) + j * 32, r0, r1, r2, r3);
                bh[2 * j][0] = r0; bh[2 * j][1] = r1; bh[2 * j + 1][0] = r2; bh[2 * j + 1][1] = r3;
            }
#pragma unroll
            for (int mt = 0; mt < 4; mt++)
#pragma unroll
                for (int nt = 0; nt < 4; nt++) mma_f16(acc[mt][nt], ah[mt], bh[nt]);
        }
    }

    const int rr = lane >> 2, cb = (lane & 3) * 2;
#pragma unroll
    for (int mt = 0; mt < 4; mt++) {
#pragma unroll
        for (int nt = 0; nt < 4; nt++) {
            const int row = m0 + wm * 64 + mt * 16 + rr;
            const int col = n0 + wn * 32 + nt * 8 + cb;
            *(float2*)(out + (long long)row * CC + col) =
                make_float2(-acc[mt][nt][0], -acc[mt][nt][1]);
            *(float2*)(out + (long long)(row + 8) * CC + col) =
                make_float2(-acc[mt][nt][2], -acc[mt][nt][3]);
        }
    }
}

// ===========================================================================
// fp32 -> fp16 hi/lo split
// ===========================================================================
__global__ __launch_bounds__(256) void split_f16(
    const float* __restrict__ src, f16* __restrict__ hi, f16* __restrict__ lo, long long n)
{
    for (long long idx = (long long)blockIdx.x * 256 + threadIdx.x; idx < n;
         idx += (long long)gridDim.x * 256) {
        const float x = src[idx];
        const f16 h = __float2half(x);
        hi[idx] = h;
        lo[idx] = __float2half(x - __half2float(h));
    }
}

// ===========================================================================
// Causal softmax: fp32 scores -> wei fp16.
// Writes ONLY s < ((t>>7)+1)*128 — K4's KCLAMP never reads beyond that.
// LPT order (longest rows first).
// ===========================================================================
__global__ __launch_bounds__(256) void softmax_causal(
    const float* __restrict__ sc, f16* __restrict__ wout)
{
    const long long row = (long long)(BB * TT - 1) - blockIdx.x;   // LPT
    const int t = (int)(row % TT);
    const float* p = sc + row * TT;
    f16* oh = wout + row * TT;
    const int tid = threadIdx.x;
    const float4* p4 = (const float4*)p;
    const int n4 = t >> 2;
    const int wlim = ((t >> 7) + 1) << 7;   // write limit (K4 read region)

    __shared__ float red[8];

    float m = -3.0e38f;
    for (int q = tid; q < n4; q += 256) {
        const float4 v = p4[q];
        m = fmaxf(m, fmaxf(fmaxf(v.x, v.y), fmaxf(v.z, v.w)));
    }
    for (int s = (n4 << 2) + tid; s < t; s += 256) m = fmaxf(m, p[s]);
#pragma unroll
    for (int o = 16; o; o >>= 1) m = fmaxf(m, __shfl_xor_sync(0xffffffffu, m, o));
    if ((tid & 31) == 0) red[tid >> 5] = m;
    __syncthreads();
    m = red[0];
#pragma unroll
    for (int w = 1; w < 8; w++) m = fmaxf(m, red[w]);
    __syncthreads();

    float sum = 0.0f;
    for (int q = tid; q < n4; q += 256) {
        const float4 v = p4[q];
        sum += __expf(v.x - m) + __expf(v.y - m) + __expf(v.z - m) + __expf(v.w - m);
    }
    for (int s = (n4 << 2) + tid; s < t; s += 256) sum += __expf(p[s] - m);
#pragma unroll
    for (int o = 16; o; o >>= 1) sum += __shfl_xor_sync(0xffffffffu, sum, o);
    if ((tid & 31) == 0) red[tid >> 5] = sum;
    __syncthreads();
    sum = red[0] + red[1] + red[2] + red[3] + red[4] + red[5] + red[6] + red[7];

    const float inv = (t > 0) ? (1.0f / sum) : 0.0f;

    for (int s0 = tid * 4; s0 < wlim; s0 += 1024) {
        f16 h[4];
#pragma unroll
        for (int e = 0; e < 4; e++) {
            const int s = s0 + e;
            const float w = (s < t) ? __expf(p[s] - m) * inv : 0.0f;
            h[e] = __float2half(w);
        }
        *(__half2*)(oh + s0)     = __halves2half2(h[0], h[1]);
        *(__half2*)(oh + s0 + 2) = __halves2half2(h[2], h[3]);
    }
}

// ===========================================================================
extern "C" void kernel_launch(void* const* d_in, const int* in_sizes, int n_in,
                              void* d_out, int out_size)
{
    const float* x = (const float*)d_in[0];
    const float* W = (const float*)d_in[1];
    float* out = (float*)d_out;

    f16 *xhi, *xlo, *whi, *wlo, *xHhi, *xHlo, *wei;
    float* sc;
    cudaGetSymbolAddress((void**)&xhi,  g_xhi);
    cudaGetSymbolAddress((void**)&xlo,  g_xlo);
    cudaGetSymbolAddress((void**)&whi,  g_whi);
    cudaGetSymbolAddress((void**)&wlo,  g_wlo);
    cudaGetSymbolAddress((void**)&xHhi, g_xHhi);
    cudaGetSymbolAddress((void**)&xHlo, g_xHlo);
    cudaGetSymbolAddress((void**)&wei,  g_wei);
    cudaGetSymbolAddress((void**)&sc,   g_sc);

    cudaFuncSetAttribute(gemm_3x<false, 2>,
                         cudaFuncAttributeMaxDynamicSharedMemorySize, SMEM_TOTAL);
    cudaFuncSetAttribute(gemm_3x<true, 0>,
                         cudaFuncAttributeMaxDynamicSharedMemorySize, SMEM_TOTAL);
    cudaFuncSetAttribute(gemm_wei,
                         cudaFuncAttributeMaxDynamicSharedMemorySize, W_SMEM);

    split_f16<<<8192, 256>>>(x, xhi, xlo, (long long)BB * TT * CC);
    split_f16<<<2048, 256>>>(W, whi, wlo, (long long)CC * CC);

    // K1: xH = x @ W^T  -> fp16 hi/lo  (3-pass)
    gemm_3x<false, 2><<<dim3(CC / 128, (BB * TT) / 128, 1), 256, SMEM_TOTAL>>>(
        xhi, xlo, whi, wlo, nullptr, xHhi, xHlo,
        CC, CC, CC, CC, 0, 0, 0);

    // K2: scores(fp32) = x @ xH^T per batch, causal tiles only (3-pass)
    gemm_3x<true, 0><<<dim3(TT / 128, TT / 128, BB), 256, SMEM_TOTAL>>>(
        xhi, xlo, xHhi, xHlo, sc, nullptr, nullptr,
        CC, CC, TT, CC,
        (long long)TT * CC, (long long)TT * CC, (long long)TT * TT);

    // K3: causal softmax -> wei fp16 (LPT, write-trimmed)
    softmax_causal<<<BB * TT, 256>>>(sc, wei);

    // K4: out = -(wei @ xHhi), 1-pass fp16, K clamped, LPT
    gemm_wei<<<dim3(CC / 128, TT / 128, BB), 256, W_SMEM>>>(
        wei, xHhi, out);
}

// round 12
// speedup vs baseline: 1.4788x; 1.0087x over previous
#include <cuda_runtime.h>
#include <cuda_fp16.h>
#include <cstdint>

#define BB 8
#define TT 2048
#define CC 1024

typedef __half f16;

// Scratch (device globals — allocation-free)
__device__ f16    g_xhi  [(size_t)BB * TT * CC];
__device__ f16    g_xlo  [(size_t)BB * TT * CC];
__device__ f16    g_whi  [(size_t)CC * CC];
__device__ f16    g_wlo  [(size_t)CC * CC];
__device__ f16    g_xHhi [(size_t)BB * TT * CC];
__device__ f16    g_xHlo [(size_t)BB * TT * CC];
__device__ float  g_sc   [(size_t)BB * TT * TT];
__device__ f16    g_wei  [(size_t)BB * TT * TT];

// ===========================================================================
// helpers
// ===========================================================================
__device__ __forceinline__ uint32_t smem_u32(const void* p) {
    uint32_t a;
    asm("{ .reg .u64 t; cvta.to.shared.u64 t, %1; cvt.u32.u64 %0, t; }" : "=r"(a) : "l"(p));
    return a;
}
__device__ __forceinline__ void cp16(uint32_t s, const void* g) {
    asm volatile("cp.async.cg.shared.global [%0], [%1], 16;" :: "r"(s), "l"(g) : "memory");
}
__device__ __forceinline__ void ldsm4(uint32_t addr, uint32_t& r0, uint32_t& r1,
                                      uint32_t& r2, uint32_t& r3) {
    asm volatile("ldmatrix.sync.aligned.m8n8.x4.shared.b16 {%0,%1,%2,%3}, [%4];"
                 : "=r"(r0), "=r"(r1), "=r"(r2), "=r"(r3) : "r"(addr));
}
__device__ __forceinline__ void ldsm4t(uint32_t addr, uint32_t& r0, uint32_t& r1,
                                       uint32_t& r2, uint32_t& r3) {
    asm volatile("ldmatrix.sync.aligned.m8n8.x4.trans.shared.b16 {%0,%1,%2,%3}, [%4];"
                 : "=r"(r0), "=r"(r1), "=r"(r2), "=r"(r3) : "r"(addr));
}
__device__ __forceinline__ void mma_f16(float c[4], const uint32_t a[4], const uint32_t b[2]) {
    asm volatile(
        "mma.sync.aligned.m16n8k16.row.col.f32.f16.f16.f32 "
        "{%0,%1,%2,%3}, {%4,%5,%6,%7}, {%8,%9}, {%0,%1,%2,%3};"
        : "+f"(c[0]), "+f"(c[1]), "+f"(c[2]), "+f"(c[3])
        : "r"(a[0]), "r"(a[1]), "r"(a[2]), "r"(a[3]), "r"(b[0]), "r"(b[1]));
}
__device__ __forceinline__ void stg_cs_f2(float* p, float a, float b) {
    asm volatile("st.global.cs.v2.f32 [%0], {%1, %2};" :: "l"(p), "f"(a), "f"(b) : "memory");
}

// swizzled 16B-chunk offset within a 128x32-f16 (64B-row) K-major tile
__device__ __forceinline__ uint32_t swz(int row, int chunk) {
    return (uint32_t)(row * 64 + ((chunk ^ ((row >> 1) & 3)) << 4));
}

// ===========================================================================
// 3xFP16 GEMM:  C = A[M,K] @ B[N,K]^T, fp16 hi/lo inputs, 128x128 tile, KC=32
// 3-stage cp.async pipeline, swizzled 64B rows, 2 CTAs/SM.
// OUTMODE: 0 = fp32 (streaming .cs stores), 2 = fp16 hi/lo split pair
// ===========================================================================
#define AHI_OFF 0
#define ALO_OFF 8192
#define BHI_OFF 16384
#define BLO_OFF 24576
#define STG_BYTES 32768
#define SMEM_TOTAL (3 * STG_BYTES)   // 98304

template <bool CAUSAL, int OUTMODE>
__global__ __launch_bounds__(256, 2) void gemm_3x(
    const f16* __restrict__ Ahi, const f16* __restrict__ Alo,
    const f16* __restrict__ Bhi, const f16* __restrict__ Blo,
    float* __restrict__ Cf, f16* __restrict__ Chi, f16* __restrict__ Clo,
    int lda, int ldb, int ldc, int Kfull,
    long long sA, long long sB, long long sC)
{
    const int bx = blockIdx.x, by = blockIdx.y, bz = blockIdx.z;
    if (CAUSAL && bx > by) return;

    Ahi += (long long)bz * sA; Alo += (long long)bz * sA;
    Bhi += (long long)bz * sB; Blo += (long long)bz * sB;

    const int m0 = by * 128, n0 = bx * 128;
    const int nc = Kfull / 32;

    extern __shared__ char smem[];
    const uint32_t sbase = smem_u32(smem);
    const int tid = threadIdx.x;
    const int wid = tid >> 5, lane = tid & 31;
    const int wm = wid & 1, wn = wid >> 1;
    const int g = lane >> 3, i = lane & 7;

    const int arow_base = wm * 64 + i + (g & 1) * 8;
    const int brow_base = wn * 32 + i + (g >> 1) * 8;
    const int achunk0 = g >> 1;
    const int bchunk0 = g & 1;

    const int l_row = tid >> 2, l_ch = tid & 3;
    const uint32_t l_soff0 = swz(l_row, l_ch);
    const uint32_t l_soff1 = swz(l_row + 64, l_ch);

    float acc[4][4][4];
#pragma unroll
    for (int a = 0; a < 4; a++)
#pragma unroll
        for (int b = 0; b < 4; b++)
#pragma unroll
            for (int c = 0; c < 4; c++) acc[a][b][c] = 0.f;

    auto issue = [&](int ch) {
        const uint32_t st = sbase + (uint32_t)(ch % 3) * STG_BYTES;
        const long long k0 = (long long)ch * 32 + l_ch * 8;
        {
            const long long ga = (long long)(m0 + l_row) * lda + k0;
            const long long gb = (long long)(n0 + l_row) * ldb + k0;
            cp16(st + AHI_OFF + l_soff0, Ahi + ga);
            cp16(st + ALO_OFF + l_soff0, Alo + ga);
            cp16(st + BHI_OFF + l_soff0, Bhi + gb);
            cp16(st + BLO_OFF + l_soff0, Blo + gb);
        }
        {
            const long long ga = (long long)(m0 + l_row + 64) * lda + k0;
            const long long gb = (long long)(n0 + l_row + 64) * ldb + k0;
            cp16(st + AHI_OFF + l_soff1, Ahi + ga);
            cp16(st + ALO_OFF + l_soff1, Alo + ga);
            cp16(st + BHI_OFF + l_soff1, Bhi + gb);
            cp16(st + BLO_OFF + l_soff1, Blo + gb);
        }
    };

#pragma unroll
    for (int s = 0; s < 2; s++) {
        if (s < nc) issue(s);
        asm volatile("cp.async.commit_group;" ::: "memory");
    }

    for (int ch = 0; ch < nc; ch++) {
        asm volatile("cp.async.wait_group 1;" ::: "memory");
        __syncthreads();
        if (ch + 2 < nc) issue(ch + 2);
        asm volatile("cp.async.commit_group;" ::: "memory");

        const uint32_t st = sbase + (uint32_t)(ch % 3) * STG_BYTES;

#pragma unroll
        for (int ks = 0; ks < 2; ks++) {
            uint32_t ah[4][4], al[4][4], bh[4][2], bl[4][2];
#pragma unroll
            for (int mt = 0; mt < 4; mt++) {
                const uint32_t ao = swz(arow_base + mt * 16, achunk0 + ks * 2);
                ldsm4(st + AHI_OFF + ao, ah[mt][0], ah[mt][1], ah[mt][2], ah[mt][3]);
                ldsm4(st + ALO_OFF + ao, al[mt][0], al[mt][1], al[mt][2], al[mt][3]);
            }
#pragma unroll
            for (int j = 0; j < 2; j++) {
                const uint32_t bo = swz(brow_base + j * 16, bchunk0 + ks * 2);
                uint32_t r0, r1, r2, r3;
                ldsm4(st + BHI_OFF + bo, r0, r1, r2, r3);
                bh[2 * j][0] = r0; bh[2 * j][1] = r1; bh[2 * j + 1][0] = r2; bh[2 * j + 1][1] = r3;
                ldsm4(st + BLO_OFF + bo, r0, r1, r2, r3);
                bl[2 * j][0] = r0; bl[2 * j][1] = r1; bl[2 * j + 1][0] = r2; bl[2 * j + 1][1] = r3;
            }
#pragma unroll
            for (int mt = 0; mt < 4; mt++)
#pragma unroll
                for (int nt = 0; nt < 4; nt++) mma_f16(acc[mt][nt], ah[mt], bh[nt]);
#pragma unroll
            for (int mt = 0; mt < 4; mt++)
#pragma unroll
                for (int nt = 0; nt < 4; nt++) mma_f16(acc[mt][nt], ah[mt], bl[nt]);
#pragma unroll
            for (int mt = 0; mt < 4; mt++)
#pragma unroll
                for (int nt = 0; nt < 4; nt++) mma_f16(acc[mt][nt], al[mt], bh[nt]);
        }
    }

    // ---- epilogue ----
    const int rr = lane >> 2, cb = (lane & 3) * 2;
#pragma unroll
    for (int mt = 0; mt < 4; mt++) {
#pragma unroll
        for (int nt = 0; nt < 4; nt++) {
            const int row = m0 + wm * 64 + mt * 16 + rr;
            const int col = n0 + wn * 32 + nt * 8 + cb;
            const float s0 = acc[mt][nt][0], s1 = acc[mt][nt][1];
            const float s2 = acc[mt][nt][2], s3 = acc[mt][nt][3];
            if (OUTMODE == 0) {
                float* base = Cf + (long long)bz * sC;
                stg_cs_f2(base + (long long)row * ldc + col, s0, s1);
                stg_cs_f2(base + (long long)(row + 8) * ldc + col, s2, s3);
            } else {
                f16* oh = Chi + (long long)bz * sC;
                f16* ol = Clo + (long long)bz * sC;
                f16 h0 = __float2half(s0), h1 = __float2half(s1);
                f16 h2 = __float2half(s2), h3 = __float2half(s3);
                f16 l0 = __float2half(s0 - __half2float(h0));
                f16 l1 = __float2half(s1 - __half2float(h1));
                f16 l2 = __float2half(s2 - __half2float(h2));
                f16 l3 = __float2half(s3 - __half2float(h3));
                *(__half2*)(oh + (long long)row * ldc + col)       = __halves2half2(h0, h1);
                *(__half2*)(oh + (long long)(row + 8) * ldc + col) = __halves2half2(h2, h3);
                *(__half2*)(ol + (long long)row * ldc + col)       = __halves2half2(l0, l1);
                *(__half2*)(ol + (long long)(row + 8) * ldc + col) = __halves2half2(l2, l3);
            }
        }
    }
}

// ===========================================================================
// K4: out[t][c] = -sum_s wei[t][s] * xH[s][c]
// 1-pass fp16 GEMM: A = wei (fp16, K-major), B = xHhi (MN-major, trans-ldsm).
// K clamped, LPT, 4-stage pipeline, 2 CTA/SM.
// ===========================================================================
#define W_A   0
#define W_B   8192
#define W_STG 16896              // 8192 + 32*272
#define W_NST 4
#define W_SMEM (W_NST * W_STG)   // 67584

__global__ __launch_bounds__(256, 2) void gemm_wei(
    const f16* __restrict__ Wei,
    const f16* __restrict__ Bh,
    float* __restrict__ Out)
{
    const int bx = blockIdx.x, bz = blockIdx.z;
    const int by = (int)gridDim.y - 1 - (int)blockIdx.y;   // LPT
    const f16* wei = Wei + (long long)bz * TT * TT;
    const f16* bhi = Bh + (long long)bz * TT * CC;
    float* out = Out + (long long)bz * TT * CC;

    const int m0 = by * 128, n0 = bx * 128;
    const int Klim = min(TT, (by + 1) * 128);
    const int nc = Klim / 32;

    extern __shared__ char smem[];
    const uint32_t sbase = smem_u32(smem);
    const int tid = threadIdx.x;
    const int wid = tid >> 5, lane = tid & 31;
    const int wm = wid & 1, wn = wid >> 1;
    const int g = lane >> 3, i = lane & 7;

    const int arow_base = wm * 64 + i + (g & 1) * 8;
    const int achunk0 = g >> 1;
    const uint32_t bLaneT = (uint32_t)((lane & 15) * 272 + (lane >> 4) * 16 + wn * 64);

    const int l_row = tid >> 2, l_ch = tid & 3;
    const uint32_t l_soff0 = swz(l_row, l_ch);
    const uint32_t l_soff1 = swz(l_row + 64, l_ch);

    float acc[4][4][4];
#pragma unroll
    for (int a = 0; a < 4; a++)
#pragma unroll
        for (int b = 0; b < 4; b++)
#pragma unroll
            for (int c = 0; c < 4; c++) acc[a][b][c] = 0.f;

    auto issue = [&](int ch) {
        const uint32_t st = sbase + (uint32_t)(ch % W_NST) * W_STG;
        const long long k0 = (long long)ch * 32 + l_ch * 8;
        {
            cp16(st + W_A + l_soff0, wei + (long long)(m0 + l_row) * TT + k0);
            cp16(st + W_A + l_soff1, wei + (long long)(m0 + l_row + 64) * TT + k0);
        }
        const long long kb = (long long)ch * 32;
#pragma unroll
        for (int r = 0; r < 2; r++) {
            const int idx = tid + r * 256;
            const int brow = idx >> 4, bseg = idx & 15;
            const long long go = (kb + brow) * CC + n0 + bseg * 8;
            const uint32_t so = (uint32_t)(brow * 272 + bseg * 16);
            cp16(st + W_B + so, bhi + go);
        }
    };

#pragma unroll
    for (int s = 0; s < W_NST - 1; s++) {
        if (s < nc) issue(s);
        asm volatile("cp.async.commit_group;" ::: "memory");
    }

    for (int ch = 0; ch < nc; ch++) {
        asm volatile("cp.async.wait_group %0;" :: "n"(W_NST - 2) : "memory");
        __syncthreads();
        if (ch + W_NST - 1 < nc) issue(ch + W_NST - 1);
        asm volatile("cp.async.commit_group;" ::: "memory");

        const uint32_t st = sbase + (uint32_t)(ch % W_NST) * W_STG;

#pragma unroll
        for (int ks = 0; ks < 2; ks++) {
            uint32_t ah[4][4], bh[4][2];
#pragma unroll
            for (int mt = 0; mt < 4; mt++) {
                const uint32_t ao = swz(arow_base + mt * 16, achunk0 + ks * 2);
                ldsm4(st + W_A + ao, ah[mt][0], ah[mt][1], ah[mt][2], ah[mt][3]);
            }
#pragma unroll
            for (int j = 0; j < 2; j++) {
                uint32_t r0, r1, r2, r3;
                ldsm4t(st + W_B + bLaneT + ks * (16 * 272) + j * 32, r0, r1, r2, r3);
                bh[2 * j][0] = r0; bh[2 * j][1] = r1; bh[2 * j + 1][0] = r2; bh[2 * j + 1][1] = r3;
            }
#pragma unroll
            for (int mt = 0; mt < 4; mt++)
#pragma unroll
                for (int nt = 0; nt < 4; nt++) mma_f16(acc[mt][nt], ah[mt], bh[nt]);
        }
    }

    const int rr = lane >> 2, cb = (lane & 3) * 2;
#pragma unroll
    for (int mt = 0; mt < 4; mt++) {
#pragma unroll
        for (int nt = 0; nt < 4; nt++) {
            const int row = m0 + wm * 64 + mt * 16 + rr;
            const int col = n0 + wn * 32 + nt * 8 + cb;
            *(float2*)(out + (long long)row * CC + col) =
                make_float2(-acc[mt][nt][0], -acc[mt][nt][1]);
            *(float2*)(out + (long long)(row + 8) * CC + col) =
                make_float2(-acc[mt][nt][2], -acc[mt][nt][3]);
        }
    }
}

// ===========================================================================
// fp32 -> fp16 hi/lo split (float4 vectorized)
// ===========================================================================
__global__ __launch_bounds__(256) void split_f16(
    const float* __restrict__ src, f16* __restrict__ hi, f16* __restrict__ lo, long long n4)
{
    const float4* s4 = (const float4*)src;
    for (long long q = (long long)blockIdx.x * 256 + threadIdx.x; q < n4;
         q += (long long)gridDim.x * 256) {
        const float4 v = s4[q];
        const f16 h0 = __float2half(v.x), h1 = __float2half(v.y);
        const f16 h2 = __float2half(v.z), h3 = __float2half(v.w);
        const f16 l0 = __float2half(v.x - __half2float(h0));
        const f16 l1 = __float2half(v.y - __half2float(h1));
        const f16 l2 = __float2half(v.z - __half2float(h2));
        const f16 l3 = __float2half(v.w - __half2float(h3));
        __half2 hh[2] = { __halves2half2(h0, h1), __halves2half2(h2, h3) };
        __half2 ll[2] = { __halves2half2(l0, l1), __halves2half2(l2, l3) };
        *(uint2*)(hi + q * 4) = *(uint2*)hh;
        *(uint2*)(lo + q * 4) = *(uint2*)ll;
    }
}

// ===========================================================================
// Causal softmax: fp32 scores -> wei fp16, 16B stores.
// Writes ONLY s < ((t>>7)+1)*128; LPT order.
// ===========================================================================
__global__ __launch_bounds__(256) void softmax_causal(
    const float* __restrict__ sc, f16* __restrict__ wout)
{
    const long long row = (long long)(BB * TT - 1) - blockIdx.x;   // LPT
    const int t = (int)(row % TT);
    const float* p = sc + row * TT;
    f16* oh = wout + row * TT;
    const int tid = threadIdx.x;
    const float4* p4 = (const float4*)p;
    const int n4 = t >> 2;
    const int wlim = ((t >> 7) + 1) << 7;

    __shared__ float red[8];

    float m = -3.0e38f;
    for (int q = tid; q < n4; q += 256) {
        const float4 v = p4[q];
        m = fmaxf(m, fmaxf(fmaxf(v.x, v.y), fmaxf(v.z, v.w)));
    }
    for (int s = (n4 << 2) + tid; s < t; s += 256) m = fmaxf(m, p[s]);
#pragma unroll
    for (int o = 16; o; o >>= 1) m = fmaxf(m, __shfl_xor_sync(0xffffffffu, m, o));
    if ((tid & 31) == 0) red[tid >> 5] = m;
    __syncthreads();
    m = red[0];
#pragma unroll
    for (int w = 1; w < 8; w++) m = fmaxf(m, red[w]);
    __syncthreads();

    float sum = 0.0f;
    for (int q = tid; q < n4; q += 256) {
        const float4 v = p4[q];
        sum += __expf(v.x - m) + __expf(v.y - m) + __expf(v.z - m) + __expf(v.w - m);
    }
    for (int s = (n4 << 2) + tid; s < t; s += 256) sum += __expf(p[s] - m);
#pragma unroll
    for (int o = 16; o; o >>= 1) sum += __shfl_xor_sync(0xffffffffu, sum, o);
    if ((tid & 31) == 0) red[tid >> 5] = sum;
    __syncthreads();
    sum = red[0] + red[1] + red[2] + red[3] + red[4] + red[5] + red[6] + red[7];

    const float inv = (t > 0) ? (1.0f / sum) : 0.0f;

    for (int s0 = tid * 8; s0 < wlim; s0 += 2048) {
        __half2 h[4];
#pragma unroll
        for (int e = 0; e < 8; e += 2) {
            const int sA = s0 + e, sB = s0 + e + 1;
            const float wA = (sA < t) ? __expf(p[sA] - m) * inv : 0.0f;
            const float wB = (sB < t) ? __expf(p[sB] - m) * inv : 0.0f;
            h[e / 2] = __halves2half2(__float2half(wA), __float2half(wB));
        }
        *(uint4*)(oh + s0) = *(uint4*)h;
    }
}

// ===========================================================================
extern "C" void kernel_launch(void* const* d_in, const int* in_sizes, int n_in,
                              void* d_out, int out_size)
{
    const float* x = (const float*)d_in[0];
    const float* W = (const float*)d_in[1];
    float* out = (float*)d_out;

    f16 *xhi, *xlo, *whi, *wlo, *xHhi, *xHlo, *wei;
    float* sc;
    cudaGetSymbolAddress((void**)&xhi,  g_xhi);
    cudaGetSymbolAddress((void**)&xlo,  g_xlo);
    cudaGetSymbolAddress((void**)&whi,  g_whi);
    cudaGetSymbolAddress((void**)&wlo,  g_wlo);
    cudaGetSymbolAddress((void**)&xHhi, g_xHhi);
    cudaGetSymbolAddress((void**)&xHlo, g_xHlo);
    cudaGetSymbolAddress((void**)&wei,  g_wei);
    cudaGetSymbolAddress((void**)&sc,   g_sc);

    cudaFuncSetAttribute(gemm_3x<false, 2>,
                         cudaFuncAttributeMaxDynamicSharedMemorySize, SMEM_TOTAL);
    cudaFuncSetAttribute(gemm_3x<true, 0>,
                         cudaFuncAttributeMaxDynamicSharedMemorySize, SMEM_TOTAL);
    cudaFuncSetAttribute(gemm_wei,
                         cudaFuncAttributeMaxDynamicSharedMemorySize, W_SMEM);

    split_f16<<<4096, 256>>>(x, xhi, xlo, (long long)BB * TT * CC / 4);
    split_f16<<<1024, 256>>>(W, whi, wlo, (long long)CC * CC / 4);

    // K1: xH = x @ W^T  -> fp16 hi/lo  (3-pass)
    gemm_3x<false, 2><<<dim3(CC / 128, (BB * TT) / 128, 1), 256, SMEM_TOTAL>>>(
        xhi, xlo, whi, wlo, nullptr, xHhi, xHlo,
        CC, CC, CC, CC, 0, 0, 0);

    // K2: scores(fp32) = x @ xH^T per batch, causal tiles only (3-pass)
    gemm_3x<true, 0><<<dim3(TT / 128, TT / 128, BB), 256, SMEM_TOTAL>>>(
        xhi, xlo, xHhi, xHlo, sc, nullptr, nullptr,
        CC, CC, TT, CC,
        (long long)TT * CC, (long long)TT * CC, (long long)TT * TT);

    // K3: causal softmax -> wei fp16 (LPT, write-trimmed)
    softmax_causal<<<BB * TT, 256>>>(sc, wei);

    // K4: out = -(wei @ xHhi), 1-pass fp16, K clamped, LPT, 4-stage
    gemm_wei<<<dim3(CC / 128, TT / 128, BB), 256, W_SMEM>>>(
        wei, xHhi, out);
}

// round 13
// speedup vs baseline: 1.4819x; 1.0021x over previous
#include <cuda_runtime.h>
#include <cuda_fp16.h>
#include <cstdint>

#define BB 8
#define TT 2048
#define CC 1024

typedef __half f16;

// Scratch (device globals — allocation-free)
__device__ f16    g_xhi  [(size_t)BB * TT * CC];
__device__ f16    g_xlo  [(size_t)BB * TT * CC];
__device__ f16    g_whi  [(size_t)CC * CC];
__device__ f16    g_wlo  [(size_t)CC * CC];
__device__ f16    g_xHhi [(size_t)BB * TT * CC];
__device__ f16    g_xHlo [(size_t)BB * TT * CC];
__device__ float  g_sc   [(size_t)BB * TT * TT];
__device__ f16    g_wei  [(size_t)BB * TT * TT];

// ===========================================================================
// helpers
// ===========================================================================
__device__ __forceinline__ uint32_t smem_u32(const void* p) {
    uint32_t a;
    asm("{ .reg .u64 t; cvta.to.shared.u64 t, %1; cvt.u32.u64 %0, t; }" : "=r"(a) : "l"(p));
    return a;
}
__device__ __forceinline__ void cp16(uint32_t s, const void* g) {
    asm volatile("cp.async.cg.shared.global [%0], [%1], 16;" :: "r"(s), "l"(g) : "memory");
}
__device__ __forceinline__ void ldsm4(uint32_t addr, uint32_t& r0, uint32_t& r1,
                                      uint32_t& r2, uint32_t& r3) {
    asm volatile("ldmatrix.sync.aligned.m8n8.x4.shared.b16 {%0,%1,%2,%3}, [%4];"
                 : "=r"(r0), "=r"(r1), "=r"(r2), "=r"(r3) : "r"(addr));
}
__device__ __forceinline__ void ldsm4t(uint32_t addr, uint32_t& r0, uint32_t& r1,
                                       uint32_t& r2, uint32_t& r3) {
    asm volatile("ldmatrix.sync.aligned.m8n8.x4.trans.shared.b16 {%0,%1,%2,%3}, [%4];"
                 : "=r"(r0), "=r"(r1), "=r"(r2), "=r"(r3) : "r"(addr));
}
__device__ __forceinline__ void mma_f16(float c[4], const uint32_t a[4], const uint32_t b[2]) {
    asm volatile(
        "mma.sync.aligned.m16n8k16.row.col.f32.f16.f16.f32 "
        "{%0,%1,%2,%3}, {%4,%5,%6,%7}, {%8,%9}, {%0,%1,%2,%3};"
        : "+f"(c[0]), "+f"(c[1]), "+f"(c[2]), "+f"(c[3])
        : "r"(a[0]), "r"(a[1]), "r"(a[2]), "r"(a[3]), "r"(b[0]), "r"(b[1]));
}
__device__ __forceinline__ void stg_cs_f2(float* p, float a, float b) {
    asm volatile("st.global.cs.v2.f32 [%0], {%1, %2};" :: "l"(p), "f"(a), "f"(b) : "memory");
}

// swizzled 16B-chunk offset within a 128x32-f16 (64B-row) K-major tile
__device__ __forceinline__ uint32_t swz(int row, int chunk) {
    return (uint32_t)(row * 64 + ((chunk ^ ((row >> 1) & 3)) << 4));
}

// ===========================================================================
// 3xFP16 GEMM:  C = A[M,K] @ B[N,K]^T, fp16 hi/lo inputs, 128x128 tile, KC=32
// 3-stage cp.async pipeline, swizzled 64B rows, 2 CTAs/SM.
// OUTMODE: 0 = fp32 (streaming .cs stores), 2 = fp16 hi/lo split pair
// ===========================================================================
#define AHI_OFF 0
#define ALO_OFF 8192
#define BHI_OFF 16384
#define BLO_OFF 24576
#define STG_BYTES 32768
#define SMEM_TOTAL (3 * STG_BYTES)   // 98304

template <bool CAUSAL, int OUTMODE>
__global__ __launch_bounds__(256, 2) void gemm_3x(
    const f16* __restrict__ Ahi, const f16* __restrict__ Alo,
    const f16* __restrict__ Bhi, const f16* __restrict__ Blo,
    float* __restrict__ Cf, f16* __restrict__ Chi, f16* __restrict__ Clo,
    int lda, int ldb, int ldc, int Kfull,
    long long sA, long long sB, long long sC)
{
    const int bx = blockIdx.x, by = blockIdx.y, bz = blockIdx.z;
    if (CAUSAL && bx > by) return;

    Ahi += (long long)bz * sA; Alo += (long long)bz * sA;
    Bhi += (long long)bz * sB; Blo += (long long)bz * sB;

    const int m0 = by * 128, n0 = bx * 128;
    const int nc = Kfull / 32;

    extern __shared__ char smem[];
    const uint32_t sbase = smem_u32(smem);
    const int tid = threadIdx.x;
    const int wid = tid >> 5, lane = tid & 31;
    const int wm = wid & 1, wn = wid >> 1;
    const int g = lane >> 3, i = lane & 7;

    const int arow_base = wm * 64 + i + (g & 1) * 8;
    const int brow_base = wn * 32 + i + (g >> 1) * 8;
    const int achunk0 = g >> 1;
    const int bchunk0 = g & 1;

    const int l_row = tid >> 2, l_ch = tid & 3;
    const uint32_t l_soff0 = swz(l_row, l_ch);
    const uint32_t l_soff1 = swz(l_row + 64, l_ch);

    float acc[4][4][4];
#pragma unroll
    for (int a = 0; a < 4; a++)
#pragma unroll
        for (int b = 0; b < 4; b++)
#pragma unroll
            for (int c = 0; c < 4; c++) acc[a][b][c] = 0.f;

    auto issue = [&](int ch) {
        const uint32_t st = sbase + (uint32_t)(ch % 3) * STG_BYTES;
        const long long k0 = (long long)ch * 32 + l_ch * 8;
        {
            const long long ga = (long long)(m0 + l_row) * lda + k0;
            const long long gb = (long long)(n0 + l_row) * ldb + k0;
            cp16(st + AHI_OFF + l_soff0, Ahi + ga);
            cp16(st + ALO_OFF + l_soff0, Alo + ga);
            cp16(st + BHI_OFF + l_soff0, Bhi + gb);
            cp16(st + BLO_OFF + l_soff0, Blo + gb);
        }
        {
            const long long ga = (long long)(m0 + l_row + 64) * lda + k0;
            const long long gb = (long long)(n0 + l_row + 64) * ldb + k0;
            cp16(st + AHI_OFF + l_soff1, Ahi + ga);
            cp16(st + ALO_OFF + l_soff1, Alo + ga);
            cp16(st + BHI_OFF + l_soff1, Bhi + gb);
            cp16(st + BLO_OFF + l_soff1, Blo + gb);
        }
    };

#pragma unroll
    for (int s = 0; s < 2; s++) {
        if (s < nc) issue(s);
        asm volatile("cp.async.commit_group;" ::: "memory");
    }

    for (int ch = 0; ch < nc; ch++) {
        asm volatile("cp.async.wait_group 1;" ::: "memory");
        __syncthreads();
        if (ch + 2 < nc) issue(ch + 2);
        asm volatile("cp.async.commit_group;" ::: "memory");

        const uint32_t st = sbase + (uint32_t)(ch % 3) * STG_BYTES;

#pragma unroll
        for (int ks = 0; ks < 2; ks++) {
            uint32_t ah[4][4], al[4][4], bh[4][2], bl[4][2];
#pragma unroll
            for (int mt = 0; mt < 4; mt++) {
                const uint32_t ao = swz(arow_base + mt * 16, achunk0 + ks * 2);
                ldsm4(st + AHI_OFF + ao, ah[mt][0], ah[mt][1], ah[mt][2], ah[mt][3]);
                ldsm4(st + ALO_OFF + ao, al[mt][0], al[mt][1], al[mt][2], al[mt][3]);
            }
#pragma unroll
            for (int j = 0; j < 2; j++) {
                const uint32_t bo = swz(brow_base + j * 16, bchunk0 + ks * 2);
                uint32_t r0, r1, r2, r3;
                ldsm4(st + BHI_OFF + bo, r0, r1, r2, r3);
                bh[2 * j][0] = r0; bh[2 * j][1] = r1; bh[2 * j + 1][0] = r2; bh[2 * j + 1][1] = r3;
                ldsm4(st + BLO_OFF + bo, r0, r1, r2, r3);
                bl[2 * j][0] = r0; bl[2 * j][1] = r1; bl[2 * j + 1][0] = r2; bl[2 * j + 1][1] = r3;
            }
#pragma unroll
            for (int mt = 0; mt < 4; mt++)
#pragma unroll
                for (int nt = 0; nt < 4; nt++) mma_f16(acc[mt][nt], ah[mt], bh[nt]);
#pragma unroll
            for (int mt = 0; mt < 4; mt++)
#pragma unroll
                for (int nt = 0; nt < 4; nt++) mma_f16(acc[mt][nt], ah[mt], bl[nt]);
#pragma unroll
            for (int mt = 0; mt < 4; mt++)
#pragma unroll
                for (int nt = 0; nt < 4; nt++) mma_f16(acc[mt][nt], al[mt], bh[nt]);
        }
    }

    // ---- epilogue ----
    const int rr = lane >> 2, cb = (lane & 3) * 2;
#pragma unroll
    for (int mt = 0; mt < 4; mt++) {
#pragma unroll
        for (int nt = 0; nt < 4; nt++) {
            const int row = m0 + wm * 64 + mt * 16 + rr;
            const int col = n0 + wn * 32 + nt * 8 + cb;
            const float s0 = acc[mt][nt][0], s1 = acc[mt][nt][1];
            const float s2 = acc[mt][nt][2], s3 = acc[mt][nt][3];
            if (OUTMODE == 0) {
                float* base = Cf + (long long)bz * sC;
                stg_cs_f2(base + (long long)row * ldc + col, s0, s1);
                stg_cs_f2(base + (long long)(row + 8) * ldc + col, s2, s3);
            } else {
                f16* oh = Chi + (long long)bz * sC;
                f16* ol = Clo + (long long)bz * sC;
                f16 h0 = __float2half(s0), h1 = __float2half(s1);
                f16 h2 = __float2half(s2), h3 = __float2half(s3);
                f16 l0 = __float2half(s0 - __half2float(h0));
                f16 l1 = __float2half(s1 - __half2float(h1));
                f16 l2 = __float2half(s2 - __half2float(h2));
                f16 l3 = __float2half(s3 - __half2float(h3));
                *(__half2*)(oh + (long long)row * ldc + col)       = __halves2half2(h0, h1);
                *(__half2*)(oh + (long long)(row + 8) * ldc + col) = __halves2half2(h2, h3);
                *(__half2*)(ol + (long long)row * ldc + col)       = __halves2half2(l0, l1);
                *(__half2*)(ol + (long long)(row + 8) * ldc + col) = __halves2half2(l2, l3);
            }
        }
    }
}

// ===========================================================================
// K4: out[t][c] = -sum_s wei[t][s] * xH[s][c]
// 1-pass fp16 GEMM: A = wei (fp16, K-major), B = xHhi (MN-major, trans-ldsm).
// K clamped, LPT, 4-stage pipeline, 2 CTA/SM.
// ===========================================================================
#define W_A   0
#define W_B   8192
#define W_STG 16896              // 8192 + 32*272
#define W_NST 4
#define W_SMEM (W_NST * W_STG)   // 67584

__global__ __launch_bounds__(256, 2) void gemm_wei(
    const f16* __restrict__ Wei,
    const f16* __restrict__ Bh,
    float* __restrict__ Out)
{
    const int bx = blockIdx.x, bz = blockIdx.z;
    const int by = (int)gridDim.y - 1 - (int)blockIdx.y;   // LPT
    const f16* wei = Wei + (long long)bz * TT * TT;
    const f16* bhi = Bh + (long long)bz * TT * CC;
    float* out = Out + (long long)bz * TT * CC;

    const int m0 = by * 128, n0 = bx * 128;
    const int Klim = min(TT, (by + 1) * 128);
    const int nc = Klim / 32;

    extern __shared__ char smem[];
    const uint32_t sbase = smem_u32(smem);
    const int tid = threadIdx.x;
    const int wid = tid >> 5, lane = tid & 31;
    const int wm = wid & 1, wn = wid >> 1;
    const int g = lane >> 3, i = lane & 7;

    const int arow_base = wm * 64 + i + (g & 1) * 8;
    const int achunk0 = g >> 1;
    const uint32_t bLaneT = (uint32_t)((lane & 15) * 272 + (lane >> 4) * 16 + wn * 64);

    const int l_row = tid >> 2, l_ch = tid & 3;
    const uint32_t l_soff0 = swz(l_row, l_ch);
    const uint32_t l_soff1 = swz(l_row + 64, l_ch);

    float acc[4][4][4];
#pragma unroll
    for (int a = 0; a < 4; a++)
#pragma unroll
        for (int b = 0; b < 4; b++)
#pragma unroll
            for (int c = 0; c < 4; c++) acc[a][b][c] = 0.f;

    auto issue = [&](int ch) {
        const uint32_t st = sbase + (uint32_t)(ch % W_NST) * W_STG;
        const long long k0 = (long long)ch * 32 + l_ch * 8;
        {
            cp16(st + W_A + l_soff0, wei + (long long)(m0 + l_row) * TT + k0);
            cp16(st + W_A + l_soff1, wei + (long long)(m0 + l_row + 64) * TT + k0);
        }
        const long long kb = (long long)ch * 32;
#pragma unroll
        for (int r = 0; r < 2; r++) {
            const int idx = tid + r * 256;
            const int brow = idx >> 4, bseg = idx & 15;
            const long long go = (kb + brow) * CC + n0 + bseg * 8;
            const uint32_t so = (uint32_t)(brow * 272 + bseg * 16);
            cp16(st + W_B + so, bhi + go);
        }
    };

#pragma unroll
    for (int s = 0; s < W_NST - 1; s++) {
        if (s < nc) issue(s);
        asm volatile("cp.async.commit_group;" ::: "memory");
    }

    for (int ch = 0; ch < nc; ch++) {
        asm volatile("cp.async.wait_group %0;" :: "n"(W_NST - 2) : "memory");
        __syncthreads();
        if (ch + W_NST - 1 < nc) issue(ch + W_NST - 1);
        asm volatile("cp.async.commit_group;" ::: "memory");

        const uint32_t st = sbase + (uint32_t)(ch % W_NST) * W_STG;

#pragma unroll
        for (int ks = 0; ks < 2; ks++) {
            uint32_t ah[4][4], bh[4][2];
#pragma unroll
            for (int mt = 0; mt < 4; mt++) {
                const uint32_t ao = swz(arow_base + mt * 16, achunk0 + ks * 2);
                ldsm4(st + W_A + ao, ah[mt][0], ah[mt][1], ah[mt][2], ah[mt][3]);
            }
#pragma unroll
            for (int j = 0; j < 2; j++) {
                uint32_t r0, r1, r2, r3;
                ldsm4t(st + W_B + bLaneT + ks * (16 * 272) + j * 32, r0, r1, r2, r3);
                bh[2 * j][0] = r0; bh[2 * j][1] = r1; bh[2 * j + 1][0] = r2; bh[2 * j + 1][1] = r3;
            }
#pragma unroll
            for (int mt = 0; mt < 4; mt++)
#pragma unroll
                for (int nt = 0; nt < 4; nt++) mma_f16(acc[mt][nt], ah[mt], bh[nt]);
        }
    }

    const int rr = lane >> 2, cb = (lane & 3) * 2;
#pragma unroll
    for (int mt = 0; mt < 4; mt++) {
#pragma unroll
        for (int nt = 0; nt < 4; nt++) {
            const int row = m0 + wm * 64 + mt * 16 + rr;
            const int col = n0 + wn * 32 + nt * 8 + cb;
            *(float2*)(out + (long long)row * CC + col) =
                make_float2(-acc[mt][nt][0], -acc[mt][nt][1]);
            *(float2*)(out + (long long)(row + 8) * CC + col) =
                make_float2(-acc[mt][nt][2], -acc[mt][nt][3]);
        }
    }
}

// ===========================================================================
// fp32 -> fp16 hi/lo split, fused for x (n4x float4s) then W (n4w float4s)
// ===========================================================================
__global__ __launch_bounds__(256) void split_f16_fused(
    const float* __restrict__ xsrc, f16* __restrict__ xh, f16* __restrict__ xl, long long n4x,
    const float* __restrict__ wsrc, f16* __restrict__ wh, f16* __restrict__ wl, long long n4w)
{
    const long long total = n4x + n4w;
    for (long long q = (long long)blockIdx.x * 256 + threadIdx.x; q < total;
         q += (long long)gridDim.x * 256) {
        const float4 v = (q < n4x) ? ((const float4*)xsrc)[q]
                                   : ((const float4*)wsrc)[q - n4x];
        const f16 h0 = __float2half(v.x), h1 = __float2half(v.y);
        const f16 h2 = __float2half(v.z), h3 = __float2half(v.w);
        const f16 l0 = __float2half(v.x - __half2float(h0));
        const f16 l1 = __float2half(v.y - __half2float(h1));
        const f16 l2 = __float2half(v.z - __half2float(h2));
        const f16 l3 = __float2half(v.w - __half2float(h3));
        __half2 hh[2] = { __halves2half2(h0, h1), __halves2half2(h2, h3) };
        __half2 ll[2] = { __halves2half2(l0, l1), __halves2half2(l2, l3) };
        if (q < n4x) {
            *(uint2*)(xh + q * 4) = *(uint2*)hh;
            *(uint2*)(xl + q * 4) = *(uint2*)ll;
        } else {
            *(uint2*)(wh + (q - n4x) * 4) = *(uint2*)hh;
            *(uint2*)(wl + (q - n4x) * 4) = *(uint2*)ll;
        }
    }
}

// ===========================================================================
// Causal softmax: fp32 scores -> wei fp16.
// exp values cached in smem during the sum pass (row = 8KB), so scores are
// read from global exactly once. Writes only s < ((t>>7)+1)*128; LPT order.
// ===========================================================================
__global__ __launch_bounds__(256) void softmax_causal(
    const float* __restrict__ sc, f16* __restrict__ wout)
{
    const long long row = (long long)(BB * TT - 1) - blockIdx.x;   // LPT
    const int t = (int)(row % TT);
    const float* p = sc + row * TT;
    f16* oh = wout + row * TT;
    const int tid = threadIdx.x;
    const float4* p4 = (const float4*)p;
    const int n4 = t >> 2;
    const int wlim = ((t >> 7) + 1) << 7;

    __shared__ float red[8];
    __shared__ float ecache[TT];      // exp(p[s]-m) for s < t

    float m = -3.0e38f;
    for (int q = tid; q < n4; q += 256) {
        const float4 v = p4[q];
        m = fmaxf(m, fmaxf(fmaxf(v.x, v.y), fmaxf(v.z, v.w)));
    }
    for (int s = (n4 << 2) + tid; s < t; s += 256) m = fmaxf(m, p[s]);
#pragma unroll
    for (int o = 16; o; o >>= 1) m = fmaxf(m, __shfl_xor_sync(0xffffffffu, m, o));
    if ((tid & 31) == 0) red[tid >> 5] = m;
    __syncthreads();
    m = red[0];
#pragma unroll
    for (int w = 1; w < 8; w++) m = fmaxf(m, red[w]);
    __syncthreads();

    float sum = 0.0f;
    for (int q = tid; q < n4; q += 256) {
        const float4 v = p4[q];
        const float e0 = __expf(v.x - m), e1 = __expf(v.y - m);
        const float e2 = __expf(v.z - m), e3 = __expf(v.w - m);
        *(float4*)(ecache + q * 4) = make_float4(e0, e1, e2, e3);
        sum += e0 + e1 + e2 + e3;
    }
    for (int s = (n4 << 2) + tid; s < t; s += 256) {
        const float e = __expf(p[s] - m);
        ecache[s] = e;
        sum += e;
    }
#pragma unroll
    for (int o = 16; o; o >>= 1) sum += __shfl_xor_sync(0xffffffffu, sum, o);
    if ((tid & 31) == 0) red[tid >> 5] = sum;
    __syncthreads();
    sum = red[0] + red[1] + red[2] + red[3] + red[4] + red[5] + red[6] + red[7];

    const float inv = (t > 0) ? (1.0f / sum) : 0.0f;

    for (int s0 = tid * 8; s0 < wlim; s0 += 2048) {
        __half2 h[4];
#pragma unroll
        for (int e = 0; e < 8; e += 2) {
            const int sA = s0 + e, sB = s0 + e + 1;
            const float wA = (sA < t) ? ecache[sA] * inv : 0.0f;
            const float wB = (sB < t) ? ecache[sB] * inv : 0.0f;
            h[e / 2] = __halves2half2(__float2half(wA), __float2half(wB));
        }
        *(uint4*)(oh + s0) = *(uint4*)h;
    }
}

// ===========================================================================
extern "C" void kernel_launch(void* const* d_in, const int* in_sizes, int n_in,
                              void* d_out, int out_size)
{
    const float* x = (const float*)d_in[0];
    const float* W = (const float*)d_in[1];
    float* out = (float*)d_out;

    f16 *xhi, *xlo, *whi, *wlo, *xHhi, *xHlo, *wei;
    float* sc;
    cudaGetSymbolAddress((void**)&xhi,  g_xhi);
    cudaGetSymbolAddress((void**)&xlo,  g_xlo);
    cudaGetSymbolAddress((void**)&whi,  g_whi);
    cudaGetSymbolAddress((void**)&wlo,  g_wlo);
    cudaGetSymbolAddress((void**)&xHhi, g_xHhi);
    cudaGetSymbolAddress((void**)&xHlo, g_xHlo);
    cudaGetSymbolAddress((void**)&wei,  g_wei);
    cudaGetSymbolAddress((void**)&sc,   g_sc);

    cudaFuncSetAttribute(gemm_3x<false, 2>,
                         cudaFuncAttributeMaxDynamicSharedMemorySize, SMEM_TOTAL);
    cudaFuncSetAttribute(gemm_3x<true, 0>,
                         cudaFuncAttributeMaxDynamicSharedMemorySize, SMEM_TOTAL);
    cudaFuncSetAttribute(gemm_wei,
                         cudaFuncAttributeMaxDynamicSharedMemorySize, W_SMEM);

    // fused split: x then W
    split_f16_fused<<<4352, 256>>>(
        x, xhi, xlo, (long long)BB * TT * CC / 4,
        W, whi, wlo, (long long)CC * CC / 4);

    // K1: xH = x @ W^T  -> fp16 hi/lo  (3-pass)
    gemm_3x<false, 2><<<dim3(CC / 128, (BB * TT) / 128, 1), 256, SMEM_TOTAL>>>(
        xhi, xlo, whi, wlo, nullptr, xHhi, xHlo,
        CC, CC, CC, CC, 0, 0, 0);

    // K2: scores(fp32) = x @ xH^T per batch, causal tiles only (3-pass)
    gemm_3x<true, 0><<<dim3(TT / 128, TT / 128, BB), 256, SMEM_TOTAL>>>(
        xhi, xlo, xHhi, xHlo, sc, nullptr, nullptr,
        CC, CC, TT, CC,
        (long long)TT * CC, (long long)TT * CC, (long long)TT * TT);

    // K3: causal softmax -> wei fp16 (LPT, write-trimmed, smem exp cache)
    softmax_causal<<<BB * TT, 256>>>(sc, wei);

    // K4: out = -(wei @ xHhi), 1-pass fp16, K clamped, LPT, 4-stage
    gemm_wei<<<dim3(CC / 128, TT / 128, BB), 256, W_SMEM>>>(
        wei, xHhi, out);
}

// round 14
// speedup vs baseline: 1.4893x; 1.0050x over previous
#include <cuda_runtime.h>
#include <cuda_fp16.h>
#include <cstdint>
#include <cmath>

#define BB 8
#define TT 2048
#define CC 1024

typedef __half f16;

// Scratch (device globals — allocation-free)
__device__ f16    g_xhi  [(size_t)BB * TT * CC];
__device__ f16    g_xlo  [(size_t)BB * TT * CC];
__device__ f16    g_whi  [(size_t)CC * CC];
__device__ f16    g_wlo  [(size_t)CC * CC];
__device__ f16    g_xHhi [(size_t)BB * TT * CC];
__device__ f16    g_xHlo [(size_t)BB * TT * CC];
__device__ float  g_sc   [(size_t)BB * TT * TT];
__device__ f16    g_wei  [(size_t)BB * TT * TT];

// ===========================================================================
// helpers
// ===========================================================================
__device__ __forceinline__ uint32_t smem_u32(const void* p) {
    uint32_t a;
    asm("{ .reg .u64 t; cvta.to.shared.u64 t, %1; cvt.u32.u64 %0, t; }" : "=r"(a) : "l"(p));
    return a;
}
__device__ __forceinline__ void cp16(uint32_t s, const void* g) {
    asm volatile("cp.async.cg.shared.global [%0], [%1], 16;" :: "r"(s), "l"(g) : "memory");
}
__device__ __forceinline__ void ldsm4(uint32_t addr, uint32_t& r0, uint32_t& r1,
                                      uint32_t& r2, uint32_t& r3) {
    asm volatile("ldmatrix.sync.aligned.m8n8.x4.shared.b16 {%0,%1,%2,%3}, [%4];"
                 : "=r"(r0), "=r"(r1), "=r"(r2), "=r"(r3) : "r"(addr));
}
__device__ __forceinline__ void ldsm4t(uint32_t addr, uint32_t& r0, uint32_t& r1,
                                       uint32_t& r2, uint32_t& r3) {
    asm volatile("ldmatrix.sync.aligned.m8n8.x4.trans.shared.b16 {%0,%1,%2,%3}, [%4];"
                 : "=r"(r0), "=r"(r1), "=r"(r2), "=r"(r3) : "r"(addr));
}
__device__ __forceinline__ void mma_f16(float c[4], const uint32_t a[4], const uint32_t b[2]) {
    asm volatile(
        "mma.sync.aligned.m16n8k16.row.col.f32.f16.f16.f32 "
        "{%0,%1,%2,%3}, {%4,%5,%6,%7}, {%8,%9}, {%0,%1,%2,%3};"
        : "+f"(c[0]), "+f"(c[1]), "+f"(c[2]), "+f"(c[3])
        : "r"(a[0]), "r"(a[1]), "r"(a[2]), "r"(a[3]), "r"(b[0]), "r"(b[1]));
}
__device__ __forceinline__ void stg_cs_f2(float* p, float a, float b) {
    asm volatile("st.global.cs.v2.f32 [%0], {%1, %2};" :: "l"(p), "f"(a), "f"(b) : "memory");
}

// swizzled 16B-chunk offset within a 128x32-f16 (64B-row) K-major tile
__device__ __forceinline__ uint32_t swz(int row, int chunk) {
    return (uint32_t)(row * 64 + ((chunk ^ ((row >> 1) & 3)) << 4));
}

// ===========================================================================
// 3xFP16 GEMM:  C = A[M,K] @ B[N,K]^T, fp16 hi/lo inputs, 128x128 tile, KC=32
// 3-stage cp.async pipeline, swizzled 64B rows, 2 CTAs/SM.
// CAUSAL: 1-D lower-triangle grid (blockIdx.x = linearized tile index).
// OUTMODE: 0 = fp32 (streaming .cs stores), 2 = fp16 hi/lo split pair
// ===========================================================================
#define AHI_OFF 0
#define ALO_OFF 8192
#define BHI_OFF 16384
#define BLO_OFF 24576
#define STG_BYTES 32768
#define SMEM_TOTAL (3 * STG_BYTES)   // 98304

template <bool CAUSAL, int OUTMODE>
__global__ __launch_bounds__(256, 2) void gemm_3x(
    const f16* __restrict__ Ahi, const f16* __restrict__ Alo,
    const f16* __restrict__ Bhi, const f16* __restrict__ Blo,
    float* __restrict__ Cf, f16* __restrict__ Chi, f16* __restrict__ Clo,
    int lda, int ldb, int ldc, int Kfull,
    long long sA, long long sB, long long sC)
{
    int bx, by;
    const int bz = blockIdx.z;
    if (CAUSAL) {
        // lower-triangle linear index -> (by, bx), bx <= by
        const int idx = blockIdx.x;
        int t = (int)((sqrtf(8.0f * idx + 1.0f) - 1.0f) * 0.5f);
        while ((t + 1) * (t + 2) / 2 <= idx) t++;      // guard fp rounding
        while (t * (t + 1) / 2 > idx) t--;
        by = t;
        bx = idx - t * (t + 1) / 2;
    } else {
        bx = blockIdx.x; by = blockIdx.y;
    }

    Ahi += (long long)bz * sA; Alo += (long long)bz * sA;
    Bhi += (long long)bz * sB; Blo += (long long)bz * sB;

    const int m0 = by * 128, n0 = bx * 128;
    const int nc = Kfull / 32;

    extern __shared__ char smem[];
    const uint32_t sbase = smem_u32(smem);
    const int tid = threadIdx.x;
    const int wid = tid >> 5, lane = tid & 31;
    const int wm = wid & 1, wn = wid >> 1;
    const int g = lane >> 3, i = lane & 7;

    const int arow_base = wm * 64 + i + (g & 1) * 8;
    const int brow_base = wn * 32 + i + (g >> 1) * 8;
    const int achunk0 = g >> 1;
    const int bchunk0 = g & 1;

    const int l_row = tid >> 2, l_ch = tid & 3;
    const uint32_t l_soff0 = swz(l_row, l_ch);
    const uint32_t l_soff1 = swz(l_row + 64, l_ch);

    float acc[4][4][4];
#pragma unroll
    for (int a = 0; a < 4; a++)
#pragma unroll
        for (int b = 0; b < 4; b++)
#pragma unroll
            for (int c = 0; c < 4; c++) acc[a][b][c] = 0.f;

    auto issue = [&](int ch) {
        const uint32_t st = sbase + (uint32_t)(ch % 3) * STG_BYTES;
        const long long k0 = (long long)ch * 32 + l_ch * 8;
        {
            const long long ga = (long long)(m0 + l_row) * lda + k0;
            const long long gb = (long long)(n0 + l_row) * ldb + k0;
            cp16(st + AHI_OFF + l_soff0, Ahi + ga);
            cp16(st + ALO_OFF + l_soff0, Alo + ga);
            cp16(st + BHI_OFF + l_soff0, Bhi + gb);
            cp16(st + BLO_OFF + l_soff0, Blo + gb);
        }
        {
            const long long ga = (long long)(m0 + l_row + 64) * lda + k0;
            const long long gb = (long long)(n0 + l_row + 64) * ldb + k0;
            cp16(st + AHI_OFF + l_soff1, Ahi + ga);
            cp16(st + ALO_OFF + l_soff1, Alo + ga);
            cp16(st + BHI_OFF + l_soff1, Bhi + gb);
            cp16(st + BLO_OFF + l_soff1, Blo + gb);
        }
    };

#pragma unroll
    for (int s = 0; s < 2; s++) {
        if (s < nc) issue(s);
        asm volatile("cp.async.commit_group;" ::: "memory");
    }

    for (int ch = 0; ch < nc; ch++) {
        asm volatile("cp.async.wait_group 1;" ::: "memory");
        __syncthreads();
        if (ch + 2 < nc) issue(ch + 2);
        asm volatile("cp.async.commit_group;" ::: "memory");

        const uint32_t st = sbase + (uint32_t)(ch % 3) * STG_BYTES;

#pragma unroll
        for (int ks = 0; ks < 2; ks++) {
            uint32_t ah[4][4], al[4][4], bh[4][2], bl[4][2];
#pragma unroll
            for (int mt = 0; mt < 4; mt++) {
                const uint32_t ao = swz(arow_base + mt * 16, achunk0 + ks * 2);
                ldsm4(st + AHI_OFF + ao, ah[mt][0], ah[mt][1], ah[mt][2], ah[mt][3]);
                ldsm4(st + ALO_OFF + ao, al[mt][0], al[mt][1], al[mt][2], al[mt][3]);
            }
#pragma unroll
            for (int j = 0; j < 2; j++) {
                const uint32_t bo = swz(brow_base + j * 16, bchunk0 + ks * 2);
                uint32_t r0, r1, r2, r3;
                ldsm4(st + BHI_OFF + bo, r0, r1, r2, r3);
                bh[2 * j][0] = r0; bh[2 * j][1] = r1; bh[2 * j + 1][0] = r2; bh[2 * j + 1][1] = r3;
                ldsm4(st + BLO_OFF + bo, r0, r1, r2, r3);
                bl[2 * j][0] = r0; bl[2 * j][1] = r1; bl[2 * j + 1][0] = r2; bl[2 * j + 1][1] = r3;
            }
#pragma unroll
            for (int mt = 0; mt < 4; mt++)
#pragma unroll
                for (int nt = 0; nt < 4; nt++) mma_f16(acc[mt][nt], ah[mt], bh[nt]);
#pragma unroll
            for (int mt = 0; mt < 4; mt++)
#pragma unroll
                for (int nt = 0; nt < 4; nt++) mma_f16(acc[mt][nt], ah[mt], bl[nt]);
#pragma unroll
            for (int mt = 0; mt < 4; mt++)
#pragma unroll
                for (int nt = 0; nt < 4; nt++) mma_f16(acc[mt][nt], al[mt], bh[nt]);
        }
    }

    // ---- epilogue ----
    const int rr = lane >> 2, cb = (lane & 3) * 2;
#pragma unroll
    for (int mt = 0; mt < 4; mt++) {
#pragma unroll
        for (int nt = 0; nt < 4; nt++) {
            const int row = m0 + wm * 64 + mt * 16 + rr;
            const int col = n0 + wn * 32 + nt * 8 + cb;
            const float s0 = acc[mt][nt][0], s1 = acc[mt][nt][1];
            const float s2 = acc[mt][nt][2], s3 = acc[mt][nt][3];
            if (OUTMODE == 0) {
                float* base = Cf + (long long)bz * sC;
                stg_cs_f2(base + (long long)row * ldc + col, s0, s1);
                stg_cs_f2(base + (long long)(row + 8) * ldc + col, s2, s3);
            } else {
                f16* oh = Chi + (long long)bz * sC;
                f16* ol = Clo + (long long)bz * sC;
                f16 h0 = __float2half(s0), h1 = __float2half(s1);
                f16 h2 = __float2half(s2), h3 = __float2half(s3);
                f16 l0 = __float2half(s0 - __half2float(h0));
                f16 l1 = __float2half(s1 - __half2float(h1));
                f16 l2 = __float2half(s2 - __half2float(h2));
                f16 l3 = __float2half(s3 - __half2float(h3));
                *(__half2*)(oh + (long long)row * ldc + col)       = __halves2half2(h0, h1);
                *(__half2*)(oh + (long long)(row + 8) * ldc + col) = __halves2half2(h2, h3);
                *(__half2*)(ol + (long long)row * ldc + col)       = __halves2half2(l0, l1);
                *(__half2*)(ol + (long long)(row + 8) * ldc + col) = __halves2half2(l2, l3);
            }
        }
    }
}

// ===========================================================================
// K4: out[t][c] = -sum_s wei[t][s] * xH[s][c]
// 1-pass fp16 GEMM: A = wei (fp16, K-major), B = xHhi (MN-major, trans-ldsm).
// K clamped, LPT, 4-stage pipeline, 2 CTA/SM.
// ===========================================================================
#define W_A   0
#define W_B   8192
#define W_STG 16896              // 8192 + 32*272
#define W_NST 4
#define W_SMEM (W_NST * W_STG)   // 67584

__global__ __launch_bounds__(256, 2) void gemm_wei(
    const f16* __restrict__ Wei,
    const f16* __restrict__ Bh,
    float* __restrict__ Out)
{
    const int bx = blockIdx.x, bz = blockIdx.z;
    const int by = (int)gridDim.y - 1 - (int)blockIdx.y;   // LPT
    const f16* wei = Wei + (long long)bz * TT * TT;
    const f16* bhi = Bh + (long long)bz * TT * CC;
    float* out = Out + (long long)bz * TT * CC;

    const int m0 = by * 128, n0 = bx * 128;
    const int Klim = min(TT, (by + 1) * 128);
    const int nc = Klim / 32;

    extern __shared__ char smem[];
    const uint32_t sbase = smem_u32(smem);
    const int tid = threadIdx.x;
    const int wid = tid >> 5, lane = tid & 31;
    const int wm = wid & 1, wn = wid >> 1;
    const int g = lane >> 3, i = lane & 7;

    const int arow_base = wm * 64 + i + (g & 1) * 8;
    const int achunk0 = g >> 1;
    const uint32_t bLaneT = (uint32_t)((lane & 15) * 272 + (lane >> 4) * 16 + wn * 64);

    const int l_row = tid >> 2, l_ch = tid & 3;
    const uint32_t l_soff0 = swz(l_row, l_ch);
    const uint32_t l_soff1 = swz(l_row + 64, l_ch);

    float acc[4][4][4];
#pragma unroll
    for (int a = 0; a < 4; a++)
#pragma unroll
        for (int b = 0; b < 4; b++)
#pragma unroll
            for (int c = 0; c < 4; c++) acc[a][b][c] = 0.f;

    auto issue = [&](int ch) {
        const uint32_t st = sbase + (uint32_t)(ch % W_NST) * W_STG;
        const long long k0 = (long long)ch * 32 + l_ch * 8;
        {
            cp16(st + W_A + l_soff0, wei + (long long)(m0 + l_row) * TT + k0);
            cp16(st + W_A + l_soff1, wei + (long long)(m0 + l_row + 64) * TT + k0);
        }
        const long long kb = (long long)ch * 32;
#pragma unroll
        for (int r = 0; r < 2; r++) {
            const int idx = tid + r * 256;
            const int brow = idx >> 4, bseg = idx & 15;
            const long long go = (kb + brow) * CC + n0 + bseg * 8;
            const uint32_t so = (uint32_t)(brow * 272 + bseg * 16);
            cp16(st + W_B + so, bhi + go);
        }
    };

#pragma unroll
    for (int s = 0; s < W_NST - 1; s++) {
        if (s < nc) issue(s);
        asm volatile("cp.async.commit_group;" ::: "memory");
    }

    for (int ch = 0; ch < nc; ch++) {
        asm volatile("cp.async.wait_group %0;" :: "n"(W_NST - 2) : "memory");
        __syncthreads();
        if (ch + W_NST - 1 < nc) issue(ch + W_NST - 1);
        asm volatile("cp.async.commit_group;" ::: "memory");

        const uint32_t st = sbase + (uint32_t)(ch % W_NST) * W_STG;

#pragma unroll
        for (int ks = 0; ks < 2; ks++) {
            uint32_t ah[4][4], bh[4][2];
#pragma unroll
            for (int mt = 0; mt < 4; mt++) {
                const uint32_t ao = swz(arow_base + mt * 16, achunk0 + ks * 2);
                ldsm4(st + W_A + ao, ah[mt][0], ah[mt][1], ah[mt][2], ah[mt][3]);
            }
#pragma unroll
            for (int j = 0; j < 2; j++) {
                uint32_t r0, r1, r2, r3;
                ldsm4t(st + W_B + bLaneT + ks * (16 * 272) + j * 32, r0, r1, r2, r3);
                bh[2 * j][0] = r0; bh[2 * j][1] = r1; bh[2 * j + 1][0] = r2; bh[2 * j + 1][1] = r3;
            }
#pragma unroll
            for (int mt = 0; mt < 4; mt++)
#pragma unroll
                for (int nt = 0; nt < 4; nt++) mma_f16(acc[mt][nt], ah[mt], bh[nt]);
        }
    }

    const int rr = lane >> 2, cb = (lane & 3) * 2;
#pragma unroll
    for (int mt = 0; mt < 4; mt++) {
#pragma unroll
        for (int nt = 0; nt < 4; nt++) {
            const int row = m0 + wm * 64 + mt * 16 + rr;
            const int col = n0 + wn * 32 + nt * 8 + cb;
            *(float2*)(out + (long long)row * CC + col) =
                make_float2(-acc[mt][nt][0], -acc[mt][nt][1]);
            *(float2*)(out + (long long)(row + 8) * CC + col) =
                make_float2(-acc[mt][nt][2], -acc[mt][nt][3]);
        }
    }
}

// ===========================================================================
// fp32 -> fp16 hi/lo split, fused for x then W
// ===========================================================================
__global__ __launch_bounds__(256) void split_f16_fused(
    const float* __restrict__ xsrc, f16* __restrict__ xh, f16* __restrict__ xl, long long n4x,
    const float* __restrict__ wsrc, f16* __restrict__ wh, f16* __restrict__ wl, long long n4w)
{
    const long long total = n4x + n4w;
    for (long long q = (long long)blockIdx.x * 256 + threadIdx.x; q < total;
         q += (long long)gridDim.x * 256) {
        const float4 v = (q < n4x) ? ((const float4*)xsrc)[q]
                                   : ((const float4*)wsrc)[q - n4x];
        const f16 h0 = __float2half(v.x), h1 = __float2half(v.y);
        const f16 h2 = __float2half(v.z), h3 = __float2half(v.w);
        const f16 l0 = __float2half(v.x - __half2float(h0));
        const f16 l1 = __float2half(v.y - __half2float(h1));
        const f16 l2 = __float2half(v.z - __half2float(h2));
        const f16 l3 = __float2half(v.w - __half2float(h3));
        __half2 hh[2] = { __halves2half2(h0, h1), __halves2half2(h2, h3) };
        __half2 ll[2] = { __halves2half2(l0, l1), __halves2half2(l2, l3) };
        if (q < n4x) {
            *(uint2*)(xh + q * 4) = *(uint2*)hh;
            *(uint2*)(xl + q * 4) = *(uint2*)ll;
        } else {
            *(uint2*)(wh + (q - n4x) * 4) = *(uint2*)hh;
            *(uint2*)(wl + (q - n4x) * 4) = *(uint2*)ll;
        }
    }
}

// ===========================================================================
// Causal softmax: fp32 scores -> wei fp16.
// SINGLE global read: row (8KB) is copied to smem once, then max / exp+sum /
// write all run from smem. Writes only s < ((t>>7)+1)*128; LPT order.
// ===========================================================================
__global__ __launch_bounds__(256) void softmax_causal(
    const float* __restrict__ sc, f16* __restrict__ wout)
{
    const long long row = (long long)(BB * TT - 1) - blockIdx.x;   // LPT
    const int t = (int)(row % TT);
    const float* p = sc + row * TT;
    f16* oh = wout + row * TT;
    const int tid = threadIdx.x;
    const int n4 = (t + 3) >> 2;          // float4s covering [0, t)
    const int wlim = ((t >> 7) + 1) << 7;

    __shared__ float red[8];
    __shared__ float scr[TT];             // score row cache -> exp in place

    // ---- pass 0: single coalesced global read into smem ----
    {
        const float4* p4 = (const float4*)p;
        float4* s4 = (float4*)scr;
        for (int q = tid; q < n4; q += 256) s4[q] = p4[q];
    }
    __syncthreads();

    // ---- max over s < t (from smem) ----
    float m = -3.0e38f;
    for (int s = tid; s < t; s += 256) m = fmaxf(m, scr[s]);
#pragma unroll
    for (int o = 16; o; o >>= 1) m = fmaxf(m, __shfl_xor_sync(0xffffffffu, m, o));
    if ((tid & 31) == 0) red[tid >> 5] = m;
    __syncthreads();
    m = red[0];
#pragma unroll
    for (int w = 1; w < 8; w++) m = fmaxf(m, red[w]);
    __syncthreads();

    // ---- exp in place + sum (from smem) ----
    float sum = 0.0f;
    for (int s = tid; s < t; s += 256) {
        const float e = __expf(scr[s] - m);
        scr[s] = e;
        sum += e;
    }
#pragma unroll
    for (int o = 16; o; o >>= 1) sum += __shfl_xor_sync(0xffffffffu, sum, o);
    if ((tid & 31) == 0) red[tid >> 5] = sum;
    __syncthreads();
    sum = red[0] + red[1] + red[2] + red[3] + red[4] + red[5] + red[6] + red[7];

    const float inv = (t > 0) ? (1.0f / sum) : 0.0f;

    // ---- write wei fp16 (16B stores) from smem ----
    for (int s0 = tid * 8; s0 < wlim; s0 += 2048) {
        __half2 h[4];
#pragma unroll
        for (int e = 0; e < 8; e += 2) {
            const int sA = s0 + e, sB = s0 + e + 1;
            const float wA = (sA < t) ? scr[sA] * inv : 0.0f;
            const float wB = (sB < t) ? scr[sB] * inv : 0.0f;
            h[e / 2] = __halves2half2(__float2half(wA), __float2half(wB));
        }
        *(uint4*)(oh + s0) = *(uint4*)h;
    }
}

// ===========================================================================
extern "C" void kernel_launch(void* const* d_in, const int* in_sizes, int n_in,
                              void* d_out, int out_size)
{
    const float* x = (const float*)d_in[0];
    const float* W = (const float*)d_in[1];
    float* out = (float*)d_out;

    f16 *xhi, *xlo, *whi, *wlo, *xHhi, *xHlo, *wei;
    float* sc;
    cudaGetSymbolAddress((void**)&xhi,  g_xhi);
    cudaGetSymbolAddress((void**)&xlo,  g_xlo);
    cudaGetSymbolAddress((void**)&whi,  g_whi);
    cudaGetSymbolAddress((void**)&wlo,  g_wlo);
    cudaGetSymbolAddress((void**)&xHhi, g_xHhi);
    cudaGetSymbolAddress((void**)&xHlo, g_xHlo);
    cudaGetSymbolAddress((void**)&wei,  g_wei);
    cudaGetSymbolAddress((void**)&sc,   g_sc);

    cudaFuncSetAttribute(gemm_3x<false, 2>,
                         cudaFuncAttributeMaxDynamicSharedMemorySize, SMEM_TOTAL);
    cudaFuncSetAttribute(gemm_3x<true, 0>,
                         cudaFuncAttributeMaxDynamicSharedMemorySize, SMEM_TOTAL);
    cudaFuncSetAttribute(gemm_wei,
                         cudaFuncAttributeMaxDynamicSharedMemorySize, W_SMEM);

    // fused split: x then W
    split_f16_fused<<<4352, 256>>>(
        x, xhi, xlo, (long long)BB * TT * CC / 4,
        W, whi, wlo, (long long)CC * CC / 4);

    // K1: xH = x @ W^T  -> fp16 hi/lo  (3-pass)
    gemm_3x<false, 2><<<dim3(CC / 128, (BB * TT) / 128, 1), 256, SMEM_TOTAL>>>(
        xhi, xlo, whi, wlo, nullptr, xHhi, xHlo,
        CC, CC, CC, CC, 0, 0, 0);

    // K2: scores(fp32) = x @ xH^T per batch, exact lower-triangle grid (3-pass)
    {
        const int ntiles = (TT / 128) * (TT / 128 + 1) / 2;   // 136
        gemm_3x<true, 0><<<dim3(ntiles, 1, BB), 256, SMEM_TOTAL>>>(
            xhi, xlo, xHhi, xHlo, sc, nullptr, nullptr,
            CC, CC, TT, CC,
            (long long)TT * CC, (long long)TT * CC, (long long)TT * TT);
    }

    // K3: causal softmax -> wei fp16 (LPT, single global read, write-trimmed)
    softmax_causal<<<BB * TT, 256>>>(sc, wei);

    // K4: out = -(wei @ xHhi), 1-pass fp16, K clamped, LPT, 4-stage
    gemm_wei<<<dim3(CC / 128, TT / 128, BB), 256, W_SMEM>>>(
        wei, xHhi, out);
}

// round 15
// speedup vs baseline: 1.5184x; 1.0195x over previous
#include <cuda_runtime.h>
#include <cuda_fp16.h>
#include <cstdint>
#include <cmath>

#define BB 8
#define TT 2048
#define CC 1024

typedef __half f16;

// Scratch (device globals — allocation-free)
__device__ f16    g_xhi  [(size_t)BB * TT * CC];
__device__ f16    g_xlo  [(size_t)BB * TT * CC];
__device__ f16    g_whi  [(size_t)CC * CC];
__device__ f16    g_wlo  [(size_t)CC * CC];
__device__ f16    g_xHhi [(size_t)BB * TT * CC];
__device__ f16    g_xHlo [(size_t)BB * TT * CC];
__device__ float  g_sc   [(size_t)BB * TT * TT];
__device__ f16    g_wei  [(size_t)BB * TT * TT];

// ===========================================================================
// helpers
// ===========================================================================
__device__ __forceinline__ uint32_t smem_u32(const void* p) {
    uint32_t a;
    asm("{ .reg .u64 t; cvta.to.shared.u64 t, %1; cvt.u32.u64 %0, t; }" : "=r"(a) : "l"(p));
    return a;
}
__device__ __forceinline__ void cp16(uint32_t s, const void* g) {
    asm volatile("cp.async.cg.shared.global [%0], [%1], 16;" :: "r"(s), "l"(g) : "memory");
}
__device__ __forceinline__ void ldsm4(uint32_t addr, uint32_t& r0, uint32_t& r1,
                                      uint32_t& r2, uint32_t& r3) {
    asm volatile("ldmatrix.sync.aligned.m8n8.x4.shared.b16 {%0,%1,%2,%3}, [%4];"
                 : "=r"(r0), "=r"(r1), "=r"(r2), "=r"(r3) : "r"(addr));
}
__device__ __forceinline__ void ldsm4t(uint32_t addr, uint32_t& r0, uint32_t& r1,
                                       uint32_t& r2, uint32_t& r3) {
    asm volatile("ldmatrix.sync.aligned.m8n8.x4.trans.shared.b16 {%0,%1,%2,%3}, [%4];"
                 : "=r"(r0), "=r"(r1), "=r"(r2), "=r"(r3) : "r"(addr));
}
__device__ __forceinline__ void mma_f16(float c[4], const uint32_t a[4], const uint32_t b[2]) {
    asm volatile(
        "mma.sync.aligned.m16n8k16.row.col.f32.f16.f16.f32 "
        "{%0,%1,%2,%3}, {%4,%5,%6,%7}, {%8,%9}, {%0,%1,%2,%3};"
        : "+f"(c[0]), "+f"(c[1]), "+f"(c[2]), "+f"(c[3])
        : "r"(a[0]), "r"(a[1]), "r"(a[2]), "r"(a[3]), "r"(b[0]), "r"(b[1]));
}
__device__ __forceinline__ void stg_cs_f2(float* p, float a, float b) {
    asm volatile("st.global.cs.v2.f32 [%0], {%1, %2};" :: "l"(p), "f"(a), "f"(b) : "memory");
}

// swizzled 16B-chunk offset within a 128x32-f16 (64B-row) K-major tile
__device__ __forceinline__ uint32_t swz(int row, int chunk) {
    return (uint32_t)(row * 64 + ((chunk ^ ((row >> 1) & 3)) << 4));
}

// ===========================================================================
// 3xFP16 GEMM:  C = A[M,K] @ B[N,K]^T, fp16 hi/lo inputs, 128x128 tile, KC=32
// 3-stage cp.async pipeline, swizzled 64B rows, 2 CTAs/SM.
// CAUSAL: 1-D lower-triangle grid (blockIdx.x = linearized tile index).
// OUTMODE: 0 = fp32 (streaming .cs stores), 2 = fp16 hi/lo split pair
// ===========================================================================
#define AHI_OFF 0
#define ALO_OFF 8192
#define BHI_OFF 16384
#define BLO_OFF 24576
#define STG_BYTES 32768
#define SMEM_TOTAL (3 * STG_BYTES)   // 98304

template <bool CAUSAL, int OUTMODE>
__global__ __launch_bounds__(256, 2) void gemm_3x(
    const f16* __restrict__ Ahi, const f16* __restrict__ Alo,
    const f16* __restrict__ Bhi, const f16* __restrict__ Blo,
    float* __restrict__ Cf, f16* __restrict__ Chi, f16* __restrict__ Clo,
    int lda, int ldb, int ldc, int Kfull,
    long long sA, long long sB, long long sC)
{
    int bx, by;
    const int bz = blockIdx.z;
    if (CAUSAL) {
        const int idx = blockIdx.x;
        int t = (int)((sqrtf(8.0f * idx + 1.0f) - 1.0f) * 0.5f);
        while ((t + 1) * (t + 2) / 2 <= idx) t++;
        while (t * (t + 1) / 2 > idx) t--;
        by = t;
        bx = idx - t * (t + 1) / 2;
    } else {
        bx = blockIdx.x; by = blockIdx.y;
    }

    Ahi += (long long)bz * sA; Alo += (long long)bz * sA;
    Bhi += (long long)bz * sB; Blo += (long long)bz * sB;

    const int m0 = by * 128, n0 = bx * 128;
    const int nc = Kfull / 32;

    extern __shared__ char smem[];
    const uint32_t sbase = smem_u32(smem);
    const int tid = threadIdx.x;
    const int wid = tid >> 5, lane = tid & 31;
    const int wm = wid & 1, wn = wid >> 1;
    const int g = lane >> 3, i = lane & 7;

    const int arow_base = wm * 64 + i + (g & 1) * 8;
    const int brow_base = wn * 32 + i + (g >> 1) * 8;
    const int achunk0 = g >> 1;
    const int bchunk0 = g & 1;

    const int l_row = tid >> 2, l_ch = tid & 3;
    const uint32_t l_soff0 = swz(l_row, l_ch);
    const uint32_t l_soff1 = swz(l_row + 64, l_ch);

    float acc[4][4][4];
#pragma unroll
    for (int a = 0; a < 4; a++)
#pragma unroll
        for (int b = 0; b < 4; b++)
#pragma unroll
            for (int c = 0; c < 4; c++) acc[a][b][c] = 0.f;

    auto issue = [&](int ch) {
        const uint32_t st = sbase + (uint32_t)(ch % 3) * STG_BYTES;
        const long long k0 = (long long)ch * 32 + l_ch * 8;
        {
            const long long ga = (long long)(m0 + l_row) * lda + k0;
            const long long gb = (long long)(n0 + l_row) * ldb + k0;
            cp16(st + AHI_OFF + l_soff0, Ahi + ga);
            cp16(st + ALO_OFF + l_soff0, Alo + ga);
            cp16(st + BHI_OFF + l_soff0, Bhi + gb);
            cp16(st + BLO_OFF + l_soff0, Blo + gb);
        }
        {
            const long long ga = (long long)(m0 + l_row + 64) * lda + k0;
            const long long gb = (long long)(n0 + l_row + 64) * ldb + k0;
            cp16(st + AHI_OFF + l_soff1, Ahi + ga);
            cp16(st + ALO_OFF + l_soff1, Alo + ga);
            cp16(st + BHI_OFF + l_soff1, Bhi + gb);
            cp16(st + BLO_OFF + l_soff1, Blo + gb);
        }
    };

#pragma unroll
    for (int s = 0; s < 2; s++) {
        if (s < nc) issue(s);
        asm volatile("cp.async.commit_group;" ::: "memory");
    }

    for (int ch = 0; ch < nc; ch++) {
        asm volatile("cp.async.wait_group 1;" ::: "memory");
        __syncthreads();
        if (ch + 2 < nc) issue(ch + 2);
        asm volatile("cp.async.commit_group;" ::: "memory");

        const uint32_t st = sbase + (uint32_t)(ch % 3) * STG_BYTES;

#pragma unroll
        for (int ks = 0; ks < 2; ks++) {
            uint32_t ah[4][4], al[4][4], bh[4][2], bl[4][2];
#pragma unroll
            for (int mt = 0; mt < 4; mt++) {
                const uint32_t ao = swz(arow_base + mt * 16, achunk0 + ks * 2);
                ldsm4(st + AHI_OFF + ao, ah[mt][0], ah[mt][1], ah[mt][2], ah[mt][3]);
                ldsm4(st + ALO_OFF + ao, al[mt][0], al[mt][1], al[mt][2], al[mt][3]);
            }
#pragma unroll
            for (int j = 0; j < 2; j++) {
                const uint32_t bo = swz(brow_base + j * 16, bchunk0 + ks * 2);
                uint32_t r0, r1, r2, r3;
                ldsm4(st + BHI_OFF + bo, r0, r1, r2, r3);
                bh[2 * j][0] = r0; bh[2 * j][1] = r1; bh[2 * j + 1][0] = r2; bh[2 * j + 1][1] = r3;
                ldsm4(st + BLO_OFF + bo, r0, r1, r2, r3);
                bl[2 * j][0] = r0; bl[2 * j][1] = r1; bl[2 * j + 1][0] = r2; bl[2 * j + 1][1] = r3;
            }
#pragma unroll
            for (int mt = 0; mt < 4; mt++)
#pragma unroll
                for (int nt = 0; nt < 4; nt++) mma_f16(acc[mt][nt], ah[mt], bh[nt]);
#pragma unroll
            for (int mt = 0; mt < 4; mt++)
#pragma unroll
                for (int nt = 0; nt < 4; nt++) mma_f16(acc[mt][nt], ah[mt], bl[nt]);
#pragma unroll
            for (int mt = 0; mt < 4; mt++)
#pragma unroll
                for (int nt = 0; nt < 4; nt++) mma_f16(acc[mt][nt], al[mt], bh[nt]);
        }
    }

    // ---- epilogue ----
    const int rr = lane >> 2, cb = (lane & 3) * 2;
#pragma unroll
    for (int mt = 0; mt < 4; mt++) {
#pragma unroll
        for (int nt = 0; nt < 4; nt++) {
            const int row = m0 + wm * 64 + mt * 16 + rr;
            const int col = n0 + wn * 32 + nt * 8 + cb;
            const float s0 = acc[mt][nt][0], s1 = acc[mt][nt][1];
            const float s2 = acc[mt][nt][2], s3 = acc[mt][nt][3];
            if (OUTMODE == 0) {
                float* base = Cf + (long long)bz * sC;
                stg_cs_f2(base + (long long)row * ldc + col, s0, s1);
                stg_cs_f2(base + (long long)(row + 8) * ldc + col, s2, s3);
            } else {
                f16* oh = Chi + (long long)bz * sC;
                f16* ol = Clo + (long long)bz * sC;
                f16 h0 = __float2half(s0), h1 = __float2half(s1);
                f16 h2 = __float2half(s2), h3 = __float2half(s3);
                f16 l0 = __float2half(s0 - __half2float(h0));
                f16 l1 = __float2half(s1 - __half2float(h1));
                f16 l2 = __float2half(s2 - __half2float(h2));
                f16 l3 = __float2half(s3 - __half2float(h3));
                *(__half2*)(oh + (long long)row * ldc + col)       = __halves2half2(h0, h1);
                *(__half2*)(oh + (long long)(row + 8) * ldc + col) = __halves2half2(h2, h3);
                *(__half2*)(ol + (long long)row * ldc + col)       = __halves2half2(l0, l1);
                *(__half2*)(ol + (long long)(row + 8) * ldc + col) = __halves2half2(l2, l3);
            }
        }
    }
}

// ===========================================================================
// K4: out[t][c] = -sum_s wei[t][s] * xH[s][c]
// 1-pass fp16 GEMM: A = wei (fp16, K-major), B = xHhi (MN-major, trans-ldsm).
// K clamped, LPT, 4-stage pipeline, 2 CTA/SM.
// ===========================================================================
#define W_A   0
#define W_B   8192
#define W_STG 16896              // 8192 + 32*272
#define W_NST 4
#define W_SMEM (W_NST * W_STG)   // 67584

__global__ __launch_bounds__(256, 2) void gemm_wei(
    const f16* __restrict__ Wei,
    const f16* __restrict__ Bh,
    float* __restrict__ Out)
{
    const int bx = blockIdx.x, bz = blockIdx.z;
    const int by = (int)gridDim.y - 1 - (int)blockIdx.y;   // LPT
    const f16* wei = Wei + (long long)bz * TT * TT;
    const f16* bhi = Bh + (long long)bz * TT * CC;
    float* out = Out + (long long)bz * TT * CC;

    const int m0 = by * 128, n0 = bx * 128;
    const int Klim = min(TT, (by + 1) * 128);
    const int nc = Klim / 32;

    extern __shared__ char smem[];
    const uint32_t sbase = smem_u32(smem);
    const int tid = threadIdx.x;
    const int wid = tid >> 5, lane = tid & 31;
    const int wm = wid & 1, wn = wid >> 1;
    const int g = lane >> 3, i = lane & 7;

    const int arow_base = wm * 64 + i + (g & 1) * 8;
    const int achunk0 = g >> 1;
    const uint32_t bLaneT = (uint32_t)((lane & 15) * 272 + (lane >> 4) * 16 + wn * 64);

    const int l_row = tid >> 2, l_ch = tid & 3;
    const uint32_t l_soff0 = swz(l_row, l_ch);
    const uint32_t l_soff1 = swz(l_row + 64, l_ch);

    float acc[4][4][4];
#pragma unroll
    for (int a = 0; a < 4; a++)
#pragma unroll
        for (int b = 0; b < 4; b++)
#pragma unroll
            for (int c = 0; c < 4; c++) acc[a][b][c] = 0.f;

    auto issue = [&](int ch) {
        const uint32_t st = sbase + (uint32_t)(ch % W_NST) * W_STG;
        const long long k0 = (long long)ch * 32 + l_ch * 8;
        {
            cp16(st + W_A + l_soff0, wei + (long long)(m0 + l_row) * TT + k0);
            cp16(st + W_A + l_soff1, wei + (long long)(m0 + l_row + 64) * TT + k0);
        }
        const long long kb = (long long)ch * 32;
#pragma unroll
        for (int r = 0; r < 2; r++) {
            const int idx = tid + r * 256;
            const int brow = idx >> 4, bseg = idx & 15;
            const long long go = (kb + brow) * CC + n0 + bseg * 8;
            const uint32_t so = (uint32_t)(brow * 272 + bseg * 16);
            cp16(st + W_B + so, bhi + go);
        }
    };

#pragma unroll
    for (int s = 0; s < W_NST - 1; s++) {
        if (s < nc) issue(s);
        asm volatile("cp.async.commit_group;" ::: "memory");
    }

    for (int ch = 0; ch < nc; ch++) {
        asm volatile("cp.async.wait_group %0;" :: "n"(W_NST - 2) : "memory");
        __syncthreads();
        if (ch + W_NST - 1 < nc) issue(ch + W_NST - 1);
        asm volatile("cp.async.commit_group;" ::: "memory");

        const uint32_t st = sbase + (uint32_t)(ch % W_NST) * W_STG;

#pragma unroll
        for (int ks = 0; ks < 2; ks++) {
            uint32_t ah[4][4], bh[4][2];
#pragma unroll
            for (int mt = 0; mt < 4; mt++) {
                const uint32_t ao = swz(arow_base + mt * 16, achunk0 + ks * 2);
                ldsm4(st + W_A + ao, ah[mt][0], ah[mt][1], ah[mt][2], ah[mt][3]);
            }
#pragma unroll
            for (int j = 0; j < 2; j++) {
                uint32_t r0, r1, r2, r3;
                ldsm4t(st + W_B + bLaneT + ks * (16 * 272) + j * 32, r0, r1, r2, r3);
                bh[2 * j][0] = r0; bh[2 * j][1] = r1; bh[2 * j + 1][0] = r2; bh[2 * j + 1][1] = r3;
            }
#pragma unroll
            for (int mt = 0; mt < 4; mt++)
#pragma unroll
                for (int nt = 0; nt < 4; nt++) mma_f16(acc[mt][nt], ah[mt], bh[nt]);
        }
    }

    const int rr = lane >> 2, cb = (lane & 3) * 2;
#pragma unroll
    for (int mt = 0; mt < 4; mt++) {
#pragma unroll
        for (int nt = 0; nt < 4; nt++) {
            const int row = m0 + wm * 64 + mt * 16 + rr;
            const int col = n0 + wn * 32 + nt * 8 + cb;
            *(float2*)(out + (long long)row * CC + col) =
                make_float2(-acc[mt][nt][0], -acc[mt][nt][1]);
            *(float2*)(out + (long long)(row + 8) * CC + col) =
                make_float2(-acc[mt][nt][2], -acc[mt][nt][3]);
        }
    }
}

// ===========================================================================
// fp32 -> fp16 hi/lo split, fused for x then W
// ===========================================================================
__global__ __launch_bounds__(256) void split_f16_fused(
    const float* __restrict__ xsrc, f16* __restrict__ xh, f16* __restrict__ xl, long long n4x,
    const float* __restrict__ wsrc, f16* __restrict__ wh, f16* __restrict__ wl, long long n4w)
{
    const long long total = n4x + n4w;
    for (long long q = (long long)blockIdx.x * 256 + threadIdx.x; q < total;
         q += (long long)gridDim.x * 256) {
        const float4 v = (q < n4x) ? ((const float4*)xsrc)[q]
                                   : ((const float4*)wsrc)[q - n4x];
        const f16 h0 = __float2half(v.x), h1 = __float2half(v.y);
        const f16 h2 = __float2half(v.z), h3 = __float2half(v.w);
        const f16 l0 = __float2half(v.x - __half2float(h0));
        const f16 l1 = __float2half(v.y - __half2float(h1));
        const f16 l2 = __float2half(v.z - __half2float(h2));
        const f16 l3 = __float2half(v.w - __half2float(h3));
        __half2 hh[2] = { __halves2half2(h0, h1), __halves2half2(h2, h3) };
        __half2 ll[2] = { __halves2half2(l0, l1), __halves2half2(l2, l3) };
        if (q < n4x) {
            *(uint2*)(xh + q * 4) = *(uint2*)hh;
            *(uint2*)(xl + q * 4) = *(uint2*)ll;
        } else {
            *(uint2*)(wh + (q - n4x) * 4) = *(uint2*)hh;
            *(uint2*)(wl + (q - n4x) * 4) = *(uint2*)ll;
        }
    }
}

// ===========================================================================
// Causal softmax: fully register-resident. 256 threads x 8 values = one row.
// Each thread: 2x float4 load (if s0 < t), masked max/exp in regs, shfl+8-word
// smem reductions, one uint4 (8 x fp16) store. Writes only s < wlim; LPT.
// ===========================================================================
__global__ __launch_bounds__(256) void softmax_causal(
    const float* __restrict__ sc, f16* __restrict__ wout)
{
    const long long row = (long long)(BB * TT - 1) - blockIdx.x;   // LPT
    const int t = (int)(row % TT);
    const float* p = sc + row * TT;
    f16* oh = wout + row * TT;
    const int tid = threadIdx.x;
    const int s0 = tid * 8;
    const int wlim = ((t >> 7) + 1) << 7;

    __shared__ float red[8];

    // ---- load 8 values into registers (masked) ----
    float v[8];
    if (s0 < t) {
        const float4 a = *(const float4*)(p + s0);
        const float4 b = *(const float4*)(p + s0 + 4);
        v[0] = a.x; v[1] = a.y; v[2] = a.z; v[3] = a.w;
        v[4] = b.x; v[5] = b.y; v[6] = b.z; v[7] = b.w;
#pragma unroll
        for (int e = 0; e < 8; e++)
            if (s0 + e >= t) v[e] = -3.0e38f;
    } else {
#pragma unroll
        for (int e = 0; e < 8; e++) v[e] = -3.0e38f;
    }

    // ---- max reduce ----
    float m = v[0];
#pragma unroll
    for (int e = 1; e < 8; e++) m = fmaxf(m, v[e]);
#pragma unroll
    for (int o = 16; o; o >>= 1) m = fmaxf(m, __shfl_xor_sync(0xffffffffu, m, o));
    if ((tid & 31) == 0) red[tid >> 5] = m;
    __syncthreads();
    m = red[0];
#pragma unroll
    for (int w = 1; w < 8; w++) m = fmaxf(m, red[w]);
    __syncthreads();

    // ---- exp in regs + sum reduce ----
    float sum = 0.0f;
#pragma unroll
    for (int e = 0; e < 8; e++) {
        v[e] = (s0 + e < t) ? __expf(v[e] - m) : 0.0f;
        sum += v[e];
    }
#pragma unroll
    for (int o = 16; o; o >>= 1) sum += __shfl_xor_sync(0xffffffffu, sum, o);
    if ((tid & 31) == 0) red[tid >> 5] = sum;
    __syncthreads();
    sum = red[0] + red[1] + red[2] + red[3] + red[4] + red[5] + red[6] + red[7];

    const float inv = (t > 0) ? (1.0f / sum) : 0.0f;

    // ---- store 8 fp16 (one uint4), only inside the K4 read region ----
    if (s0 < wlim) {
        __half2 h[4];
#pragma unroll
        for (int e = 0; e < 8; e += 2)
            h[e / 2] = __halves2half2(__float2half(v[e] * inv),
                                      __float2half(v[e + 1] * inv));
        *(uint4*)(oh + s0) = *(uint4*)h;
    }
}

// ===========================================================================
extern "C" void kernel_launch(void* const* d_in, const int* in_sizes, int n_in,
                              void* d_out, int out_size)
{
    const float* x = (const float*)d_in[0];
    const float* W = (const float*)d_in[1];
    float* out = (float*)d_out;

    f16 *xhi, *xlo, *whi, *wlo, *xHhi, *xHlo, *wei;
    float* sc;
    cudaGetSymbolAddress((void**)&xhi,  g_xhi);
    cudaGetSymbolAddress((void**)&xlo,  g_xlo);
    cudaGetSymbolAddress((void**)&whi,  g_whi);
    cudaGetSymbolAddress((void**)&wlo,  g_wlo);
    cudaGetSymbolAddress((void**)&xHhi, g_xHhi);
    cudaGetSymbolAddress((void**)&xHlo, g_xHlo);
    cudaGetSymbolAddress((void**)&wei,  g_wei);
    cudaGetSymbolAddress((void**)&sc,   g_sc);

    cudaFuncSetAttribute(gemm_3x<false, 2>,
                         cudaFuncAttributeMaxDynamicSharedMemorySize, SMEM_TOTAL);
    cudaFuncSetAttribute(gemm_3x<true, 0>,
                         cudaFuncAttributeMaxDynamicSharedMemorySize, SMEM_TOTAL);
    cudaFuncSetAttribute(gemm_wei,
                         cudaFuncAttributeMaxDynamicSharedMemorySize, W_SMEM);

    // fused split: x then W
    split_f16_fused<<<4352, 256>>>(
        x, xhi, xlo, (long long)BB * TT * CC / 4,
        W, whi, wlo, (long long)CC * CC / 4);

    // K1: xH = x @ W^T  -> fp16 hi/lo  (3-pass)
    gemm_3x<false, 2><<<dim3(CC / 128, (BB * TT) / 128, 1), 256, SMEM_TOTAL>>>(
        xhi, xlo, whi, wlo, nullptr, xHhi, xHlo,
        CC, CC, CC, CC, 0, 0, 0);

    // K2: scores(fp32) = x @ xH^T per batch, exact lower-triangle grid (3-pass)
    {
        const int ntiles = (TT / 128) * (TT / 128 + 1) / 2;   // 136
        gemm_3x<true, 0><<<dim3(ntiles, 1, BB), 256, SMEM_TOTAL>>>(
            xhi, xlo, xHhi, xHlo, sc, nullptr, nullptr,
            CC, CC, TT, CC,
            (long long)TT * CC, (long long)TT * CC, (long long)TT * TT);
    }

    // K3: causal softmax -> wei fp16 (register-resident, LPT, write-trimmed)
    softmax_causal<<<BB * TT, 256>>>(sc, wei);

    // K4: out = -(wei @ xHhi), 1-pass fp16, K clamped, LPT, 4-stage
    gemm_wei<<<dim3(CC / 128, TT / 128, BB), 256, W_SMEM>>>(
        wei, xHhi, out);
}